// round 1
// baseline (speedup 1.0000x reference)
#include <cuda_runtime.h>
#include <math.h>

// Problem constants
#define DD   1024
#define NTOK 8192      // B*T*H*W
#define NBT  32        // B*T
#define NSEQ 512       // B*H*W
#define TT   16

// ---------------- scratch (device globals; no allocations allowed) ----------------
__device__ float g_cs[NBT * DD];
__device__ float g_smod[NBT * 6 * DD];
__device__ float g_tmod[NBT * 6 * DD];
__device__ float g_rmod[NBT * 3 * DD];
__device__ float g_xbuf[NTOK * DD];
__device__ float g_h1[NTOK * DD];
__device__ float g_qkv[NTOK * 3 * DD];
__device__ float g_delta[NTOK * DD];
__device__ float g_mlph[NTOK * 4 * DD];
__device__ float g_gatesx[NTOK * 4 * DD];
__device__ float g_gatesh[NSEQ * 4 * DD];
__device__ float g_hstate[NSEQ * DD];
__device__ float g_cstate[NSEQ * DD];
__device__ float g_lstmout[NTOK * DD];
__device__ float g_lstmbias[4 * DD];

// ---------------- generic fp32 GEMM: C[M,N] = A[M,K] @ B[K,N] (+bias, opt gelu) ----
// EPI: 0 = plain (+bias if non-null), 1 = gelu(tanh approx)(x+bias)
template<int EPI>
__global__ __launch_bounds__(256)
void gemm_kernel(const float* __restrict__ A, const float* __restrict__ B,
                 const float* __restrict__ bias, float* __restrict__ C,
                 int M, int N, int K) {
    __shared__ __align__(16) float As[8][128];
    __shared__ __align__(16) float Bs[8][128];
    const int tid = threadIdx.x;
    const int bx = blockIdx.x, by = blockIdx.y;
    const int tx = tid & 15, ty = tid >> 4;
    const int arow = tid >> 1;
    const int acol = (tid & 1) << 2;
    const int brow = tid >> 5;
    const int bcol = (tid & 31) << 2;

    float acc[8][8];
#pragma unroll
    for (int i = 0; i < 8; i++)
#pragma unroll
        for (int j = 0; j < 8; j++) acc[i][j] = 0.f;

    const int gr_a = by * 128 + arow;
    const bool a_ok = gr_a < M;
    const float* Aptr = A + (size_t)gr_a * K + acol;
    const float* Bptr = B + (size_t)brow * N + (size_t)bx * 128 + bcol;

    for (int k0 = 0; k0 < K; k0 += 8) {
        float4 av = make_float4(0.f, 0.f, 0.f, 0.f);
        if (a_ok) av = *(const float4*)(Aptr + k0);
        As[acol + 0][arow] = av.x;
        As[acol + 1][arow] = av.y;
        As[acol + 2][arow] = av.z;
        As[acol + 3][arow] = av.w;
        float4 bv = *(const float4*)(Bptr + (size_t)k0 * N);
        *(float4*)&Bs[brow][bcol] = bv;
        __syncthreads();
#pragma unroll
        for (int k = 0; k < 8; k++) {
            float4 a0 = *(const float4*)&As[k][ty * 8];
            float4 a1 = *(const float4*)&As[k][ty * 8 + 4];
            float4 b0 = *(const float4*)&Bs[k][tx * 8];
            float4 b1 = *(const float4*)&Bs[k][tx * 8 + 4];
            float ar[8] = {a0.x, a0.y, a0.z, a0.w, a1.x, a1.y, a1.z, a1.w};
            float br[8] = {b0.x, b0.y, b0.z, b0.w, b1.x, b1.y, b1.z, b1.w};
#pragma unroll
            for (int i = 0; i < 8; i++)
#pragma unroll
                for (int j = 0; j < 8; j++)
                    acc[i][j] = fmaf(ar[i], br[j], acc[i][j]);
        }
        __syncthreads();
    }

    const int col0 = bx * 128 + tx * 8;
    float bv[8];
#pragma unroll
    for (int j = 0; j < 8; j++) bv[j] = bias ? bias[col0 + j] : 0.f;
#pragma unroll
    for (int i = 0; i < 8; i++) {
        int gr = by * 128 + ty * 8 + i;
        if (gr >= M) break;
        float r[8];
#pragma unroll
        for (int j = 0; j < 8; j++) {
            float v = acc[i][j] + bv[j];
            if (EPI == 1) {
                float x = v;
                v = 0.5f * x * (1.f + tanhf(0.7978845608028654f * (x + 0.044715f * x * x * x)));
            }
            r[j] = v;
        }
        float4* cp = (float4*)(C + (size_t)gr * N + col0);
        cp[0] = make_float4(r[0], r[1], r[2], r[3]);
        cp[1] = make_float4(r[4], r[5], r[6], r[7]);
    }
}

// ---------------- LayerNorm + adaLN modulate ----------------
// out[tok,:] = ln(x[tok,:]) * (1 + mod[bt, scale_off:+D]) + mod[bt, shift_off:+D]
__global__ __launch_bounds__(256)
void ln_mod_kernel(const float* __restrict__ x, const float* __restrict__ mod,
                   int mstride, int shift_off, int scale_off, float* __restrict__ out) {
    __shared__ float red[16];
    const int tok = blockIdx.x;
    const int tid = threadIdx.x;
    const float* xr = x + (size_t)tok * DD;
    float v[4];
    float s = 0.f, s2 = 0.f;
#pragma unroll
    for (int k = 0; k < 4; k++) {
        float f = xr[tid + k * 256];
        v[k] = f; s += f; s2 += f * f;
    }
#pragma unroll
    for (int o = 16; o; o >>= 1) {
        s += __shfl_xor_sync(0xffffffffu, s, o);
        s2 += __shfl_xor_sync(0xffffffffu, s2, o);
    }
    if ((tid & 31) == 0) { red[tid >> 5] = s; red[8 + (tid >> 5)] = s2; }
    __syncthreads();
    if (tid == 0) {
        float a = 0.f, b = 0.f;
        for (int i = 0; i < 8; i++) { a += red[i]; b += red[8 + i]; }
        red[0] = a; red[8] = b;
    }
    __syncthreads();
    const float mean = red[0] * (1.f / DD);
    const float var = red[8] * (1.f / DD) - mean * mean;
    const float inv = rsqrtf(var + 1e-6f);
    const int bt = tok >> 8;
    const float* m = mod + (size_t)bt * mstride;
    float* orow = out + (size_t)tok * DD;
#pragma unroll
    for (int k = 0; k < 4; k++) {
        int d = tid + k * 256;
        float ln = (v[k] - mean) * inv;
        orow[d] = ln * (1.f + m[scale_off + d]) + m[shift_off + d];
    }
}

// ---------------- gated residual add ----------------
__global__ __launch_bounds__(256)
void gated_add_kernel(const float* __restrict__ xin, const float* __restrict__ delta,
                      const float* __restrict__ mod, int mstride, int gate_off,
                      float* __restrict__ xout) {
    int idx = blockIdx.x * 256 + threadIdx.x;
    int tok = idx >> 10, d = idx & 1023;
    int bt = tok >> 8;
    xout[idx] = xin[idx] + mod[(size_t)bt * mstride + gate_off + d] * delta[idx];
}

// ---------------- small utilities ----------------
__global__ void silu_kernel(const float* __restrict__ c, float* __restrict__ out, int n) {
    int i = blockIdx.x * 256 + threadIdx.x;
    if (i < n) { float v = c[i]; out[i] = v / (1.f + expf(-v)); }
}
__global__ void add_bias2_kernel(const float* __restrict__ a, const float* __restrict__ b,
                                 float* __restrict__ o, int n) {
    int i = blockIdx.x * 256 + threadIdx.x;
    if (i < n) o[i] = a[i] + b[i];
}
__global__ void zero2_kernel(float* __restrict__ a, float* __restrict__ b, int n) {
    int i = blockIdx.x * 256 + threadIdx.x;
    if (i < n) { a[i] = 0.f; b[i] = 0.f; }
}

// ---------------- spatial attention (L=256, dh=64, non-causal) ----------------
// One block per (n in 32, head in 16, qtile in 16 of 16 queries). qkv rows == token rows.
__global__ __launch_bounds__(256)
void spatial_attn_kernel(const float* __restrict__ qkv, float* __restrict__ out) {
    __shared__ float Q[16][65];
    __shared__ float S[16][260];
    __shared__ float KV[32][65];
    const int bid = blockIdx.x;
    const int qt = bid & 15;
    const int head = (bid >> 4) & 15;
    const int n = bid >> 8;
    const int tid = threadIdx.x;
    const size_t rowbase = (size_t)n * 256;

    // load Q tile (16x64)
    for (int i = tid; i < 16 * 64; i += 256) {
        int qi = i >> 6, d = i & 63;
        Q[qi][d] = qkv[(rowbase + qt * 16 + qi) * 3072 + head * 64 + d];
    }
    __syncthreads();

    // pass 1: scores
    const int sqi = tid >> 4;
    const int skj = (tid & 15) * 2;
    for (int kt = 0; kt < 8; kt++) {
        for (int i = tid; i < 32 * 64; i += 256) {
            int r = i >> 6, d = i & 63;
            KV[r][d] = qkv[(rowbase + kt * 32 + r) * 3072 + 1024 + head * 64 + d];
        }
        __syncthreads();
#pragma unroll
        for (int jj = 0; jj < 2; jj++) {
            int kj = skj + jj;
            float acc = 0.f;
#pragma unroll
            for (int d = 0; d < 64; d++) acc += Q[sqi][d] * KV[kj][d];
            S[sqi][kt * 32 + kj] = acc * 0.125f;
        }
        __syncthreads();
    }

    // softmax over 256 (16 lanes per row)
    {
        const int row = tid >> 4, c0 = tid & 15;
        float mx = -1e30f;
        for (int j = c0; j < 256; j += 16) mx = fmaxf(mx, S[row][j]);
#pragma unroll
        for (int o = 8; o; o >>= 1) mx = fmaxf(mx, __shfl_xor_sync(0xffffffffu, mx, o));
        float sum = 0.f;
        for (int j = c0; j < 256; j += 16) { float e = expf(S[row][j] - mx); S[row][j] = e; sum += e; }
#pragma unroll
        for (int o = 8; o; o >>= 1) sum += __shfl_xor_sync(0xffffffffu, sum, o);
        float inv = 1.f / sum;
        for (int j = c0; j < 256; j += 16) S[row][j] *= inv;
    }
    __syncthreads();

    // pass 2: O = P @ V
    const int oqi = tid >> 4;
    const int od = (tid & 15) * 4;
    float o0 = 0.f, o1 = 0.f, o2 = 0.f, o3 = 0.f;
    for (int vt = 0; vt < 8; vt++) {
        for (int i = tid; i < 32 * 64; i += 256) {
            int r = i >> 6, d = i & 63;
            KV[r][d] = qkv[(rowbase + vt * 32 + r) * 3072 + 2048 + head * 64 + d];
        }
        __syncthreads();
#pragma unroll
        for (int k = 0; k < 32; k++) {
            float p = S[oqi][vt * 32 + k];
            o0 = fmaf(p, KV[k][od + 0], o0);
            o1 = fmaf(p, KV[k][od + 1], o1);
            o2 = fmaf(p, KV[k][od + 2], o2);
            o3 = fmaf(p, KV[k][od + 3], o3);
        }
        __syncthreads();
    }
    float* op = out + (rowbase + qt * 16 + oqi) * 1024 + head * 64 + od;
    op[0] = o0; op[1] = o1; op[2] = o2; op[3] = o3;
}

// ---------------- temporal attention (T=16, dh=64, causal) ----------------
// One block per (n in 512 = b*256+hw, head in 16). 128 threads.
__global__ __launch_bounds__(128)
void temporal_attn_kernel(const float* __restrict__ qkv, float* __restrict__ out) {
    __shared__ float Q[16][65], K[16][65], V[16][65], S[16][17];
    const int bid = blockIdx.x;
    const int head = bid & 15;
    const int n = bid >> 4;
    const int b = n >> 8;
    const int hw = n & 255;
    const int tid = threadIdx.x;
    const size_t tokbase = (size_t)b * 4096 + hw;   // + t*256

    for (int i = tid; i < 16 * 64; i += 128) {
        int t = i >> 6, d = i & 63;
        size_t base = (tokbase + (size_t)t * 256) * 3072 + head * 64 + d;
        Q[t][d] = qkv[base];
        K[t][d] = qkv[base + 1024];
        V[t][d] = qkv[base + 2048];
    }
    __syncthreads();

    for (int idx = tid; idx < 256; idx += 128) {
        int qi = idx >> 4, kj = idx & 15;
        float s;
        if (kj <= qi) {
            float acc = 0.f;
#pragma unroll
            for (int d = 0; d < 64; d++) acc += Q[qi][d] * K[kj][d];
            s = acc * 0.125f;
        } else s = -1e30f;
        S[qi][kj] = s;
    }
    __syncthreads();

    {
        const int row = tid >> 3, c0 = tid & 7;
        float mx = fmaxf(S[row][c0], S[row][c0 + 8]);
#pragma unroll
        for (int o = 4; o; o >>= 1) mx = fmaxf(mx, __shfl_xor_sync(0xffffffffu, mx, o));
        float e0 = expf(S[row][c0] - mx), e1 = expf(S[row][c0 + 8] - mx);
        float sum = e0 + e1;
#pragma unroll
        for (int o = 4; o; o >>= 1) sum += __shfl_xor_sync(0xffffffffu, sum, o);
        float inv = 1.f / sum;
        S[row][c0] = e0 * inv;
        S[row][c0 + 8] = e1 * inv;
    }
    __syncthreads();

    for (int i = tid; i < 16 * 64; i += 128) {
        int qi = i >> 6, d = i & 63;
        float acc = 0.f;
#pragma unroll
        for (int k = 0; k < 16; k++) acc = fmaf(S[qi][k], V[k][d], acc);
        out[(tokbase + (size_t)qi * 256) * 1024 + head * 64 + d] = acc;
    }
}

// ---------------- LSTM cell (one time step) ----------------
__global__ __launch_bounds__(256)
void lstm_cell_kernel(const float* __restrict__ gx, const float* __restrict__ gh,
                      float* __restrict__ h, float* __restrict__ c,
                      float* __restrict__ out, int t) {
    int idx = blockIdx.x * 256 + threadIdx.x;   // < 512*1024
    int n = idx >> 10, j = idx & 1023;
    int b = n >> 8, hw = n & 255;
    size_t tok = (size_t)b * 4096 + (size_t)t * 256 + hw;
    const float* gxr = gx + tok * 4096;
    const float* ghr = gh + (size_t)n * 4096;
    float gi = gxr[j] + ghr[j];
    float gf = gxr[1024 + j] + ghr[1024 + j];
    float gg = gxr[2048 + j] + ghr[2048 + j];
    float go = gxr[3072 + j] + ghr[3072 + j];
    float si = 1.f / (1.f + expf(-gi));
    float sf = 1.f / (1.f + expf(-gf));
    float so = 1.f / (1.f + expf(-go));
    float cc = sf * c[idx] + si * tanhf(gg);
    float hh = so * tanhf(cc);
    c[idx] = cc;
    h[idx] = hh;
    out[tok * 1024 + j] = hh;
}

// ---------------- launch helpers ----------------
static void gemm(const float* A, const float* B, const float* bias, float* C,
                 int M, int N, int K, int epi) {
    dim3 g(N / 128, (M + 127) / 128);
    if (epi == 1) gemm_kernel<1><<<g, 256>>>(A, B, bias, C, M, N, K);
    else          gemm_kernel<0><<<g, 256>>>(A, B, bias, C, M, N, K);
}

extern "C" void kernel_launch(void* const* d_in, const int* in_sizes, int n_in,
                              void* d_out, int out_size) {
    const float* x        = (const float*)d_in[0];
    const float* c        = (const float*)d_in[1];
    const float* s_ada_w  = (const float*)d_in[2];
    const float* s_ada_b  = (const float*)d_in[3];
    const float* t_ada_w  = (const float*)d_in[4];
    const float* t_ada_b  = (const float*)d_in[5];
    const float* r_ada_w  = (const float*)d_in[6];
    const float* r_ada_b  = (const float*)d_in[7];
    const float* s_qkv_w  = (const float*)d_in[8];
    const float* s_out_w  = (const float*)d_in[9];
    const float* s_out_b  = (const float*)d_in[10];
    const float* t_qkv_w  = (const float*)d_in[11];
    const float* t_out_w  = (const float*)d_in[12];
    const float* t_out_b  = (const float*)d_in[13];
    const float* s_mlp_w1 = (const float*)d_in[14];
    const float* s_mlp_b1 = (const float*)d_in[15];
    const float* s_mlp_w2 = (const float*)d_in[16];
    const float* s_mlp_b2 = (const float*)d_in[17];
    const float* t_mlp_w1 = (const float*)d_in[18];
    const float* t_mlp_b1 = (const float*)d_in[19];
    const float* t_mlp_w2 = (const float*)d_in[20];
    const float* t_mlp_b2 = (const float*)d_in[21];
    const float* lstm_w_ih = (const float*)d_in[22];
    const float* lstm_w_hh = (const float*)d_in[23];
    const float* lstm_b_ih = (const float*)d_in[24];
    const float* lstm_b_hh = (const float*)d_in[25];
    float* out = (float*)d_out;

    float *cs, *smod, *tmod, *rmod, *xbuf, *h1, *qkv, *delta, *mlph;
    float *gatesx, *gatesh, *hstate, *cstate, *lstmout, *lstmbias;
    cudaGetSymbolAddress((void**)&cs, g_cs);
    cudaGetSymbolAddress((void**)&smod, g_smod);
    cudaGetSymbolAddress((void**)&tmod, g_tmod);
    cudaGetSymbolAddress((void**)&rmod, g_rmod);
    cudaGetSymbolAddress((void**)&xbuf, g_xbuf);
    cudaGetSymbolAddress((void**)&h1, g_h1);
    cudaGetSymbolAddress((void**)&qkv, g_qkv);
    cudaGetSymbolAddress((void**)&delta, g_delta);
    cudaGetSymbolAddress((void**)&mlph, g_mlph);
    cudaGetSymbolAddress((void**)&gatesx, g_gatesx);
    cudaGetSymbolAddress((void**)&gatesh, g_gatesh);
    cudaGetSymbolAddress((void**)&hstate, g_hstate);
    cudaGetSymbolAddress((void**)&cstate, g_cstate);
    cudaGetSymbolAddress((void**)&lstmout, g_lstmout);
    cudaGetSymbolAddress((void**)&lstmbias, g_lstmbias);

    const int NEL = NTOK * DD;            // 8388608
    const int EW_BLOCKS = NEL / 256;      // 32768

    // conditioning
    silu_kernel<<<(NBT * DD + 255) / 256, 256>>>(c, cs, NBT * DD);
    gemm(cs, s_ada_w, s_ada_b, smod, NBT, 6 * DD, DD, 0);
    gemm(cs, t_ada_w, t_ada_b, tmod, NBT, 6 * DD, DD, 0);
    gemm(cs, r_ada_w, r_ada_b, rmod, NBT, 3 * DD, DD, 0);

    // ---- spatial attention ----
    ln_mod_kernel<<<NTOK, 256>>>(x, smod, 6 * DD, 0, DD, h1);
    gemm(h1, s_qkv_w, nullptr, qkv, NTOK, 3 * DD, DD, 0);
    spatial_attn_kernel<<<8192, 256>>>(qkv, h1);                    // h1 reused as attn out
    gemm(h1, s_out_w, s_out_b, delta, NTOK, DD, DD, 0);
    gated_add_kernel<<<EW_BLOCKS, 256>>>(x, delta, smod, 6 * DD, 2 * DD, xbuf);

    // ---- spatial MLP ----
    ln_mod_kernel<<<NTOK, 256>>>(xbuf, smod, 6 * DD, 3 * DD, 4 * DD, h1);
    gemm(h1, s_mlp_w1, s_mlp_b1, mlph, NTOK, 4 * DD, DD, 1);
    gemm(mlph, s_mlp_w2, s_mlp_b2, delta, NTOK, DD, 4 * DD, 0);
    gated_add_kernel<<<EW_BLOCKS, 256>>>(xbuf, delta, smod, 6 * DD, 5 * DD, xbuf);

    // ---- temporal attention (causal) ----
    ln_mod_kernel<<<NTOK, 256>>>(xbuf, tmod, 6 * DD, 0, DD, h1);
    gemm(h1, t_qkv_w, nullptr, qkv, NTOK, 3 * DD, DD, 0);
    temporal_attn_kernel<<<8192, 128>>>(qkv, h1);
    gemm(h1, t_out_w, t_out_b, delta, NTOK, DD, DD, 0);
    gated_add_kernel<<<EW_BLOCKS, 256>>>(xbuf, delta, tmod, 6 * DD, 2 * DD, xbuf);

    // ---- temporal MLP ----
    ln_mod_kernel<<<NTOK, 256>>>(xbuf, tmod, 6 * DD, 3 * DD, 4 * DD, h1);
    gemm(h1, t_mlp_w1, t_mlp_b1, mlph, NTOK, 4 * DD, DD, 1);
    gemm(mlph, t_mlp_w2, t_mlp_b2, delta, NTOK, DD, 4 * DD, 0);
    gated_add_kernel<<<EW_BLOCKS, 256>>>(xbuf, delta, tmod, 6 * DD, 5 * DD, xbuf);

    // ---- LSTM branch ----
    ln_mod_kernel<<<NTOK, 256>>>(xbuf, rmod, 3 * DD, 0, DD, h1);    // xr
    add_bias2_kernel<<<(4 * DD + 255) / 256, 256>>>(lstm_b_ih, lstm_b_hh, lstmbias, 4 * DD);
    gemm(h1, lstm_w_ih, lstmbias, gatesx, NTOK, 4 * DD, DD, 0);
    zero2_kernel<<<(NSEQ * DD + 255) / 256, 256>>>(hstate, cstate, NSEQ * DD);
    for (int t = 0; t < TT; t++) {
        gemm(hstate, lstm_w_hh, nullptr, gatesh, NSEQ, 4 * DD, DD, 0);
        lstm_cell_kernel<<<(NSEQ * DD) / 256, 256>>>(gatesx, gatesh, hstate, cstate, lstmout, t);
    }
    gated_add_kernel<<<EW_BLOCKS, 256>>>(xbuf, lstmout, rmod, 3 * DD, 2 * DD, out);
}

// round 3
// speedup vs baseline: 2.6880x; 2.6880x over previous
#include <cuda_runtime.h>
#include <math.h>
#include <cstdint>

// Problem constants
#define DD   1024
#define NTOK 8192      // B*T*H*W
#define NBT  32        // B*T
#define NSEQ 512       // B*H*W
#define TT   16

// ---------------- scratch (device globals; no allocations allowed) ----------------
__device__ float g_cs[NBT * DD];
__device__ float g_smod[NBT * 6 * DD];
__device__ float g_tmod[NBT * 6 * DD];
__device__ float g_rmod[NBT * 3 * DD];
__device__ float g_xbuf[NTOK * DD];
__device__ float g_h1[NTOK * DD];
__device__ float g_qkv[NTOK * 3 * DD];
__device__ float g_delta[NTOK * DD];
__device__ float g_mlph[NTOK * 4 * DD];
__device__ float g_gatesx[NTOK * 4 * DD];
__device__ float g_gatesh[NSEQ * 4 * DD];
__device__ float g_hstate[NSEQ * DD];
__device__ float g_cstate[NSEQ * DD];
__device__ float g_lstmout[NTOK * DD];
__device__ float g_lstmbias[4 * DD];
// transposed weights: 47 M floats
__device__ float g_wT[47u * 1048576u];

__device__ __forceinline__ float to_tf32(float x) {
    float r; asm("cvt.rna.tf32.f32 %0, %1;" : "=f"(r) : "f"(x)); return r;
}
__device__ __forceinline__ float gelu_tanh(float x) {
    return 0.5f * x * (1.f + tanhf(0.7978845608028654f * (x + 0.044715f * x * x * x)));
}
__device__ __forceinline__ void mma_tf32(float d[4], uint32_t a0, uint32_t a1, uint32_t a2,
                                         uint32_t a3, uint32_t b0, uint32_t b1) {
    asm volatile(
        "mma.sync.aligned.m16n8k8.row.col.f32.tf32.tf32.f32 "
        "{%0,%1,%2,%3}, {%4,%5,%6,%7}, {%8,%9}, {%0,%1,%2,%3};\n"
        : "+f"(d[0]), "+f"(d[1]), "+f"(d[2]), "+f"(d[3])
        : "r"(a0), "r"(a1), "r"(a2), "r"(a3), "r"(b0), "r"(b1));
}

// ================== tensor-core GEMM: C[M,N] = A[M,K] @ BT[N,K]^T ==================
// A row-major [M,K]; BT row-major [N,K] (pre-transposed weight). N%128==0, K%32==0.
// mma.sync m16n8k8 tf32 (compute_80 feature -> compiles under compute_103 PTX).
// Block tile 128x128x32, 8 warps (2x4), warp tile 64x32, double-buffered smem.
// smem layout per stage: A[128][36] floats, B[128][36] floats (stride 36: conflict-free
// fragment LDS, 144B row pitch keeps float4 STS aligned).
// EPI: 0 = +bias, 1 = gelu(tanh)(x+bias)
#define GTC_STAGE_F 4608            // 128*36 floats per operand per stage
#define GTC_SMEM_TOTAL (4 * 4608 * 4)   // 73728 bytes

template<int EPI>
__global__ __launch_bounds__(256, 1)
void gemm_tc(const float* __restrict__ A, const float* __restrict__ BT,
             const float* __restrict__ bias, float* __restrict__ C,
             int M, int N, int K) {
    extern __shared__ float sm[];
    float* sA = sm;                 // [2][4608]
    float* sB = sm + 2 * GTC_STAGE_F;

    const int tid = threadIdx.x;
    const int lane = tid & 31;
    const int wid = tid >> 5;
    const int wr = wid >> 2;        // 0..1
    const int wc = wid & 3;         // 0..3
    const int bx = blockIdx.x, by = blockIdx.y;

    float acc[4][4][4];
#pragma unroll
    for (int mt = 0; mt < 4; mt++)
#pragma unroll
        for (int nt = 0; nt < 4; nt++)
#pragma unroll
            for (int q = 0; q < 4; q++) acc[mt][nt][q] = 0.f;

    const int ldrow = tid >> 3;            // 0..31 (x4 iterations -> 128 rows)
    const int ldc4 = (tid & 7) * 4;        // float4 col offset within 32
    const int gra = by * 128;              // block row origin

    float4 sa[4], sb[4];
    const int nk = K >> 5;

    // prologue: load chunk 0
#pragma unroll
    for (int i = 0; i < 4; i++) {
        const int row = ldrow + i * 32;
        const int ga = gra + row;
        sa[i] = (ga < M) ? *(const float4*)(A + (size_t)ga * K + ldc4)
                         : make_float4(0.f, 0.f, 0.f, 0.f);
        sb[i] = *(const float4*)(BT + (size_t)(bx * 128 + row) * K + ldc4);
    }
#pragma unroll
    for (int i = 0; i < 4; i++) {
        const int row = ldrow + i * 32;
        float4 av = sa[i], bv = sb[i];
        av.x = to_tf32(av.x); av.y = to_tf32(av.y); av.z = to_tf32(av.z); av.w = to_tf32(av.w);
        bv.x = to_tf32(bv.x); bv.y = to_tf32(bv.y); bv.z = to_tf32(bv.z); bv.w = to_tf32(bv.w);
        *(float4*)(sA + row * 36 + ldc4) = av;
        *(float4*)(sB + row * 36 + ldc4) = bv;
    }
    __syncthreads();

    for (int kc = 0; kc < nk; kc++) {
        const int st = kc & 1;
        // prefetch next chunk into registers
        if (kc + 1 < nk) {
            const int koff = (kc + 1) * 32 + ldc4;
#pragma unroll
            for (int i = 0; i < 4; i++) {
                const int row = ldrow + i * 32;
                const int ga = gra + row;
                sa[i] = (ga < M) ? *(const float4*)(A + (size_t)ga * K + koff)
                                 : make_float4(0.f, 0.f, 0.f, 0.f);
                sb[i] = *(const float4*)(BT + (size_t)(bx * 128 + row) * K + koff);
            }
        }
        // compute current stage
        const float* sAp = sA + st * GTC_STAGE_F;
        const float* sBp = sB + st * GTC_STAGE_F;
#pragma unroll
        for (int ks = 0; ks < 4; ks++) {
            const int k0 = ks * 8 + (lane & 3);
            uint32_t af[4][4];
            uint32_t bf[4][2];
#pragma unroll
            for (int mt = 0; mt < 4; mt++) {
                const int r = wr * 64 + mt * 16 + (lane >> 2);
                af[mt][0] = __float_as_uint(sAp[r * 36 + k0]);
                af[mt][1] = __float_as_uint(sAp[(r + 8) * 36 + k0]);
                af[mt][2] = __float_as_uint(sAp[r * 36 + k0 + 4]);
                af[mt][3] = __float_as_uint(sAp[(r + 8) * 36 + k0 + 4]);
            }
#pragma unroll
            for (int nt = 0; nt < 4; nt++) {
                const int n = wc * 32 + nt * 8 + (lane >> 2);
                bf[nt][0] = __float_as_uint(sBp[n * 36 + k0]);
                bf[nt][1] = __float_as_uint(sBp[n * 36 + k0 + 4]);
            }
#pragma unroll
            for (int mt = 0; mt < 4; mt++)
#pragma unroll
                for (int nt = 0; nt < 4; nt++)
                    mma_tf32(acc[mt][nt], af[mt][0], af[mt][1], af[mt][2], af[mt][3],
                             bf[nt][0], bf[nt][1]);
        }
        // store next chunk to the other stage
        if (kc + 1 < nk) {
            float* dA = sA + (st ^ 1) * GTC_STAGE_F;
            float* dB = sB + (st ^ 1) * GTC_STAGE_F;
#pragma unroll
            for (int i = 0; i < 4; i++) {
                const int row = ldrow + i * 32;
                float4 av = sa[i], bv = sb[i];
                av.x = to_tf32(av.x); av.y = to_tf32(av.y); av.z = to_tf32(av.z); av.w = to_tf32(av.w);
                bv.x = to_tf32(bv.x); bv.y = to_tf32(bv.y); bv.z = to_tf32(bv.z); bv.w = to_tf32(bv.w);
                *(float4*)(dA + row * 36 + ldc4) = av;
                *(float4*)(dB + row * 36 + ldc4) = bv;
            }
        }
        __syncthreads();
    }

    // epilogue
#pragma unroll
    for (int mt = 0; mt < 4; mt++) {
        const int r0 = by * 128 + wr * 64 + mt * 16 + (lane >> 2);
#pragma unroll
        for (int nt = 0; nt < 4; nt++) {
            const int col = bx * 128 + wc * 32 + nt * 8 + (lane & 3) * 2;
            float b0 = 0.f, b1 = 0.f;
            if (bias) { b0 = __ldg(bias + col); b1 = __ldg(bias + col + 1); }
            float v0 = acc[mt][nt][0] + b0;
            float v1 = acc[mt][nt][1] + b1;
            float v2 = acc[mt][nt][2] + b0;
            float v3 = acc[mt][nt][3] + b1;
            if (EPI == 1) {
                v0 = gelu_tanh(v0); v1 = gelu_tanh(v1);
                v2 = gelu_tanh(v2); v3 = gelu_tanh(v3);
            }
            if (r0 < M) *(float2*)(C + (size_t)r0 * N + col) = make_float2(v0, v1);
            if (r0 + 8 < M) *(float2*)(C + (size_t)(r0 + 8) * N + col) = make_float2(v2, v3);
        }
    }
}

// ---------------- weight transpose: WT[N,K] = W[K,N] ----------------
__global__ __launch_bounds__(256)
void transpose_kernel(const float* __restrict__ W, float* __restrict__ WT, int K, int N) {
    __shared__ float t[32][33];
    const int n0 = blockIdx.x * 32, k0 = blockIdx.y * 32;
    const int tx = threadIdx.x & 31, ty = threadIdx.x >> 5;  // 32x8
#pragma unroll
    for (int j = 0; j < 4; j++)
        t[ty + j * 8][tx] = W[(size_t)(k0 + ty + j * 8) * N + n0 + tx];
    __syncthreads();
#pragma unroll
    for (int j = 0; j < 4; j++)
        WT[(size_t)(n0 + ty + j * 8) * K + k0 + tx] = t[tx][ty + j * 8];
}

// ---------------- LayerNorm + adaLN modulate ----------------
__global__ __launch_bounds__(256)
void ln_mod_kernel(const float* __restrict__ x, const float* __restrict__ mod,
                   int mstride, int shift_off, int scale_off, float* __restrict__ out) {
    __shared__ float red[16];
    const int tok = blockIdx.x;
    const int tid = threadIdx.x;
    const float* xr = x + (size_t)tok * DD;
    float v[4];
    float s = 0.f, s2 = 0.f;
#pragma unroll
    for (int k = 0; k < 4; k++) {
        float f = xr[tid + k * 256];
        v[k] = f; s += f; s2 += f * f;
    }
#pragma unroll
    for (int o = 16; o; o >>= 1) {
        s += __shfl_xor_sync(0xffffffffu, s, o);
        s2 += __shfl_xor_sync(0xffffffffu, s2, o);
    }
    if ((tid & 31) == 0) { red[tid >> 5] = s; red[8 + (tid >> 5)] = s2; }
    __syncthreads();
    if (tid == 0) {
        float a = 0.f, b = 0.f;
        for (int i = 0; i < 8; i++) { a += red[i]; b += red[8 + i]; }
        red[0] = a; red[8] = b;
    }
    __syncthreads();
    const float mean = red[0] * (1.f / DD);
    const float var = red[8] * (1.f / DD) - mean * mean;
    const float inv = rsqrtf(var + 1e-6f);
    const int bt = tok >> 8;
    const float* m = mod + (size_t)bt * mstride;
    float* orow = out + (size_t)tok * DD;
#pragma unroll
    for (int k = 0; k < 4; k++) {
        int d = tid + k * 256;
        float ln = (v[k] - mean) * inv;
        orow[d] = ln * (1.f + m[scale_off + d]) + m[shift_off + d];
    }
}

// ---------------- gated residual add ----------------
__global__ __launch_bounds__(256)
void gated_add_kernel(const float* __restrict__ xin, const float* __restrict__ delta,
                      const float* __restrict__ mod, int mstride, int gate_off,
                      float* __restrict__ xout) {
    int idx = blockIdx.x * 256 + threadIdx.x;
    int tok = idx >> 10, d = idx & 1023;
    int bt = tok >> 8;
    xout[idx] = xin[idx] + mod[(size_t)bt * mstride + gate_off + d] * delta[idx];
}

// ---------------- small utilities ----------------
__global__ void silu_kernel(const float* __restrict__ c, float* __restrict__ out, int n) {
    int i = blockIdx.x * 256 + threadIdx.x;
    if (i < n) { float v = c[i]; out[i] = v / (1.f + expf(-v)); }
}
__global__ void add_bias2_kernel(const float* __restrict__ a, const float* __restrict__ b,
                                 float* __restrict__ o, int n) {
    int i = blockIdx.x * 256 + threadIdx.x;
    if (i < n) o[i] = a[i] + b[i];
}
__global__ void zero2_kernel(float* __restrict__ a, float* __restrict__ b, int n) {
    int i = blockIdx.x * 256 + threadIdx.x;
    if (i < n) { a[i] = 0.f; b[i] = 0.f; }
}

// ---------------- spatial attention (L=256, dh=64, non-causal) ----------------
__global__ __launch_bounds__(256)
void spatial_attn_kernel(const float* __restrict__ qkv, float* __restrict__ out) {
    __shared__ float Q[16][65];
    __shared__ float S[16][260];
    __shared__ float KV[32][65];
    const int bid = blockIdx.x;
    const int qt = bid & 15;
    const int head = (bid >> 4) & 15;
    const int n = bid >> 8;
    const int tid = threadIdx.x;
    const size_t rowbase = (size_t)n * 256;

    for (int i = tid; i < 16 * 64; i += 256) {
        int qi = i >> 6, d = i & 63;
        Q[qi][d] = qkv[(rowbase + qt * 16 + qi) * 3072 + head * 64 + d];
    }
    __syncthreads();

    const int sqi = tid >> 4;
    const int skj = (tid & 15) * 2;
    for (int kt = 0; kt < 8; kt++) {
        for (int i = tid; i < 32 * 64; i += 256) {
            int r = i >> 6, d = i & 63;
            KV[r][d] = qkv[(rowbase + kt * 32 + r) * 3072 + 1024 + head * 64 + d];
        }
        __syncthreads();
#pragma unroll
        for (int jj = 0; jj < 2; jj++) {
            int kj = skj + jj;
            float acc = 0.f;
#pragma unroll
            for (int d = 0; d < 64; d++) acc += Q[sqi][d] * KV[kj][d];
            S[sqi][kt * 32 + kj] = acc * 0.125f;
        }
        __syncthreads();
    }

    {
        const int row = tid >> 4, c0 = tid & 15;
        float mx = -1e30f;
        for (int j = c0; j < 256; j += 16) mx = fmaxf(mx, S[row][j]);
#pragma unroll
        for (int o = 8; o; o >>= 1) mx = fmaxf(mx, __shfl_xor_sync(0xffffffffu, mx, o));
        float sum = 0.f;
        for (int j = c0; j < 256; j += 16) { float e = expf(S[row][j] - mx); S[row][j] = e; sum += e; }
#pragma unroll
        for (int o = 8; o; o >>= 1) sum += __shfl_xor_sync(0xffffffffu, sum, o);
        float inv = 1.f / sum;
        for (int j = c0; j < 256; j += 16) S[row][j] *= inv;
    }
    __syncthreads();

    const int oqi = tid >> 4;
    const int od = (tid & 15) * 4;
    float o0 = 0.f, o1 = 0.f, o2 = 0.f, o3 = 0.f;
    for (int vt = 0; vt < 8; vt++) {
        for (int i = tid; i < 32 * 64; i += 256) {
            int r = i >> 6, d = i & 63;
            KV[r][d] = qkv[(rowbase + vt * 32 + r) * 3072 + 2048 + head * 64 + d];
        }
        __syncthreads();
#pragma unroll
        for (int k = 0; k < 32; k++) {
            float p = S[oqi][vt * 32 + k];
            o0 = fmaf(p, KV[k][od + 0], o0);
            o1 = fmaf(p, KV[k][od + 1], o1);
            o2 = fmaf(p, KV[k][od + 2], o2);
            o3 = fmaf(p, KV[k][od + 3], o3);
        }
        __syncthreads();
    }
    float* op = out + (rowbase + qt * 16 + oqi) * 1024 + head * 64 + od;
    op[0] = o0; op[1] = o1; op[2] = o2; op[3] = o3;
}

// ---------------- temporal attention (T=16, dh=64, causal) ----------------
__global__ __launch_bounds__(128)
void temporal_attn_kernel(const float* __restrict__ qkv, float* __restrict__ out) {
    __shared__ float Q[16][65], K[16][65], V[16][65], S[16][17];
    const int bid = blockIdx.x;
    const int head = bid & 15;
    const int n = bid >> 4;
    const int b = n >> 8;
    const int hw = n & 255;
    const int tid = threadIdx.x;
    const size_t tokbase = (size_t)b * 4096 + hw;

    for (int i = tid; i < 16 * 64; i += 128) {
        int t = i >> 6, d = i & 63;
        size_t base = (tokbase + (size_t)t * 256) * 3072 + head * 64 + d;
        Q[t][d] = qkv[base];
        K[t][d] = qkv[base + 1024];
        V[t][d] = qkv[base + 2048];
    }
    __syncthreads();

    for (int idx = tid; idx < 256; idx += 128) {
        int qi = idx >> 4, kj = idx & 15;
        float s;
        if (kj <= qi) {
            float acc = 0.f;
#pragma unroll
            for (int d = 0; d < 64; d++) acc += Q[qi][d] * K[kj][d];
            s = acc * 0.125f;
        } else s = -1e30f;
        S[qi][kj] = s;
    }
    __syncthreads();

    {
        const int row = tid >> 3, c0 = tid & 7;
        float mx = fmaxf(S[row][c0], S[row][c0 + 8]);
#pragma unroll
        for (int o = 4; o; o >>= 1) mx = fmaxf(mx, __shfl_xor_sync(0xffffffffu, mx, o));
        float e0 = expf(S[row][c0] - mx), e1 = expf(S[row][c0 + 8] - mx);
        float sum = e0 + e1;
#pragma unroll
        for (int o = 4; o; o >>= 1) sum += __shfl_xor_sync(0xffffffffu, sum, o);
        float inv = 1.f / sum;
        S[row][c0] = e0 * inv;
        S[row][c0 + 8] = e1 * inv;
    }
    __syncthreads();

    for (int i = tid; i < 16 * 64; i += 128) {
        int qi = i >> 6, d = i & 63;
        float acc = 0.f;
#pragma unroll
        for (int k = 0; k < 16; k++) acc = fmaf(S[qi][k], V[k][d], acc);
        out[(tokbase + (size_t)qi * 256) * 1024 + head * 64 + d] = acc;
    }
}

// ---------------- LSTM cell (one time step) ----------------
__global__ __launch_bounds__(256)
void lstm_cell_kernel(const float* __restrict__ gx, const float* __restrict__ gh,
                      float* __restrict__ h, float* __restrict__ c,
                      float* __restrict__ out, int t) {
    int idx = blockIdx.x * 256 + threadIdx.x;
    int n = idx >> 10, j = idx & 1023;
    int b = n >> 8, hw = n & 255;
    size_t tok = (size_t)b * 4096 + (size_t)t * 256 + hw;
    const float* gxr = gx + tok * 4096;
    const float* ghr = gh + (size_t)n * 4096;
    float gi = gxr[j] + ghr[j];
    float gf = gxr[1024 + j] + ghr[1024 + j];
    float gg = gxr[2048 + j] + ghr[2048 + j];
    float go = gxr[3072 + j] + ghr[3072 + j];
    float si = 1.f / (1.f + expf(-gi));
    float sf = 1.f / (1.f + expf(-gf));
    float so = 1.f / (1.f + expf(-go));
    float cc = sf * c[idx] + si * tanhf(gg);
    float hh = so * tanhf(cc);
    c[idx] = cc;
    h[idx] = hh;
    out[tok * 1024 + j] = hh;
}

// ---------------- launch helpers ----------------
static void gemm(const float* A, const float* BT, const float* bias, float* C,
                 int M, int N, int K, int epi) {
    dim3 g(N / 128, (M + 127) / 128);
    if (epi == 1) gemm_tc<1><<<g, 256, GTC_SMEM_TOTAL>>>(A, BT, bias, C, M, N, K);
    else          gemm_tc<0><<<g, 256, GTC_SMEM_TOTAL>>>(A, BT, bias, C, M, N, K);
}
static void wtrans(const float* W, float* WT, int K, int N) {
    transpose_kernel<<<dim3(N / 32, K / 32), 256>>>(W, WT, K, N);
}

extern "C" void kernel_launch(void* const* d_in, const int* in_sizes, int n_in,
                              void* d_out, int out_size) {
    const float* x        = (const float*)d_in[0];
    const float* c        = (const float*)d_in[1];
    const float* s_ada_w  = (const float*)d_in[2];
    const float* s_ada_b  = (const float*)d_in[3];
    const float* t_ada_w  = (const float*)d_in[4];
    const float* t_ada_b  = (const float*)d_in[5];
    const float* r_ada_w  = (const float*)d_in[6];
    const float* r_ada_b  = (const float*)d_in[7];
    const float* s_qkv_w  = (const float*)d_in[8];
    const float* s_out_w  = (const float*)d_in[9];
    const float* s_out_b  = (const float*)d_in[10];
    const float* t_qkv_w  = (const float*)d_in[11];
    const float* t_out_w  = (const float*)d_in[12];
    const float* t_out_b  = (const float*)d_in[13];
    const float* s_mlp_w1 = (const float*)d_in[14];
    const float* s_mlp_b1 = (const float*)d_in[15];
    const float* s_mlp_w2 = (const float*)d_in[16];
    const float* s_mlp_b2 = (const float*)d_in[17];
    const float* t_mlp_w1 = (const float*)d_in[18];
    const float* t_mlp_b1 = (const float*)d_in[19];
    const float* t_mlp_w2 = (const float*)d_in[20];
    const float* t_mlp_b2 = (const float*)d_in[21];
    const float* lstm_w_ih = (const float*)d_in[22];
    const float* lstm_w_hh = (const float*)d_in[23];
    const float* lstm_b_ih = (const float*)d_in[24];
    const float* lstm_b_hh = (const float*)d_in[25];
    float* out = (float*)d_out;

    cudaFuncSetAttribute(gemm_tc<0>, cudaFuncAttributeMaxDynamicSharedMemorySize, GTC_SMEM_TOTAL);
    cudaFuncSetAttribute(gemm_tc<1>, cudaFuncAttributeMaxDynamicSharedMemorySize, GTC_SMEM_TOTAL);

    float *cs, *smod, *tmod, *rmod, *xbuf, *h1, *qkv, *delta, *mlph;
    float *gatesx, *gatesh, *hstate, *cstate, *lstmout, *lstmbias, *wT;
    cudaGetSymbolAddress((void**)&cs, g_cs);
    cudaGetSymbolAddress((void**)&smod, g_smod);
    cudaGetSymbolAddress((void**)&tmod, g_tmod);
    cudaGetSymbolAddress((void**)&rmod, g_rmod);
    cudaGetSymbolAddress((void**)&xbuf, g_xbuf);
    cudaGetSymbolAddress((void**)&h1, g_h1);
    cudaGetSymbolAddress((void**)&qkv, g_qkv);
    cudaGetSymbolAddress((void**)&delta, g_delta);
    cudaGetSymbolAddress((void**)&mlph, g_mlph);
    cudaGetSymbolAddress((void**)&gatesx, g_gatesx);
    cudaGetSymbolAddress((void**)&gatesh, g_gatesh);
    cudaGetSymbolAddress((void**)&hstate, g_hstate);
    cudaGetSymbolAddress((void**)&cstate, g_cstate);
    cudaGetSymbolAddress((void**)&lstmout, g_lstmout);
    cudaGetSymbolAddress((void**)&lstmbias, g_lstmbias);
    cudaGetSymbolAddress((void**)&wT, g_wT);

    const size_t MEG = 1048576;
    float* wt_sada  = wT + 0 * MEG;   // [6144,1024]
    float* wt_tada  = wT + 6 * MEG;
    float* wt_rada  = wT + 12 * MEG;  // [3072,1024]
    float* wt_sqkv  = wT + 15 * MEG;  // [3072,1024]
    float* wt_sout  = wT + 18 * MEG;  // [1024,1024]
    float* wt_tqkv  = wT + 19 * MEG;
    float* wt_tout  = wT + 22 * MEG;
    float* wt_smlp1 = wT + 23 * MEG;  // [4096,1024]
    float* wt_smlp2 = wT + 27 * MEG;  // [1024,4096]
    float* wt_tmlp1 = wT + 31 * MEG;
    float* wt_tmlp2 = wT + 35 * MEG;
    float* wt_lih   = wT + 39 * MEG;  // [4096,1024]
    float* wt_lhh   = wT + 43 * MEG;  // [4096,1024]

    // pre-transpose all weights (B-side of every GEMM becomes [N,K] = mma .col layout)
    wtrans(s_ada_w, wt_sada, 1024, 6144);
    wtrans(t_ada_w, wt_tada, 1024, 6144);
    wtrans(r_ada_w, wt_rada, 1024, 3072);
    wtrans(s_qkv_w, wt_sqkv, 1024, 3072);
    wtrans(s_out_w, wt_sout, 1024, 1024);
    wtrans(t_qkv_w, wt_tqkv, 1024, 3072);
    wtrans(t_out_w, wt_tout, 1024, 1024);
    wtrans(s_mlp_w1, wt_smlp1, 1024, 4096);
    wtrans(s_mlp_w2, wt_smlp2, 4096, 1024);
    wtrans(t_mlp_w1, wt_tmlp1, 1024, 4096);
    wtrans(t_mlp_w2, wt_tmlp2, 4096, 1024);
    wtrans(lstm_w_ih, wt_lih, 1024, 4096);
    wtrans(lstm_w_hh, wt_lhh, 1024, 4096);

    const int NEL = NTOK * DD;
    const int EW_BLOCKS = NEL / 256;

    // conditioning
    silu_kernel<<<(NBT * DD + 255) / 256, 256>>>(c, cs, NBT * DD);
    gemm(cs, wt_sada, s_ada_b, smod, NBT, 6 * DD, DD, 0);
    gemm(cs, wt_tada, t_ada_b, tmod, NBT, 6 * DD, DD, 0);
    gemm(cs, wt_rada, r_ada_b, rmod, NBT, 3 * DD, DD, 0);

    // ---- spatial attention ----
    ln_mod_kernel<<<NTOK, 256>>>(x, smod, 6 * DD, 0, DD, h1);
    gemm(h1, wt_sqkv, nullptr, qkv, NTOK, 3 * DD, DD, 0);
    spatial_attn_kernel<<<8192, 256>>>(qkv, h1);
    gemm(h1, wt_sout, s_out_b, delta, NTOK, DD, DD, 0);
    gated_add_kernel<<<EW_BLOCKS, 256>>>(x, delta, smod, 6 * DD, 2 * DD, xbuf);

    // ---- spatial MLP ----
    ln_mod_kernel<<<NTOK, 256>>>(xbuf, smod, 6 * DD, 3 * DD, 4 * DD, h1);
    gemm(h1, wt_smlp1, s_mlp_b1, mlph, NTOK, 4 * DD, DD, 1);
    gemm(mlph, wt_smlp2, s_mlp_b2, delta, NTOK, DD, 4 * DD, 0);
    gated_add_kernel<<<EW_BLOCKS, 256>>>(xbuf, delta, smod, 6 * DD, 5 * DD, xbuf);

    // ---- temporal attention (causal) ----
    ln_mod_kernel<<<NTOK, 256>>>(xbuf, tmod, 6 * DD, 0, DD, h1);
    gemm(h1, wt_tqkv, nullptr, qkv, NTOK, 3 * DD, DD, 0);
    temporal_attn_kernel<<<8192, 128>>>(qkv, h1);
    gemm(h1, wt_tout, t_out_b, delta, NTOK, DD, DD, 0);
    gated_add_kernel<<<EW_BLOCKS, 256>>>(xbuf, delta, tmod, 6 * DD, 2 * DD, xbuf);

    // ---- temporal MLP ----
    ln_mod_kernel<<<NTOK, 256>>>(xbuf, tmod, 6 * DD, 3 * DD, 4 * DD, h1);
    gemm(h1, wt_tmlp1, t_mlp_b1, mlph, NTOK, 4 * DD, DD, 1);
    gemm(mlph, wt_tmlp2, t_mlp_b2, delta, NTOK, DD, 4 * DD, 0);
    gated_add_kernel<<<EW_BLOCKS, 256>>>(xbuf, delta, tmod, 6 * DD, 5 * DD, xbuf);

    // ---- LSTM branch ----
    ln_mod_kernel<<<NTOK, 256>>>(xbuf, rmod, 3 * DD, 0, DD, h1);
    add_bias2_kernel<<<(4 * DD + 255) / 256, 256>>>(lstm_b_ih, lstm_b_hh, lstmbias, 4 * DD);
    gemm(h1, wt_lih, lstmbias, gatesx, NTOK, 4 * DD, DD, 0);
    zero2_kernel<<<(NSEQ * DD + 255) / 256, 256>>>(hstate, cstate, NSEQ * DD);
    for (int t = 0; t < TT; t++) {
        gemm(hstate, wt_lhh, nullptr, gatesh, NSEQ, 4 * DD, DD, 0);
        lstm_cell_kernel<<<(NSEQ * DD) / 256, 256>>>(gatesx, gatesh, hstate, cstate, lstmout, t);
    }
    gated_add_kernel<<<EW_BLOCKS, 256>>>(xbuf, lstmout, rmod, 3 * DD, 2 * DD, out);
}

// round 4
// speedup vs baseline: 4.4522x; 1.6563x over previous
#include <cuda_runtime.h>
#include <cuda_fp16.h>
#include <math.h>
#include <cstdint>

// Problem constants
#define DD   1024
#define NTOK 8192      // B*T*H*W
#define NBT  32        // B*T
#define NSEQ 512       // B*H*W
#define TT   16

// ---------------- scratch (device globals; no allocations allowed) ----------------
__device__ __half  g_csh[NBT * DD];
__device__ float  g_smod[NBT * 6 * DD];
__device__ float  g_tmod[NBT * 6 * DD];
__device__ float  g_rmod[NBT * 3 * DD];
__device__ float  g_xbuf[NTOK * DD];
__device__ __half g_h1h[NTOK * DD];
__device__ __half g_qkvh[NTOK * 3 * DD];
__device__ float  g_delta[NTOK * DD];
__device__ __half g_mlph[NTOK * 4 * DD];
__device__ float  g_gatesx[NTOK * 4 * DD];
__device__ float  g_gatesh[NSEQ * 4 * DD];
__device__ __half g_hstateh[NSEQ * DD];
__device__ float  g_cstate[NSEQ * DD];
__device__ float  g_lstmout[NTOK * DD];
__device__ float  g_lstmbias[4 * DD];
__device__ __half g_wTh[47u * 1048576u];   // transposed fp16 weights

__device__ __forceinline__ float gelu_tanh(float x) {
    return 0.5f * x * (1.f + tanhf(0.7978845608028654f * (x + 0.044715f * x * x * x)));
}
__device__ __forceinline__ void mma_f16(float d[4], uint32_t a0, uint32_t a1, uint32_t a2,
                                        uint32_t a3, uint32_t b0, uint32_t b1) {
    asm volatile(
        "mma.sync.aligned.m16n8k16.row.col.f32.f16.f16.f32 "
        "{%0,%1,%2,%3}, {%4,%5,%6,%7}, {%8,%9}, {%0,%1,%2,%3};\n"
        : "+f"(d[0]), "+f"(d[1]), "+f"(d[2]), "+f"(d[3])
        : "r"(a0), "r"(a1), "r"(a2), "r"(a3), "r"(b0), "r"(b1));
}
__device__ __forceinline__ void cp_async16(uint32_t dst, const void* src, int szvalid) {
    asm volatile("cp.async.cg.shared.global [%0], [%1], 16, %2;"
                 :: "r"(dst), "l"(src), "r"(szvalid));
}
__device__ __forceinline__ void cp_commit() { asm volatile("cp.async.commit_group;"); }

// ================== fp16 tensor-core GEMM: C[M,N] = A[M,K] @ BT[N,K]^T ==================
// A fp16 row-major [M,K]; BT fp16 row-major [N,K]. N%128==0, K%32==0.
// Block tile 128x128x32, 8 warps (2x4), warp tile 64x32, cp.async double-buffered smem.
// smem per stage per operand: 128 rows x 40 halfs (80B pitch; conflict-free frag LDS).
// EPI: 0 = +bias, 1 = gelu(tanh)(x+bias). OUTH: 0 = fp32 C, 1 = fp16 C.
#define GPITCH_B   80                 // bytes per smem row
#define GOP_BYTES  (128 * GPITCH_B)   // 10240 bytes per operand
#define GSTAGE_B   (2 * GOP_BYTES)    // A + B
#define GTC_SMEM_TOTAL (2 * GSTAGE_B) // 40960 bytes

template<int EPI, int OUTH>
__global__ __launch_bounds__(256, 2)
void gemm_tc(const __half* __restrict__ A, const __half* __restrict__ BT,
             const float* __restrict__ bias, void* __restrict__ Cout,
             int M, int N, int K) {
    extern __shared__ char smem[];
    const uint32_t sb = (uint32_t)__cvta_generic_to_shared(smem);
    const int tid = threadIdx.x;
    const int lane = tid & 31;
    const int wid = tid >> 5;
    const int wr = wid >> 2;        // 0..1
    const int wc = wid & 3;         // 0..3
    const int bx = blockIdx.x, by = blockIdx.y;
    const int gra = by * 128;
    const int gnb = bx * 128;

    float acc[4][4][4];
#pragma unroll
    for (int mt = 0; mt < 4; mt++)
#pragma unroll
        for (int nt = 0; nt < 4; nt++)
#pragma unroll
            for (int q = 0; q < 4; q++) acc[mt][nt][q] = 0.f;

    const int nk = K >> 5;

    // stage loader: 512 16B-chunks per operand, thread does 2 of each
    auto load_stage = [&](int kc, int p) {
        const uint32_t sbase = sb + p * GSTAGE_B;
#pragma unroll
        for (int i = 0; i < 2; i++) {
            const int c = tid + i * 256;
            const int row = c >> 2, seg = c & 3;
            const int ga = gra + row;
            const bool ok = ga < M;
            cp_async16(sbase + row * GPITCH_B + seg * 16,
                       A + (size_t)(ok ? ga : 0) * K + kc * 32 + seg * 8, ok ? 16 : 0);
            cp_async16(sbase + GOP_BYTES + row * GPITCH_B + seg * 16,
                       BT + (size_t)(gnb + row) * K + kc * 32 + seg * 8, 16);
        }
    };

    load_stage(0, 0);
    cp_commit();

    for (int kc = 0; kc < nk; kc++) {
        const int p = kc & 1;
        if (kc + 1 < nk) {
            load_stage(kc + 1, p ^ 1);
            cp_commit();
            asm volatile("cp.async.wait_group 1;");
        } else {
            asm volatile("cp.async.wait_group 0;");
        }
        __syncthreads();

        const char* sA = smem + p * GSTAGE_B;
        const char* sB = sA + GOP_BYTES;
#pragma unroll
        for (int ks = 0; ks < 2; ks++) {
            const int kb = ks * 32 + (lane & 3) * 4;   // byte offset within row
            uint32_t af[4][4];
            uint32_t bf[4][2];
#pragma unroll
            for (int mt = 0; mt < 4; mt++) {
                const int r = wr * 64 + mt * 16 + (lane >> 2);
                af[mt][0] = *(const uint32_t*)(sA + r * GPITCH_B + kb);
                af[mt][1] = *(const uint32_t*)(sA + (r + 8) * GPITCH_B + kb);
                af[mt][2] = *(const uint32_t*)(sA + r * GPITCH_B + kb + 16);
                af[mt][3] = *(const uint32_t*)(sA + (r + 8) * GPITCH_B + kb + 16);
            }
#pragma unroll
            for (int nt = 0; nt < 4; nt++) {
                const int n = wc * 32 + nt * 8 + (lane >> 2);
                bf[nt][0] = *(const uint32_t*)(sB + n * GPITCH_B + kb);
                bf[nt][1] = *(const uint32_t*)(sB + n * GPITCH_B + kb + 16);
            }
#pragma unroll
            for (int mt = 0; mt < 4; mt++)
#pragma unroll
                for (int nt = 0; nt < 4; nt++)
                    mma_f16(acc[mt][nt], af[mt][0], af[mt][1], af[mt][2], af[mt][3],
                            bf[nt][0], bf[nt][1]);
        }
        __syncthreads();
    }

    // epilogue: c0,c1 -> (row=lane>>2, cols (lane&3)*2,+1); c2,c3 -> row+8
#pragma unroll
    for (int mt = 0; mt < 4; mt++) {
        const int r0 = by * 128 + wr * 64 + mt * 16 + (lane >> 2);
#pragma unroll
        for (int nt = 0; nt < 4; nt++) {
            const int col = bx * 128 + wc * 32 + nt * 8 + (lane & 3) * 2;
            float b0 = 0.f, b1 = 0.f;
            if (bias) { b0 = __ldg(bias + col); b1 = __ldg(bias + col + 1); }
            float v0 = acc[mt][nt][0] + b0;
            float v1 = acc[mt][nt][1] + b1;
            float v2 = acc[mt][nt][2] + b0;
            float v3 = acc[mt][nt][3] + b1;
            if (EPI == 1) {
                v0 = gelu_tanh(v0); v1 = gelu_tanh(v1);
                v2 = gelu_tanh(v2); v3 = gelu_tanh(v3);
            }
            if (OUTH) {
                __half* Ch = (__half*)Cout;
                if (r0 < M) *(__half2*)(Ch + (size_t)r0 * N + col) = __floats2half2_rn(v0, v1);
                if (r0 + 8 < M) *(__half2*)(Ch + (size_t)(r0 + 8) * N + col) = __floats2half2_rn(v2, v3);
            } else {
                float* Cf = (float*)Cout;
                if (r0 < M) *(float2*)(Cf + (size_t)r0 * N + col) = make_float2(v0, v1);
                if (r0 + 8 < M) *(float2*)(Cf + (size_t)(r0 + 8) * N + col) = make_float2(v2, v3);
            }
        }
    }
}

// ---------------- weight transpose to fp16: WT[N,K] = half(W[K,N]) ----------------
__global__ __launch_bounds__(256)
void transpose_kernel(const float* __restrict__ W, __half* __restrict__ WT, int K, int N) {
    __shared__ float t[32][33];
    const int n0 = blockIdx.x * 32, k0 = blockIdx.y * 32;
    const int tx = threadIdx.x & 31, ty = threadIdx.x >> 5;  // 32x8
#pragma unroll
    for (int j = 0; j < 4; j++)
        t[ty + j * 8][tx] = W[(size_t)(k0 + ty + j * 8) * N + n0 + tx];
    __syncthreads();
#pragma unroll
    for (int j = 0; j < 4; j++)
        WT[(size_t)(n0 + ty + j * 8) * K + k0 + tx] = __float2half(t[tx][ty + j * 8]);
}

// ---------------- LayerNorm + adaLN modulate (fp16 out) ----------------
__global__ __launch_bounds__(256)
void ln_mod_kernel(const float* __restrict__ x, const float* __restrict__ mod,
                   int mstride, int shift_off, int scale_off, __half* __restrict__ out) {
    __shared__ float red[16];
    const int tok = blockIdx.x;
    const int tid = threadIdx.x;
    const float* xr = x + (size_t)tok * DD;
    float v[4];
    float s = 0.f, s2 = 0.f;
#pragma unroll
    for (int k = 0; k < 4; k++) {
        float f = xr[tid + k * 256];
        v[k] = f; s += f; s2 += f * f;
    }
#pragma unroll
    for (int o = 16; o; o >>= 1) {
        s += __shfl_xor_sync(0xffffffffu, s, o);
        s2 += __shfl_xor_sync(0xffffffffu, s2, o);
    }
    if ((tid & 31) == 0) { red[tid >> 5] = s; red[8 + (tid >> 5)] = s2; }
    __syncthreads();
    if (tid == 0) {
        float a = 0.f, b = 0.f;
        for (int i = 0; i < 8; i++) { a += red[i]; b += red[8 + i]; }
        red[0] = a; red[8] = b;
    }
    __syncthreads();
    const float mean = red[0] * (1.f / DD);
    const float var = red[8] * (1.f / DD) - mean * mean;
    const float inv = rsqrtf(var + 1e-6f);
    const int bt = tok >> 8;
    const float* m = mod + (size_t)bt * mstride;
    __half* orow = out + (size_t)tok * DD;
#pragma unroll
    for (int k = 0; k < 4; k++) {
        int d = tid + k * 256;
        float ln = (v[k] - mean) * inv;
        orow[d] = __float2half(ln * (1.f + m[scale_off + d]) + m[shift_off + d]);
    }
}

// ---------------- fused gated residual add + LayerNorm + modulate ----------------
// xout = xin + gate*delta;  lnout = half(ln(xout)*(1+scale)+shift)
__global__ __launch_bounds__(256)
void ga_ln_kernel(const float* __restrict__ xin, const float* __restrict__ delta,
                  const float* __restrict__ modg, int gstride, int gate_off,
                  const float* __restrict__ modl, int lstride, int shift_off, int scale_off,
                  float* __restrict__ xout, __half* __restrict__ lnout) {
    __shared__ float red[16];
    const int tok = blockIdx.x;
    const int tid = threadIdx.x;
    const int bt = tok >> 8;
    const float* xr = xin + (size_t)tok * DD;
    const float* dr = delta + (size_t)tok * DD;
    const float* mg = modg + (size_t)bt * gstride + gate_off;
    float v[4];
    float s = 0.f, s2 = 0.f;
    float* xo = xout + (size_t)tok * DD;
#pragma unroll
    for (int k = 0; k < 4; k++) {
        int d = tid + k * 256;
        float f = xr[d] + mg[d] * dr[d];
        xo[d] = f;
        v[k] = f; s += f; s2 += f * f;
    }
#pragma unroll
    for (int o = 16; o; o >>= 1) {
        s += __shfl_xor_sync(0xffffffffu, s, o);
        s2 += __shfl_xor_sync(0xffffffffu, s2, o);
    }
    if ((tid & 31) == 0) { red[tid >> 5] = s; red[8 + (tid >> 5)] = s2; }
    __syncthreads();
    if (tid == 0) {
        float a = 0.f, b = 0.f;
        for (int i = 0; i < 8; i++) { a += red[i]; b += red[8 + i]; }
        red[0] = a; red[8] = b;
    }
    __syncthreads();
    const float mean = red[0] * (1.f / DD);
    const float var = red[8] * (1.f / DD) - mean * mean;
    const float inv = rsqrtf(var + 1e-6f);
    const float* ml = modl + (size_t)bt * lstride;
    __half* lo = lnout + (size_t)tok * DD;
#pragma unroll
    for (int k = 0; k < 4; k++) {
        int d = tid + k * 256;
        float ln = (v[k] - mean) * inv;
        lo[d] = __float2half(ln * (1.f + ml[scale_off + d]) + ml[shift_off + d]);
    }
}

// ---------------- gated residual add (final, fp32 out) ----------------
__global__ __launch_bounds__(256)
void gated_add_kernel(const float* __restrict__ xin, const float* __restrict__ delta,
                      const float* __restrict__ mod, int mstride, int gate_off,
                      float* __restrict__ xout) {
    int idx = blockIdx.x * 256 + threadIdx.x;
    int tok = idx >> 10, d = idx & 1023;
    int bt = tok >> 8;
    xout[idx] = xin[idx] + mod[(size_t)bt * mstride + gate_off + d] * delta[idx];
}

// ---------------- small utilities ----------------
__global__ void silu_kernel(const float* __restrict__ c, __half* __restrict__ out, int n) {
    int i = blockIdx.x * 256 + threadIdx.x;
    if (i < n) { float v = c[i]; out[i] = __float2half(v / (1.f + expf(-v))); }
}
__global__ void add_bias2_kernel(const float* __restrict__ a, const float* __restrict__ b,
                                 float* __restrict__ o, int n) {
    int i = blockIdx.x * 256 + threadIdx.x;
    if (i < n) o[i] = a[i] + b[i];
}
__global__ void zero_state_kernel(__half* __restrict__ h, float* __restrict__ c, int n) {
    int i = blockIdx.x * 256 + threadIdx.x;
    if (i < n) { h[i] = __float2half(0.f); c[i] = 0.f; }
}

// ---------------- spatial attention (L=256, dh=64, non-causal; fp16 qkv in/out) ----------------
__global__ __launch_bounds__(256)
void spatial_attn_kernel(const __half* __restrict__ qkv, __half* __restrict__ out) {
    __shared__ float Q[16][65];
    __shared__ float S[16][260];
    __shared__ float KV[32][65];
    const int bid = blockIdx.x;
    const int qt = bid & 15;
    const int head = (bid >> 4) & 15;
    const int n = bid >> 8;
    const int tid = threadIdx.x;
    const size_t rowbase = (size_t)n * 256;

    for (int i = tid; i < 16 * 64; i += 256) {
        int qi = i >> 6, d = i & 63;
        Q[qi][d] = __half2float(qkv[(rowbase + qt * 16 + qi) * 3072 + head * 64 + d]);
    }
    __syncthreads();

    const int sqi = tid >> 4;
    const int skj = (tid & 15) * 2;
    for (int kt = 0; kt < 8; kt++) {
        for (int i = tid; i < 32 * 64; i += 256) {
            int r = i >> 6, d = i & 63;
            KV[r][d] = __half2float(qkv[(rowbase + kt * 32 + r) * 3072 + 1024 + head * 64 + d]);
        }
        __syncthreads();
#pragma unroll
        for (int jj = 0; jj < 2; jj++) {
            int kj = skj + jj;
            float acc = 0.f;
#pragma unroll
            for (int d = 0; d < 64; d++) acc += Q[sqi][d] * KV[kj][d];
            S[sqi][kt * 32 + kj] = acc * 0.125f;
        }
        __syncthreads();
    }

    {
        const int row = tid >> 4, c0 = tid & 15;
        float mx = -1e30f;
        for (int j = c0; j < 256; j += 16) mx = fmaxf(mx, S[row][j]);
#pragma unroll
        for (int o = 8; o; o >>= 1) mx = fmaxf(mx, __shfl_xor_sync(0xffffffffu, mx, o));
        float sum = 0.f;
        for (int j = c0; j < 256; j += 16) { float e = expf(S[row][j] - mx); S[row][j] = e; sum += e; }
#pragma unroll
        for (int o = 8; o; o >>= 1) sum += __shfl_xor_sync(0xffffffffu, sum, o);
        float inv = 1.f / sum;
        for (int j = c0; j < 256; j += 16) S[row][j] *= inv;
    }
    __syncthreads();

    const int oqi = tid >> 4;
    const int od = (tid & 15) * 4;
    float o0 = 0.f, o1 = 0.f, o2 = 0.f, o3 = 0.f;
    for (int vt = 0; vt < 8; vt++) {
        for (int i = tid; i < 32 * 64; i += 256) {
            int r = i >> 6, d = i & 63;
            KV[r][d] = __half2float(qkv[(rowbase + vt * 32 + r) * 3072 + 2048 + head * 64 + d]);
        }
        __syncthreads();
#pragma unroll
        for (int k = 0; k < 32; k++) {
            float p = S[oqi][vt * 32 + k];
            o0 = fmaf(p, KV[k][od + 0], o0);
            o1 = fmaf(p, KV[k][od + 1], o1);
            o2 = fmaf(p, KV[k][od + 2], o2);
            o3 = fmaf(p, KV[k][od + 3], o3);
        }
        __syncthreads();
    }
    __half* op = out + (rowbase + qt * 16 + oqi) * 1024 + head * 64 + od;
    op[0] = __float2half(o0); op[1] = __float2half(o1);
    op[2] = __float2half(o2); op[3] = __float2half(o3);
}

// ---------------- temporal attention (T=16, dh=64, causal; fp16 qkv in/out) ----------------
__global__ __launch_bounds__(128)
void temporal_attn_kernel(const __half* __restrict__ qkv, __half* __restrict__ out) {
    __shared__ float Q[16][65], K[16][65], V[16][65], S[16][17];
    const int bid = blockIdx.x;
    const int head = bid & 15;
    const int n = bid >> 4;
    const int b = n >> 8;
    const int hw = n & 255;
    const int tid = threadIdx.x;
    const size_t tokbase = (size_t)b * 4096 + hw;

    for (int i = tid; i < 16 * 64; i += 128) {
        int t = i >> 6, d = i & 63;
        size_t base = (tokbase + (size_t)t * 256) * 3072 + head * 64 + d;
        Q[t][d] = __half2float(qkv[base]);
        K[t][d] = __half2float(qkv[base + 1024]);
        V[t][d] = __half2float(qkv[base + 2048]);
    }
    __syncthreads();

    for (int idx = tid; idx < 256; idx += 128) {
        int qi = idx >> 4, kj = idx & 15;
        float s;
        if (kj <= qi) {
            float acc = 0.f;
#pragma unroll
            for (int d = 0; d < 64; d++) acc += Q[qi][d] * K[kj][d];
            s = acc * 0.125f;
        } else s = -1e30f;
        S[qi][kj] = s;
    }
    __syncthreads();

    {
        const int row = tid >> 3, c0 = tid & 7;
        float mx = fmaxf(S[row][c0], S[row][c0 + 8]);
#pragma unroll
        for (int o = 4; o; o >>= 1) mx = fmaxf(mx, __shfl_xor_sync(0xffffffffu, mx, o));
        float e0 = expf(S[row][c0] - mx), e1 = expf(S[row][c0 + 8] - mx);
        float sum = e0 + e1;
#pragma unroll
        for (int o = 4; o; o >>= 1) sum += __shfl_xor_sync(0xffffffffu, sum, o);
        float inv = 1.f / sum;
        S[row][c0] = e0 * inv;
        S[row][c0 + 8] = e1 * inv;
    }
    __syncthreads();

    for (int i = tid; i < 16 * 64; i += 128) {
        int qi = i >> 6, d = i & 63;
        float acc = 0.f;
#pragma unroll
        for (int k = 0; k < 16; k++) acc = fmaf(S[qi][k], V[k][d], acc);
        out[(tokbase + (size_t)qi * 256) * 1024 + head * 64 + d] = __float2half(acc);
    }
}

// ---------------- LSTM cell (one time step) ----------------
__global__ __launch_bounds__(256)
void lstm_cell_kernel(const float* __restrict__ gx, const float* __restrict__ gh,
                      __half* __restrict__ h, float* __restrict__ c,
                      float* __restrict__ out, int t) {
    int idx = blockIdx.x * 256 + threadIdx.x;
    int n = idx >> 10, j = idx & 1023;
    int b = n >> 8, hw = n & 255;
    size_t tok = (size_t)b * 4096 + (size_t)t * 256 + hw;
    const float* gxr = gx + tok * 4096;
    const float* ghr = gh + (size_t)n * 4096;
    float gi = gxr[j] + ghr[j];
    float gf = gxr[1024 + j] + ghr[1024 + j];
    float gg = gxr[2048 + j] + ghr[2048 + j];
    float go = gxr[3072 + j] + ghr[3072 + j];
    float si = 1.f / (1.f + expf(-gi));
    float sf = 1.f / (1.f + expf(-gf));
    float so = 1.f / (1.f + expf(-go));
    float cc = sf * c[idx] + si * tanhf(gg);
    float hh = so * tanhf(cc);
    c[idx] = cc;
    h[idx] = __float2half(hh);
    out[tok * 1024 + j] = hh;
}

// ---------------- launch helpers ----------------
static void gemm(const __half* A, const __half* BT, const float* bias, void* C,
                 int M, int N, int K, int epi, int outh) {
    dim3 g(N / 128, (M + 127) / 128);
    if (epi == 1)      gemm_tc<1, 1><<<g, 256, GTC_SMEM_TOTAL>>>(A, BT, bias, C, M, N, K);
    else if (outh)     gemm_tc<0, 1><<<g, 256, GTC_SMEM_TOTAL>>>(A, BT, bias, C, M, N, K);
    else               gemm_tc<0, 0><<<g, 256, GTC_SMEM_TOTAL>>>(A, BT, bias, C, M, N, K);
}
static void wtrans(const float* W, __half* WT, int K, int N) {
    transpose_kernel<<<dim3(N / 32, K / 32), 256>>>(W, WT, K, N);
}

extern "C" void kernel_launch(void* const* d_in, const int* in_sizes, int n_in,
                              void* d_out, int out_size) {
    const float* x        = (const float*)d_in[0];
    const float* c        = (const float*)d_in[1];
    const float* s_ada_w  = (const float*)d_in[2];
    const float* s_ada_b  = (const float*)d_in[3];
    const float* t_ada_w  = (const float*)d_in[4];
    const float* t_ada_b  = (const float*)d_in[5];
    const float* r_ada_w  = (const float*)d_in[6];
    const float* r_ada_b  = (const float*)d_in[7];
    const float* s_qkv_w  = (const float*)d_in[8];
    const float* s_out_w  = (const float*)d_in[9];
    const float* s_out_b  = (const float*)d_in[10];
    const float* t_qkv_w  = (const float*)d_in[11];
    const float* t_out_w  = (const float*)d_in[12];
    const float* t_out_b  = (const float*)d_in[13];
    const float* s_mlp_w1 = (const float*)d_in[14];
    const float* s_mlp_b1 = (const float*)d_in[15];
    const float* s_mlp_w2 = (const float*)d_in[16];
    const float* s_mlp_b2 = (const float*)d_in[17];
    const float* t_mlp_w1 = (const float*)d_in[18];
    const float* t_mlp_b1 = (const float*)d_in[19];
    const float* t_mlp_w2 = (const float*)d_in[20];
    const float* t_mlp_b2 = (const float*)d_in[21];
    const float* lstm_w_ih = (const float*)d_in[22];
    const float* lstm_w_hh = (const float*)d_in[23];
    const float* lstm_b_ih = (const float*)d_in[24];
    const float* lstm_b_hh = (const float*)d_in[25];
    float* out = (float*)d_out;

    __half *csh, *h1h, *qkvh, *mlph, *hstateh, *wTh;
    float *smod, *tmod, *rmod, *xbuf, *delta, *gatesx, *gatesh, *cstate, *lstmout, *lstmbias;
    cudaGetSymbolAddress((void**)&csh, g_csh);
    cudaGetSymbolAddress((void**)&smod, g_smod);
    cudaGetSymbolAddress((void**)&tmod, g_tmod);
    cudaGetSymbolAddress((void**)&rmod, g_rmod);
    cudaGetSymbolAddress((void**)&xbuf, g_xbuf);
    cudaGetSymbolAddress((void**)&h1h, g_h1h);
    cudaGetSymbolAddress((void**)&qkvh, g_qkvh);
    cudaGetSymbolAddress((void**)&delta, g_delta);
    cudaGetSymbolAddress((void**)&mlph, g_mlph);
    cudaGetSymbolAddress((void**)&gatesx, g_gatesx);
    cudaGetSymbolAddress((void**)&gatesh, g_gatesh);
    cudaGetSymbolAddress((void**)&hstateh, g_hstateh);
    cudaGetSymbolAddress((void**)&cstate, g_cstate);
    cudaGetSymbolAddress((void**)&lstmout, g_lstmout);
    cudaGetSymbolAddress((void**)&lstmbias, g_lstmbias);
    cudaGetSymbolAddress((void**)&wTh, g_wTh);

    const size_t MEG = 1048576;
    __half* wt_sada  = wTh + 0 * MEG;   // [6144,1024]
    __half* wt_tada  = wTh + 6 * MEG;
    __half* wt_rada  = wTh + 12 * MEG;  // [3072,1024]
    __half* wt_sqkv  = wTh + 15 * MEG;  // [3072,1024]
    __half* wt_sout  = wTh + 18 * MEG;  // [1024,1024]
    __half* wt_tqkv  = wTh + 19 * MEG;
    __half* wt_tout  = wTh + 22 * MEG;
    __half* wt_smlp1 = wTh + 23 * MEG;  // [4096,1024]
    __half* wt_smlp2 = wTh + 27 * MEG;  // [1024,4096]
    __half* wt_tmlp1 = wTh + 31 * MEG;
    __half* wt_tmlp2 = wTh + 35 * MEG;
    __half* wt_lih   = wTh + 39 * MEG;  // [4096,1024]
    __half* wt_lhh   = wTh + 43 * MEG;  // [4096,1024]

    // pre-transpose all weights to fp16 [N,K]
    wtrans(s_ada_w, wt_sada, 1024, 6144);
    wtrans(t_ada_w, wt_tada, 1024, 6144);
    wtrans(r_ada_w, wt_rada, 1024, 3072);
    wtrans(s_qkv_w, wt_sqkv, 1024, 3072);
    wtrans(s_out_w, wt_sout, 1024, 1024);
    wtrans(t_qkv_w, wt_tqkv, 1024, 3072);
    wtrans(t_out_w, wt_tout, 1024, 1024);
    wtrans(s_mlp_w1, wt_smlp1, 1024, 4096);
    wtrans(s_mlp_w2, wt_smlp2, 4096, 1024);
    wtrans(t_mlp_w1, wt_tmlp1, 1024, 4096);
    wtrans(t_mlp_w2, wt_tmlp2, 4096, 1024);
    wtrans(lstm_w_ih, wt_lih, 1024, 4096);
    wtrans(lstm_w_hh, wt_lhh, 1024, 4096);

    const int NEL = NTOK * DD;
    const int EW_BLOCKS = NEL / 256;

    // conditioning
    silu_kernel<<<(NBT * DD + 255) / 256, 256>>>(c, csh, NBT * DD);
    gemm(csh, wt_sada, s_ada_b, smod, NBT, 6 * DD, DD, 0, 0);
    gemm(csh, wt_tada, t_ada_b, tmod, NBT, 6 * DD, DD, 0, 0);
    gemm(csh, wt_rada, r_ada_b, rmod, NBT, 3 * DD, DD, 0, 0);

    // ---- spatial attention ----
    ln_mod_kernel<<<NTOK, 256>>>(x, smod, 6 * DD, 0, DD, h1h);
    gemm(h1h, wt_sqkv, nullptr, qkvh, NTOK, 3 * DD, DD, 0, 1);
    spatial_attn_kernel<<<8192, 256>>>(qkvh, h1h);
    gemm(h1h, wt_sout, s_out_b, delta, NTOK, DD, DD, 0, 0);
    // x + gate*delta -> xbuf; ln+mod(spatial mlp) -> h1h
    ga_ln_kernel<<<NTOK, 256>>>(x, delta, smod, 6 * DD, 2 * DD,
                                smod, 6 * DD, 3 * DD, 4 * DD, xbuf, h1h);

    // ---- spatial MLP ----
    gemm(h1h, wt_smlp1, s_mlp_b1, mlph, NTOK, 4 * DD, DD, 1, 1);
    gemm(mlph, wt_smlp2, s_mlp_b2, delta, NTOK, DD, 4 * DD, 0, 0);
    // xbuf += gate*delta; ln+mod(temporal msa) -> h1h
    ga_ln_kernel<<<NTOK, 256>>>(xbuf, delta, smod, 6 * DD, 5 * DD,
                                tmod, 6 * DD, 0, DD, xbuf, h1h);

    // ---- temporal attention (causal) ----
    gemm(h1h, wt_tqkv, nullptr, qkvh, NTOK, 3 * DD, DD, 0, 1);
    temporal_attn_kernel<<<8192, 128>>>(qkvh, h1h);
    gemm(h1h, wt_tout, t_out_b, delta, NTOK, DD, DD, 0, 0);
    // xbuf += gate*delta; ln+mod(temporal mlp) -> h1h
    ga_ln_kernel<<<NTOK, 256>>>(xbuf, delta, tmod, 6 * DD, 2 * DD,
                                tmod, 6 * DD, 3 * DD, 4 * DD, xbuf, h1h);

    // ---- temporal MLP ----
    gemm(h1h, wt_tmlp1, t_mlp_b1, mlph, NTOK, 4 * DD, DD, 1, 1);
    gemm(mlph, wt_tmlp2, t_mlp_b2, delta, NTOK, DD, 4 * DD, 0, 0);
    // xbuf += gate*delta; ln+mod(recurrent) -> h1h
    ga_ln_kernel<<<NTOK, 256>>>(xbuf, delta, tmod, 6 * DD, 5 * DD,
                                rmod, 3 * DD, 0, DD, xbuf, h1h);

    // ---- LSTM branch ----
    add_bias2_kernel<<<(4 * DD + 255) / 256, 256>>>(lstm_b_ih, lstm_b_hh, lstmbias, 4 * DD);
    gemm(h1h, wt_lih, lstmbias, gatesx, NTOK, 4 * DD, DD, 0, 0);
    zero_state_kernel<<<(NSEQ * DD + 255) / 256, 256>>>(hstateh, cstate, NSEQ * DD);
    for (int t = 0; t < TT; t++) {
        gemm(hstateh, wt_lhh, nullptr, gatesh, NSEQ, 4 * DD, DD, 0, 0);
        lstm_cell_kernel<<<(NSEQ * DD) / 256, 256>>>(gatesx, gatesh, hstateh, cstate, lstmout, t);
    }
    gated_add_kernel<<<EW_BLOCKS, 256>>>(xbuf, lstmout, rmod, 3 * DD, 2 * DD, out);
}

// round 6
// speedup vs baseline: 5.2711x; 1.1839x over previous
#include <cuda_runtime.h>
#include <cuda_fp16.h>
#include <math.h>
#include <cstdint>

// Problem constants
#define DD   1024
#define NTOK 8192      // B*T*H*W
#define NBT  32        // B*T
#define NSEQ 512       // B*H*W
#define TT   16

// ---------------- scratch (device globals; no allocations allowed) ----------------
__device__ __half g_csh[NBT * DD];
__device__ float  g_smod[NBT * 6 * DD];
__device__ float  g_tmod[NBT * 6 * DD];
__device__ float  g_rmod[NBT * 3 * DD];
__device__ float  g_xbuf[NTOK * DD];
__device__ __half g_h1h[NTOK * DD];
__device__ __half g_qkvh[NTOK * 3 * DD];
__device__ float  g_delta[NTOK * DD];
__device__ __half g_mlph[NTOK * 4 * DD];
__device__ float  g_gatesx[NTOK * 4 * DD];
__device__ __half g_hstateh[NSEQ * DD];
__device__ __half g_hstate2h[NSEQ * DD];
__device__ float  g_cstate[NSEQ * DD];
__device__ float  g_lstmout[NTOK * DD];
__device__ float  g_lstmbias[4 * DD];
__device__ __half g_wTh[47u * 1048576u];   // transposed fp16 weights

__device__ __forceinline__ float gelu_tanh(float x) {
    return 0.5f * x * (1.f + tanhf(0.7978845608028654f * (x + 0.044715f * x * x * x)));
}
__device__ __forceinline__ float sigm(float x) { return 1.f / (1.f + expf(-x)); }
__device__ __forceinline__ uint32_t h2_as_u32(__half2 h) {
    uint32_t u; *reinterpret_cast<__half2*>(&u) = h; return u;
}
__device__ __forceinline__ void mma_f16(float d[4], uint32_t a0, uint32_t a1, uint32_t a2,
                                        uint32_t a3, uint32_t b0, uint32_t b1) {
    asm volatile(
        "mma.sync.aligned.m16n8k16.row.col.f32.f16.f16.f32 "
        "{%0,%1,%2,%3}, {%4,%5,%6,%7}, {%8,%9}, {%0,%1,%2,%3};\n"
        : "+f"(d[0]), "+f"(d[1]), "+f"(d[2]), "+f"(d[3])
        : "r"(a0), "r"(a1), "r"(a2), "r"(a3), "r"(b0), "r"(b1));
}
__device__ __forceinline__ void cp_async16(uint32_t dst, const void* src, int szvalid) {
    asm volatile("cp.async.cg.shared.global [%0], [%1], 16, %2;"
                 :: "r"(dst), "l"(src), "r"(szvalid));
}
__device__ __forceinline__ void cp_commit() { asm volatile("cp.async.commit_group;"); }

// ================== fp16 tensor-core GEMM: C[M,N] = A[M,K] @ BT[N,K]^T ==================
#define GPITCH_B   80
#define GOP_BYTES  (128 * GPITCH_B)
#define GSTAGE_B   (2 * GOP_BYTES)
#define GTC_SMEM_TOTAL (2 * GSTAGE_B)  // 40960 bytes

template<int EPI, int OUTH>
__global__ __launch_bounds__(256, 2)
void gemm_tc(const __half* __restrict__ A, const __half* __restrict__ BT,
             const float* __restrict__ bias, void* __restrict__ Cout,
             int M, int N, int K) {
    extern __shared__ char smem[];
    const uint32_t sb = (uint32_t)__cvta_generic_to_shared(smem);
    const int tid = threadIdx.x;
    const int lane = tid & 31;
    const int wid = tid >> 5;
    const int wr = wid >> 2;
    const int wc = wid & 3;
    const int bx = blockIdx.x, by = blockIdx.y;
    const int gra = by * 128;
    const int gnb = bx * 128;

    float acc[4][4][4];
#pragma unroll
    for (int mt = 0; mt < 4; mt++)
#pragma unroll
        for (int nt = 0; nt < 4; nt++)
#pragma unroll
            for (int q = 0; q < 4; q++) acc[mt][nt][q] = 0.f;

    const int nk = K >> 5;

    auto load_stage = [&](int kc, int p) {
        const uint32_t sbase = sb + p * GSTAGE_B;
#pragma unroll
        for (int i = 0; i < 2; i++) {
            const int c = tid + i * 256;
            const int row = c >> 2, seg = c & 3;
            const int ga = gra + row;
            const bool ok = ga < M;
            cp_async16(sbase + row * GPITCH_B + seg * 16,
                       A + (size_t)(ok ? ga : 0) * K + kc * 32 + seg * 8, ok ? 16 : 0);
            cp_async16(sbase + GOP_BYTES + row * GPITCH_B + seg * 16,
                       BT + (size_t)(gnb + row) * K + kc * 32 + seg * 8, 16);
        }
    };

    load_stage(0, 0);
    cp_commit();

    for (int kc = 0; kc < nk; kc++) {
        const int p = kc & 1;
        if (kc + 1 < nk) {
            load_stage(kc + 1, p ^ 1);
            cp_commit();
            asm volatile("cp.async.wait_group 1;");
        } else {
            asm volatile("cp.async.wait_group 0;");
        }
        __syncthreads();

        const char* sA = smem + p * GSTAGE_B;
        const char* sB = sA + GOP_BYTES;
#pragma unroll
        for (int ks = 0; ks < 2; ks++) {
            const int kb = ks * 32 + (lane & 3) * 4;
            uint32_t af[4][4];
            uint32_t bf[4][2];
#pragma unroll
            for (int mt = 0; mt < 4; mt++) {
                const int r = wr * 64 + mt * 16 + (lane >> 2);
                af[mt][0] = *(const uint32_t*)(sA + r * GPITCH_B + kb);
                af[mt][1] = *(const uint32_t*)(sA + (r + 8) * GPITCH_B + kb);
                af[mt][2] = *(const uint32_t*)(sA + r * GPITCH_B + kb + 16);
                af[mt][3] = *(const uint32_t*)(sA + (r + 8) * GPITCH_B + kb + 16);
            }
#pragma unroll
            for (int nt = 0; nt < 4; nt++) {
                const int n = wc * 32 + nt * 8 + (lane >> 2);
                bf[nt][0] = *(const uint32_t*)(sB + n * GPITCH_B + kb);
                bf[nt][1] = *(const uint32_t*)(sB + n * GPITCH_B + kb + 16);
            }
#pragma unroll
            for (int mt = 0; mt < 4; mt++)
#pragma unroll
                for (int nt = 0; nt < 4; nt++)
                    mma_f16(acc[mt][nt], af[mt][0], af[mt][1], af[mt][2], af[mt][3],
                            bf[nt][0], bf[nt][1]);
        }
        __syncthreads();
    }

#pragma unroll
    for (int mt = 0; mt < 4; mt++) {
        const int r0 = by * 128 + wr * 64 + mt * 16 + (lane >> 2);
#pragma unroll
        for (int nt = 0; nt < 4; nt++) {
            const int col = bx * 128 + wc * 32 + nt * 8 + (lane & 3) * 2;
            float b0 = 0.f, b1 = 0.f;
            if (bias) { b0 = __ldg(bias + col); b1 = __ldg(bias + col + 1); }
            float v0 = acc[mt][nt][0] + b0;
            float v1 = acc[mt][nt][1] + b1;
            float v2 = acc[mt][nt][2] + b0;
            float v3 = acc[mt][nt][3] + b1;
            if (EPI == 1) {
                v0 = gelu_tanh(v0); v1 = gelu_tanh(v1);
                v2 = gelu_tanh(v2); v3 = gelu_tanh(v3);
            }
            if (OUTH) {
                __half* Ch = (__half*)Cout;
                if (r0 < M) *(__half2*)(Ch + (size_t)r0 * N + col) = __floats2half2_rn(v0, v1);
                if (r0 + 8 < M) *(__half2*)(Ch + (size_t)(r0 + 8) * N + col) = __floats2half2_rn(v2, v3);
            } else {
                float* Cf = (float*)Cout;
                if (r0 < M) *(float2*)(Cf + (size_t)r0 * N + col) = make_float2(v0, v1);
                if (r0 + 8 < M) *(float2*)(Cf + (size_t)(r0 + 8) * N + col) = make_float2(v2, v3);
            }
        }
    }
}

// ============ fused LSTM step: gates = h@w_hhT (gate-interleaved) + gatesx; cell ============
// A = h fp16 [512,1024]; BT = wt_lhh_perm [4096,1024]; N-col n = 4*j + gate.
__global__ __launch_bounds__(256, 2)
void lstm_step_tc(const __half* __restrict__ A, const __half* __restrict__ BT,
                  const float* __restrict__ gx, float* __restrict__ cst,
                  __half* __restrict__ hnext, float* __restrict__ lout, int t) {
    extern __shared__ char smem[];
    const uint32_t sb = (uint32_t)__cvta_generic_to_shared(smem);
    const int tid = threadIdx.x;
    const int lane = tid & 31;
    const int wid = tid >> 5;
    const int wr = wid >> 2;
    const int wc = wid & 3;
    const int bx = blockIdx.x, by = blockIdx.y;
    const int gra = by * 128;
    const int gnb = bx * 128;
    const int K = 1024, nk = 32;

    float acc[4][4][4];
#pragma unroll
    for (int mt = 0; mt < 4; mt++)
#pragma unroll
        for (int nt = 0; nt < 4; nt++)
#pragma unroll
            for (int q = 0; q < 4; q++) acc[mt][nt][q] = 0.f;

    auto load_stage = [&](int kc, int p) {
        const uint32_t sbase = sb + p * GSTAGE_B;
#pragma unroll
        for (int i = 0; i < 2; i++) {
            const int c = tid + i * 256;
            const int row = c >> 2, seg = c & 3;
            cp_async16(sbase + row * GPITCH_B + seg * 16,
                       A + (size_t)(gra + row) * K + kc * 32 + seg * 8, 16);
            cp_async16(sbase + GOP_BYTES + row * GPITCH_B + seg * 16,
                       BT + (size_t)(gnb + row) * K + kc * 32 + seg * 8, 16);
        }
    };

    load_stage(0, 0);
    cp_commit();

    for (int kc = 0; kc < nk; kc++) {
        const int p = kc & 1;
        if (kc + 1 < nk) {
            load_stage(kc + 1, p ^ 1);
            cp_commit();
            asm volatile("cp.async.wait_group 1;");
        } else {
            asm volatile("cp.async.wait_group 0;");
        }
        __syncthreads();
        const char* sA = smem + p * GSTAGE_B;
        const char* sB = sA + GOP_BYTES;
#pragma unroll
        for (int ks = 0; ks < 2; ks++) {
            const int kb = ks * 32 + (lane & 3) * 4;
            uint32_t af[4][4];
            uint32_t bf[4][2];
#pragma unroll
            for (int mt = 0; mt < 4; mt++) {
                const int r = wr * 64 + mt * 16 + (lane >> 2);
                af[mt][0] = *(const uint32_t*)(sA + r * GPITCH_B + kb);
                af[mt][1] = *(const uint32_t*)(sA + (r + 8) * GPITCH_B + kb);
                af[mt][2] = *(const uint32_t*)(sA + r * GPITCH_B + kb + 16);
                af[mt][3] = *(const uint32_t*)(sA + (r + 8) * GPITCH_B + kb + 16);
            }
#pragma unroll
            for (int nt = 0; nt < 4; nt++) {
                const int n = wc * 32 + nt * 8 + (lane >> 2);
                bf[nt][0] = *(const uint32_t*)(sB + n * GPITCH_B + kb);
                bf[nt][1] = *(const uint32_t*)(sB + n * GPITCH_B + kb + 16);
            }
#pragma unroll
            for (int mt = 0; mt < 4; mt++)
#pragma unroll
                for (int nt = 0; nt < 4; nt++)
                    mma_f16(acc[mt][nt], af[mt][0], af[mt][1], af[mt][2], af[mt][3],
                            bf[nt][0], bf[nt][1]);
        }
        __syncthreads();
    }

    // fused cell epilogue (gate-interleaved columns: col = 4j+g)
#pragma unroll
    for (int mt = 0; mt < 4; mt++) {
        const int r0 = by * 128 + wr * 64 + mt * 16 + (lane >> 2);
        const int r1 = r0 + 8;
        const int tok0 = ((r0 >> 8) << 12) + (t << 8) + (r0 & 255);
        const int tok1 = ((r1 >> 8) << 12) + (t << 8) + (r1 & 255);
#pragma unroll
        for (int nt = 0; nt < 4; nt++) {
            const int col = bx * 128 + wc * 32 + nt * 8 + (lane & 3) * 2;
            float v0 = acc[mt][nt][0] + __ldg(gx + (size_t)tok0 * 4096 + col);
            float v1 = acc[mt][nt][1] + __ldg(gx + (size_t)tok0 * 4096 + col + 1);
            float v2 = acc[mt][nt][2] + __ldg(gx + (size_t)tok1 * 4096 + col);
            float v3 = acc[mt][nt][3] + __ldg(gx + (size_t)tok1 * 4096 + col + 1);
            float p0 = __shfl_xor_sync(0xffffffffu, v0, 1);
            float p1 = __shfl_xor_sync(0xffffffffu, v1, 1);
            float p2 = __shfl_xor_sync(0xffffffffu, v2, 1);
            float p3 = __shfl_xor_sync(0xffffffffu, v3, 1);
            if (!(lane & 1)) {
                // this lane: cols 4j,4j+1 = (i,f); partner: 4j+2,4j+3 = (g,o)
                const int j = col >> 2;
                {
                    float cc = sigm(v1) * cst[r0 * 1024 + j] + sigm(v0) * tanhf(p0);
                    float hh = sigm(p1) * tanhf(cc);
                    cst[r0 * 1024 + j] = cc;
                    hnext[r0 * 1024 + j] = __float2half(hh);
                    lout[(size_t)tok0 * 1024 + j] = hh;
                }
                {
                    float cc = sigm(v3) * cst[r1 * 1024 + j] + sigm(v2) * tanhf(p2);
                    float hh = sigm(p3) * tanhf(cc);
                    cst[r1 * 1024 + j] = cc;
                    hnext[r1 * 1024 + j] = __float2half(hh);
                    lout[(size_t)tok1 * 1024 + j] = hh;
                }
            }
        }
    }
}

// ---------------- weight transpose to fp16: WT[n][k]; PERM: n -> 4*(n%1024)+(n/1024) ----
template<int PERM>
__global__ __launch_bounds__(256)
void transpose_kernel(const float* __restrict__ W, __half* __restrict__ WT, int K, int N) {
    __shared__ float t[32][33];
    const int n0 = blockIdx.x * 32, k0 = blockIdx.y * 32;
    const int tx = threadIdx.x & 31, ty = threadIdx.x >> 5;
#pragma unroll
    for (int j = 0; j < 4; j++)
        t[ty + j * 8][tx] = W[(size_t)(k0 + ty + j * 8) * N + n0 + tx];
    __syncthreads();
#pragma unroll
    for (int j = 0; j < 4; j++) {
        int n = n0 + ty + j * 8;
        int nd = PERM ? (4 * (n & 1023) + (n >> 10)) : n;
        WT[(size_t)nd * K + k0 + tx] = __float2half(t[tx][ty + j * 8]);
    }
}

// ---------------- LayerNorm + adaLN modulate (fp16 out) ----------------
__global__ __launch_bounds__(256)
void ln_mod_kernel(const float* __restrict__ x, const float* __restrict__ mod,
                   int mstride, int shift_off, int scale_off, __half* __restrict__ out) {
    __shared__ float red[16];
    const int tok = blockIdx.x;
    const int tid = threadIdx.x;
    const float* xr = x + (size_t)tok * DD;
    float v[4];
    float s = 0.f, s2 = 0.f;
#pragma unroll
    for (int k = 0; k < 4; k++) {
        float f = xr[tid + k * 256];
        v[k] = f; s += f; s2 += f * f;
    }
#pragma unroll
    for (int o = 16; o; o >>= 1) {
        s += __shfl_xor_sync(0xffffffffu, s, o);
        s2 += __shfl_xor_sync(0xffffffffu, s2, o);
    }
    if ((tid & 31) == 0) { red[tid >> 5] = s; red[8 + (tid >> 5)] = s2; }
    __syncthreads();
    if (tid == 0) {
        float a = 0.f, b = 0.f;
        for (int i = 0; i < 8; i++) { a += red[i]; b += red[8 + i]; }
        red[0] = a; red[8] = b;
    }
    __syncthreads();
    const float mean = red[0] * (1.f / DD);
    const float var = red[8] * (1.f / DD) - mean * mean;
    const float inv = rsqrtf(var + 1e-6f);
    const int bt = tok >> 8;
    const float* m = mod + (size_t)bt * mstride;
    __half* orow = out + (size_t)tok * DD;
#pragma unroll
    for (int k = 0; k < 4; k++) {
        int d = tid + k * 256;
        float ln = (v[k] - mean) * inv;
        orow[d] = __float2half(ln * (1.f + m[scale_off + d]) + m[shift_off + d]);
    }
}

// ---------------- fused gated residual add + LayerNorm + modulate ----------------
__global__ __launch_bounds__(256)
void ga_ln_kernel(const float* __restrict__ xin, const float* __restrict__ delta,
                  const float* __restrict__ modg, int gstride, int gate_off,
                  const float* __restrict__ modl, int lstride, int shift_off, int scale_off,
                  float* __restrict__ xout, __half* __restrict__ lnout) {
    __shared__ float red[16];
    const int tok = blockIdx.x;
    const int tid = threadIdx.x;
    const int bt = tok >> 8;
    const float* xr = xin + (size_t)tok * DD;
    const float* dr = delta + (size_t)tok * DD;
    const float* mg = modg + (size_t)bt * gstride + gate_off;
    float v[4];
    float s = 0.f, s2 = 0.f;
    float* xo = xout + (size_t)tok * DD;
#pragma unroll
    for (int k = 0; k < 4; k++) {
        int d = tid + k * 256;
        float f = xr[d] + mg[d] * dr[d];
        xo[d] = f;
        v[k] = f; s += f; s2 += f * f;
    }
#pragma unroll
    for (int o = 16; o; o >>= 1) {
        s += __shfl_xor_sync(0xffffffffu, s, o);
        s2 += __shfl_xor_sync(0xffffffffu, s2, o);
    }
    if ((tid & 31) == 0) { red[tid >> 5] = s; red[8 + (tid >> 5)] = s2; }
    __syncthreads();
    if (tid == 0) {
        float a = 0.f, b = 0.f;
        for (int i = 0; i < 8; i++) { a += red[i]; b += red[8 + i]; }
        red[0] = a; red[8] = b;
    }
    __syncthreads();
    const float mean = red[0] * (1.f / DD);
    const float var = red[8] * (1.f / DD) - mean * mean;
    const float inv = rsqrtf(var + 1e-6f);
    const float* ml = modl + (size_t)bt * lstride;
    __half* lo = lnout + (size_t)tok * DD;
#pragma unroll
    for (int k = 0; k < 4; k++) {
        int d = tid + k * 256;
        float ln = (v[k] - mean) * inv;
        lo[d] = __float2half(ln * (1.f + ml[scale_off + d]) + ml[shift_off + d]);
    }
}

// ---------------- gated residual add (final) ----------------
__global__ __launch_bounds__(256)
void gated_add_kernel(const float* __restrict__ xin, const float* __restrict__ delta,
                      const float* __restrict__ mod, int mstride, int gate_off,
                      float* __restrict__ xout) {
    int idx = blockIdx.x * 256 + threadIdx.x;
    int tok = idx >> 10, d = idx & 1023;
    int bt = tok >> 8;
    xout[idx] = xin[idx] + mod[(size_t)bt * mstride + gate_off + d] * delta[idx];
}

// ---------------- small utilities ----------------
__global__ void silu_kernel(const float* __restrict__ c, __half* __restrict__ out, int n) {
    int i = blockIdx.x * 256 + threadIdx.x;
    if (i < n) { float v = c[i]; out[i] = __float2half(v / (1.f + expf(-v))); }
}
// permuted LSTM bias: o[4j+g] = a[g*1024+j] + b[g*1024+j]
__global__ void lstm_bias_kernel(const float* __restrict__ a, const float* __restrict__ b,
                                 float* __restrict__ o, int n) {
    int i = blockIdx.x * 256 + threadIdx.x;
    if (i < n) {
        int j = i >> 2, g = i & 3;
        o[i] = a[g * 1024 + j] + b[g * 1024 + j];
    }
}
__global__ void zero_state_kernel(__half* __restrict__ h0, __half* __restrict__ h1,
                                  float* __restrict__ c, int n) {
    int i = blockIdx.x * 256 + threadIdx.x;
    if (i < n) { h0[i] = __float2half(0.f); h1[i] = __float2half(0.f); c[i] = 0.f; }
}

// ======= spatial attention via mma.sync fp16 flash (L=256, dh=64, non-causal) =======
// grid: 1024 = n(32) x head(16) x qhalf(2); 256 threads (8 warps x 16 q-rows).
__global__ __launch_bounds__(256, 2)
void spatial_attn_tc(const __half* __restrict__ qkv, __half* __restrict__ out) {
    __shared__ __half sQ[128 * 72];
    __shared__ __half sK[64 * 72];
    __shared__ __half sVT[64 * 72];
    const int bid = blockIdx.x;
    const int qhalf = bid & 1;
    const int head = (bid >> 1) & 15;
    const int n = bid >> 5;
    const int tid = threadIdx.x;
    const int lane = tid & 31;
    const int wid = tid >> 5;
    const int g4 = lane >> 2, t4 = lane & 3;
    const size_t rowbase = (size_t)n * 256;

    // load Q tile (128 x 64 halfs)
#pragma unroll
    for (int i = 0; i < 4; i++) {
        int idx = tid + i * 256;
        int row = idx >> 3, seg = idx & 7;
        *(uint4*)&sQ[row * 72 + seg * 8] =
            *(const uint4*)(qkv + (rowbase + qhalf * 128 + row) * 3072 + head * 64 + seg * 8);
    }
    __syncthreads();

    uint32_t af[4][4];
    {
        const int r = wid * 16 + g4;
#pragma unroll
        for (int ks = 0; ks < 4; ks++) {
            af[ks][0] = *(const uint32_t*)&sQ[r * 72 + ks * 16 + t4 * 2];
            af[ks][1] = *(const uint32_t*)&sQ[(r + 8) * 72 + ks * 16 + t4 * 2];
            af[ks][2] = *(const uint32_t*)&sQ[r * 72 + ks * 16 + 8 + t4 * 2];
            af[ks][3] = *(const uint32_t*)&sQ[(r + 8) * 72 + ks * 16 + 8 + t4 * 2];
        }
    }

    float O[8][4];
#pragma unroll
    for (int i = 0; i < 8; i++)
#pragma unroll
        for (int q = 0; q < 4; q++) O[i][q] = 0.f;
    float m0 = -1e30f, m1 = -1e30f, l0 = 0.f, l1 = 0.f;

    for (int kt = 0; kt < 4; kt++) {
        // load K tile + transposed V tile
#pragma unroll
        for (int i = 0; i < 2; i++) {
            int idx = tid + i * 256;
            int row = idx >> 3, seg = idx & 7;
            const __half* src = qkv + (rowbase + kt * 64 + row) * 3072 + 1024 + head * 64 + seg * 8;
            *(uint4*)&sK[row * 72 + seg * 8] = *(const uint4*)src;
            __half vv[8];
            *(uint4*)vv = *(const uint4*)(src + 1024);
#pragma unroll
            for (int jj = 0; jj < 8; jj++) sVT[(seg * 8 + jj) * 72 + row] = vv[jj];
        }
        __syncthreads();

        // S = Q @ K^T  (16 x 64 per warp)
        float sc[8][4];
#pragma unroll
        for (int nt = 0; nt < 8; nt++) {
#pragma unroll
            for (int q = 0; q < 4; q++) sc[nt][q] = 0.f;
#pragma unroll
            for (int ks = 0; ks < 4; ks++) {
                uint32_t b0 = *(const uint32_t*)&sK[(nt * 8 + g4) * 72 + ks * 16 + t4 * 2];
                uint32_t b1 = *(const uint32_t*)&sK[(nt * 8 + g4) * 72 + ks * 16 + 8 + t4 * 2];
                mma_f16(sc[nt], af[ks][0], af[ks][1], af[ks][2], af[ks][3], b0, b1);
            }
        }

        // online softmax (rows r0 = wid*16+g4, r1 = +8)
        float mx0 = -1e30f, mx1 = -1e30f;
#pragma unroll
        for (int nt = 0; nt < 8; nt++) {
            sc[nt][0] *= 0.125f; sc[nt][1] *= 0.125f;
            sc[nt][2] *= 0.125f; sc[nt][3] *= 0.125f;
            mx0 = fmaxf(mx0, fmaxf(sc[nt][0], sc[nt][1]));
            mx1 = fmaxf(mx1, fmaxf(sc[nt][2], sc[nt][3]));
        }
        mx0 = fmaxf(mx0, __shfl_xor_sync(0xffffffffu, mx0, 1));
        mx0 = fmaxf(mx0, __shfl_xor_sync(0xffffffffu, mx0, 2));
        mx1 = fmaxf(mx1, __shfl_xor_sync(0xffffffffu, mx1, 1));
        mx1 = fmaxf(mx1, __shfl_xor_sync(0xffffffffu, mx1, 2));
        const float mn0 = fmaxf(m0, mx0), mn1 = fmaxf(m1, mx1);
        const float al0 = __expf(m0 - mn0), al1 = __expf(m1 - mn1);
        m0 = mn0; m1 = mn1;

        float sum0 = 0.f, sum1 = 0.f;
        uint32_t aP[8][2];
#pragma unroll
        for (int nt = 0; nt < 8; nt++) {
            float p0 = __expf(sc[nt][0] - mn0);
            float p1 = __expf(sc[nt][1] - mn0);
            float p2 = __expf(sc[nt][2] - mn1);
            float p3 = __expf(sc[nt][3] - mn1);
            sum0 += p0 + p1; sum1 += p2 + p3;
            aP[nt][0] = h2_as_u32(__floats2half2_rn(p0, p1));
            aP[nt][1] = h2_as_u32(__floats2half2_rn(p2, p3));
        }
        sum0 += __shfl_xor_sync(0xffffffffu, sum0, 1);
        sum0 += __shfl_xor_sync(0xffffffffu, sum0, 2);
        sum1 += __shfl_xor_sync(0xffffffffu, sum1, 1);
        sum1 += __shfl_xor_sync(0xffffffffu, sum1, 2);
        l0 = l0 * al0 + sum0;
        l1 = l1 * al1 + sum1;
#pragma unroll
        for (int nt2 = 0; nt2 < 8; nt2++) {
            O[nt2][0] *= al0; O[nt2][1] *= al0;
            O[nt2][2] *= al1; O[nt2][3] *= al1;
        }

        // O += P @ V  (P fragments from S C-frags; B from transposed V)
#pragma unroll
        for (int ks2 = 0; ks2 < 4; ks2++) {
            const uint32_t a0 = aP[2 * ks2][0], a1 = aP[2 * ks2][1];
            const uint32_t a2 = aP[2 * ks2 + 1][0], a3 = aP[2 * ks2 + 1][1];
#pragma unroll
            for (int nt2 = 0; nt2 < 8; nt2++) {
                uint32_t b0 = *(const uint32_t*)&sVT[(nt2 * 8 + g4) * 72 + ks2 * 16 + t4 * 2];
                uint32_t b1 = *(const uint32_t*)&sVT[(nt2 * 8 + g4) * 72 + ks2 * 16 + 8 + t4 * 2];
                mma_f16(O[nt2], a0, a1, a2, a3, b0, b1);
            }
        }
        __syncthreads();
    }

    const float inv0 = 1.f / l0, inv1 = 1.f / l1;
    const int q0 = qhalf * 128 + wid * 16 + g4;
#pragma unroll
    for (int nt2 = 0; nt2 < 8; nt2++) {
        const int col = head * 64 + nt2 * 8 + t4 * 2;
        *(__half2*)(out + (rowbase + q0) * 1024 + col) =
            __floats2half2_rn(O[nt2][0] * inv0, O[nt2][1] * inv0);
        *(__half2*)(out + (rowbase + q0 + 8) * 1024 + col) =
            __floats2half2_rn(O[nt2][2] * inv1, O[nt2][3] * inv1);
    }
}

// ---------------- temporal attention (T=16, dh=64, causal; fp16 qkv in/out) ----------------
__global__ __launch_bounds__(128)
void temporal_attn_kernel(const __half* __restrict__ qkv, __half* __restrict__ out) {
    __shared__ float Q[16][65], K[16][65], V[16][65], S[16][17];
    const int bid = blockIdx.x;
    const int head = bid & 15;
    const int n = bid >> 4;
    const int b = n >> 8;
    const int hw = n & 255;
    const int tid = threadIdx.x;
    const size_t tokbase = (size_t)b * 4096 + hw;

    for (int i = tid; i < 16 * 64; i += 128) {
        int t = i >> 6, d = i & 63;
        size_t base = (tokbase + (size_t)t * 256) * 3072 + head * 64 + d;
        Q[t][d] = __half2float(qkv[base]);
        K[t][d] = __half2float(qkv[base + 1024]);
        V[t][d] = __half2float(qkv[base + 2048]);
    }
    __syncthreads();

    for (int idx = tid; idx < 256; idx += 128) {
        int qi = idx >> 4, kj = idx & 15;
        float s;
        if (kj <= qi) {
            float acc = 0.f;
#pragma unroll
            for (int d = 0; d < 64; d++) acc += Q[qi][d] * K[kj][d];
            s = acc * 0.125f;
        } else s = -1e30f;
        S[qi][kj] = s;
    }
    __syncthreads();

    {
        const int row = tid >> 3, c0 = tid & 7;
        float mx = fmaxf(S[row][c0], S[row][c0 + 8]);
#pragma unroll
        for (int o = 4; o; o >>= 1) mx = fmaxf(mx, __shfl_xor_sync(0xffffffffu, mx, o));
        float e0 = expf(S[row][c0] - mx), e1 = expf(S[row][c0 + 8] - mx);
        float sum = e0 + e1;
#pragma unroll
        for (int o = 4; o; o >>= 1) sum += __shfl_xor_sync(0xffffffffu, sum, o);
        float inv = 1.f / sum;
        S[row][c0] = e0 * inv;
        S[row][c0 + 8] = e1 * inv;
    }
    __syncthreads();

    for (int i = tid; i < 16 * 64; i += 128) {
        int qi = i >> 6, d = i & 63;
        float acc = 0.f;
#pragma unroll
        for (int k = 0; k < 16; k++) acc = fmaf(S[qi][k], V[k][d], acc);
        out[(tokbase + (size_t)qi * 256) * 1024 + head * 64 + d] = __float2half(acc);
    }
}

// ---------------- launch helpers ----------------
static void gemm(const __half* A, const __half* BT, const float* bias, void* C,
                 int M, int N, int K, int epi, int outh) {
    dim3 g(N / 128, (M + 127) / 128);
    if (epi == 1)      gemm_tc<1, 1><<<g, 256, GTC_SMEM_TOTAL>>>(A, BT, bias, C, M, N, K);
    else if (outh)     gemm_tc<0, 1><<<g, 256, GTC_SMEM_TOTAL>>>(A, BT, bias, C, M, N, K);
    else               gemm_tc<0, 0><<<g, 256, GTC_SMEM_TOTAL>>>(A, BT, bias, C, M, N, K);
}
static void wtrans(const float* W, __half* WT, int K, int N) {
    transpose_kernel<0><<<dim3(N / 32, K / 32), 256>>>(W, WT, K, N);
}
static void wtrans_perm(const float* W, __half* WT, int K, int N) {
    transpose_kernel<1><<<dim3(N / 32, K / 32), 256>>>(W, WT, K, N);
}

extern "C" void kernel_launch(void* const* d_in, const int* in_sizes, int n_in,
                              void* d_out, int out_size) {
    const float* x        = (const float*)d_in[0];
    const float* c        = (const float*)d_in[1];
    const float* s_ada_w  = (const float*)d_in[2];
    const float* s_ada_b  = (const float*)d_in[3];
    const float* t_ada_w  = (const float*)d_in[4];
    const float* t_ada_b  = (const float*)d_in[5];
    const float* r_ada_w  = (const float*)d_in[6];
    const float* r_ada_b  = (const float*)d_in[7];
    const float* s_qkv_w  = (const float*)d_in[8];
    const float* s_out_w  = (const float*)d_in[9];
    const float* s_out_b  = (const float*)d_in[10];
    const float* t_qkv_w  = (const float*)d_in[11];
    const float* t_out_w  = (const float*)d_in[12];
    const float* t_out_b  = (const float*)d_in[13];
    const float* s_mlp_w1 = (const float*)d_in[14];
    const float* s_mlp_b1 = (const float*)d_in[15];
    const float* s_mlp_w2 = (const float*)d_in[16];
    const float* s_mlp_b2 = (const float*)d_in[17];
    const float* t_mlp_w1 = (const float*)d_in[18];
    const float* t_mlp_b1 = (const float*)d_in[19];
    const float* t_mlp_w2 = (const float*)d_in[20];
    const float* t_mlp_b2 = (const float*)d_in[21];
    const float* lstm_w_ih = (const float*)d_in[22];
    const float* lstm_w_hh = (const float*)d_in[23];
    const float* lstm_b_ih = (const float*)d_in[24];
    const float* lstm_b_hh = (const float*)d_in[25];
    float* out = (float*)d_out;

    __half *csh, *h1h, *qkvh, *mlph, *hstateh, *hstate2h, *wTh;
    float *smod, *tmod, *rmod, *xbuf, *delta, *gatesx, *cstate, *lstmout, *lstmbias;
    cudaGetSymbolAddress((void**)&csh, g_csh);
    cudaGetSymbolAddress((void**)&smod, g_smod);
    cudaGetSymbolAddress((void**)&tmod, g_tmod);
    cudaGetSymbolAddress((void**)&rmod, g_rmod);
    cudaGetSymbolAddress((void**)&xbuf, g_xbuf);
    cudaGetSymbolAddress((void**)&h1h, g_h1h);
    cudaGetSymbolAddress((void**)&qkvh, g_qkvh);
    cudaGetSymbolAddress((void**)&delta, g_delta);
    cudaGetSymbolAddress((void**)&mlph, g_mlph);
    cudaGetSymbolAddress((void**)&gatesx, g_gatesx);
    cudaGetSymbolAddress((void**)&hstateh, g_hstateh);
    cudaGetSymbolAddress((void**)&hstate2h, g_hstate2h);
    cudaGetSymbolAddress((void**)&cstate, g_cstate);
    cudaGetSymbolAddress((void**)&lstmout, g_lstmout);
    cudaGetSymbolAddress((void**)&lstmbias, g_lstmbias);
    cudaGetSymbolAddress((void**)&wTh, g_wTh);

    const size_t MEG = 1048576;
    __half* wt_sada  = wTh + 0 * MEG;
    __half* wt_tada  = wTh + 6 * MEG;
    __half* wt_rada  = wTh + 12 * MEG;
    __half* wt_sqkv  = wTh + 15 * MEG;
    __half* wt_sout  = wTh + 18 * MEG;
    __half* wt_tqkv  = wTh + 19 * MEG;
    __half* wt_tout  = wTh + 22 * MEG;
    __half* wt_smlp1 = wTh + 23 * MEG;
    __half* wt_smlp2 = wTh + 27 * MEG;
    __half* wt_tmlp1 = wTh + 31 * MEG;
    __half* wt_tmlp2 = wTh + 35 * MEG;
    __half* wt_lih   = wTh + 39 * MEG;  // gate-interleaved [4096,1024]
    __half* wt_lhh   = wTh + 43 * MEG;  // gate-interleaved [4096,1024]

    wtrans(s_ada_w, wt_sada, 1024, 6144);
    wtrans(t_ada_w, wt_tada, 1024, 6144);
    wtrans(r_ada_w, wt_rada, 1024, 3072);
    wtrans(s_qkv_w, wt_sqkv, 1024, 3072);
    wtrans(s_out_w, wt_sout, 1024, 1024);
    wtrans(t_qkv_w, wt_tqkv, 1024, 3072);
    wtrans(t_out_w, wt_tout, 1024, 1024);
    wtrans(s_mlp_w1, wt_smlp1, 1024, 4096);
    wtrans(s_mlp_w2, wt_smlp2, 4096, 1024);
    wtrans(t_mlp_w1, wt_tmlp1, 1024, 4096);
    wtrans(t_mlp_w2, wt_tmlp2, 4096, 1024);
    wtrans_perm(lstm_w_ih, wt_lih, 1024, 4096);
    wtrans_perm(lstm_w_hh, wt_lhh, 1024, 4096);

    const int NEL = NTOK * DD;
    const int EW_BLOCKS = NEL / 256;

    // conditioning
    silu_kernel<<<(NBT * DD + 255) / 256, 256>>>(c, csh, NBT * DD);
    gemm(csh, wt_sada, s_ada_b, smod, NBT, 6 * DD, DD, 0, 0);
    gemm(csh, wt_tada, t_ada_b, tmod, NBT, 6 * DD, DD, 0, 0);
    gemm(csh, wt_rada, r_ada_b, rmod, NBT, 3 * DD, DD, 0, 0);

    // ---- spatial attention ----
    ln_mod_kernel<<<NTOK, 256>>>(x, smod, 6 * DD, 0, DD, h1h);
    gemm(h1h, wt_sqkv, nullptr, qkvh, NTOK, 3 * DD, DD, 0, 1);
    spatial_attn_tc<<<1024, 256>>>(qkvh, h1h);
    gemm(h1h, wt_sout, s_out_b, delta, NTOK, DD, DD, 0, 0);
    ga_ln_kernel<<<NTOK, 256>>>(x, delta, smod, 6 * DD, 2 * DD,
                                smod, 6 * DD, 3 * DD, 4 * DD, xbuf, h1h);

    // ---- spatial MLP ----
    gemm(h1h, wt_smlp1, s_mlp_b1, mlph, NTOK, 4 * DD, DD, 1, 1);
    gemm(mlph, wt_smlp2, s_mlp_b2, delta, NTOK, DD, 4 * DD, 0, 0);
    ga_ln_kernel<<<NTOK, 256>>>(xbuf, delta, smod, 6 * DD, 5 * DD,
                                tmod, 6 * DD, 0, DD, xbuf, h1h);

    // ---- temporal attention (causal) ----
    gemm(h1h, wt_tqkv, nullptr, qkvh, NTOK, 3 * DD, DD, 0, 1);
    temporal_attn_kernel<<<8192, 128>>>(qkvh, h1h);
    gemm(h1h, wt_tout, t_out_b, delta, NTOK, DD, DD, 0, 0);
    ga_ln_kernel<<<NTOK, 256>>>(xbuf, delta, tmod, 6 * DD, 2 * DD,
                                tmod, 6 * DD, 3 * DD, 4 * DD, xbuf, h1h);

    // ---- temporal MLP ----
    gemm(h1h, wt_tmlp1, t_mlp_b1, mlph, NTOK, 4 * DD, DD, 1, 1);
    gemm(mlph, wt_tmlp2, t_mlp_b2, delta, NTOK, DD, 4 * DD, 0, 0);
    ga_ln_kernel<<<NTOK, 256>>>(xbuf, delta, tmod, 6 * DD, 5 * DD,
                                rmod, 3 * DD, 0, DD, xbuf, h1h);

    // ---- LSTM branch (gate-interleaved, fused cell) ----
    lstm_bias_kernel<<<(4 * DD + 255) / 256, 256>>>(lstm_b_ih, lstm_b_hh, lstmbias, 4 * DD);
    gemm(h1h, wt_lih, lstmbias, gatesx, NTOK, 4 * DD, DD, 0, 0);
    zero_state_kernel<<<(NSEQ * DD + 255) / 256, 256>>>(hstateh, hstate2h, cstate, NSEQ * DD);
    {
        __half* hb[2] = {hstateh, hstate2h};
        for (int t = 0; t < TT; t++) {
            lstm_step_tc<<<dim3(32, 4), 256, GTC_SMEM_TOTAL>>>(
                hb[t & 1], wt_lhh, gatesx, cstate, hb[(t + 1) & 1], lstmout, t);
        }
    }
    gated_add_kernel<<<EW_BLOCKS, 256>>>(xbuf, lstmout, rmod, 3 * DD, 2 * DD, out);
}

// round 7
// speedup vs baseline: 5.6091x; 1.0641x over previous
#include <cuda_runtime.h>
#include <cuda_fp16.h>
#include <math.h>
#include <cstdint>

// Problem constants
#define DD   1024
#define NTOK 8192      // B*T*H*W
#define NBT  32        // B*T
#define NSEQ 512       // B*H*W
#define TT   16

// ---------------- scratch (device globals; no allocations allowed) ----------------
__device__ __half g_csh[NBT * DD];
__device__ float  g_smod[NBT * 6 * DD];
__device__ float  g_tmod[NBT * 6 * DD];
__device__ float  g_rmod[NBT * 3 * DD];
__device__ float  g_xbuf[NTOK * DD];
__device__ __half g_h1h[NTOK * DD];
__device__ __half g_qkvh[NTOK * 3 * DD];
__device__ float  g_delta[NTOK * DD];
__device__ __half g_mlph[NTOK * 4 * DD];
__device__ float  g_gatesx[NTOK * 4 * DD];
__device__ __half g_hstateh[NSEQ * DD];
__device__ __half g_hstate2h[NSEQ * DD];
__device__ float  g_cstate[NSEQ * DD];
__device__ float  g_lstmout[NTOK * DD];
__device__ float  g_lstmbias[4 * DD];
__device__ __half g_wTh[47u * 1048576u];   // transposed fp16 weights

__device__ __forceinline__ float gelu_tanh(float x) {
    return 0.5f * x * (1.f + tanhf(0.7978845608028654f * (x + 0.044715f * x * x * x)));
}
__device__ __forceinline__ float sigm(float x) { return 1.f / (1.f + expf(-x)); }
__device__ __forceinline__ uint32_t h2_as_u32(__half2 h) {
    uint32_t u; *reinterpret_cast<__half2*>(&u) = h; return u;
}
__device__ __forceinline__ void mma_f16(float d[4], uint32_t a0, uint32_t a1, uint32_t a2,
                                        uint32_t a3, uint32_t b0, uint32_t b1) {
    asm volatile(
        "mma.sync.aligned.m16n8k16.row.col.f32.f16.f16.f32 "
        "{%0,%1,%2,%3}, {%4,%5,%6,%7}, {%8,%9}, {%0,%1,%2,%3};\n"
        : "+f"(d[0]), "+f"(d[1]), "+f"(d[2]), "+f"(d[3])
        : "r"(a0), "r"(a1), "r"(a2), "r"(a3), "r"(b0), "r"(b1));
}
__device__ __forceinline__ void cp_async16(uint32_t dst, const void* src, int szvalid) {
    asm volatile("cp.async.cg.shared.global [%0], [%1], 16, %2;"
                 :: "r"(dst), "l"(src), "r"(szvalid));
}
__device__ __forceinline__ void cp_commit() { asm volatile("cp.async.commit_group;"); }

// ================== fp16 tensor-core GEMM: C[M,N] = A[M,K] @ BT[N,K]^T ==================
// 128 threads = 4 warps (2x2), warp tile 64x64, block tile 128x128x32.
#define GPITCH_B   80
#define GOP_BYTES  (128 * GPITCH_B)
#define GSTAGE_B   (2 * GOP_BYTES)
#define GTC_SMEM_TOTAL (2 * GSTAGE_B)  // 40960 bytes

template<int EPI, int OUTH>
__global__ __launch_bounds__(128, 2)
void gemm_tc(const __half* __restrict__ A, const __half* __restrict__ BT,
             const float* __restrict__ bias, void* __restrict__ Cout,
             int M, int N, int K) {
    extern __shared__ char smem[];
    const uint32_t sb = (uint32_t)__cvta_generic_to_shared(smem);
    const int tid = threadIdx.x;
    const int lane = tid & 31;
    const int wid = tid >> 5;
    const int wr = wid >> 1;        // 0..1
    const int wc = wid & 1;         // 0..1
    const int g4 = lane >> 2, t4 = lane & 3;
    const int bx = blockIdx.x, by = blockIdx.y;
    const int gra = by * 128;
    const int gnb = bx * 128;

    float acc[4][8][4];
#pragma unroll
    for (int mt = 0; mt < 4; mt++)
#pragma unroll
        for (int nt = 0; nt < 8; nt++)
#pragma unroll
            for (int q = 0; q < 4; q++) acc[mt][nt][q] = 0.f;

    const int nk = K >> 5;

    auto load_stage = [&](int kc, int p) {
        const uint32_t sbase = sb + p * GSTAGE_B;
#pragma unroll
        for (int i = 0; i < 4; i++) {
            const int c = tid + i * 128;
            const int row = c >> 2, seg = c & 3;
            const int ga = gra + row;
            const bool ok = ga < M;
            cp_async16(sbase + row * GPITCH_B + seg * 16,
                       A + (size_t)(ok ? ga : 0) * K + kc * 32 + seg * 8, ok ? 16 : 0);
            cp_async16(sbase + GOP_BYTES + row * GPITCH_B + seg * 16,
                       BT + (size_t)(gnb + row) * K + kc * 32 + seg * 8, 16);
        }
    };

    load_stage(0, 0);
    cp_commit();

    for (int kc = 0; kc < nk; kc++) {
        const int p = kc & 1;
        if (kc + 1 < nk) {
            load_stage(kc + 1, p ^ 1);
            cp_commit();
            asm volatile("cp.async.wait_group 1;");
        } else {
            asm volatile("cp.async.wait_group 0;");
        }
        __syncthreads();

        const char* sA = smem + p * GSTAGE_B;
        const char* sB = sA + GOP_BYTES;
#pragma unroll
        for (int ks = 0; ks < 2; ks++) {
            const int kb = ks * 32 + t4 * 4;
            uint32_t af[4][4];
            uint32_t bf[8][2];
#pragma unroll
            for (int mt = 0; mt < 4; mt++) {
                const int r = wr * 64 + mt * 16 + g4;
                af[mt][0] = *(const uint32_t*)(sA + r * GPITCH_B + kb);
                af[mt][1] = *(const uint32_t*)(sA + (r + 8) * GPITCH_B + kb);
                af[mt][2] = *(const uint32_t*)(sA + r * GPITCH_B + kb + 16);
                af[mt][3] = *(const uint32_t*)(sA + (r + 8) * GPITCH_B + kb + 16);
            }
#pragma unroll
            for (int nt = 0; nt < 8; nt++) {
                const int n = wc * 64 + nt * 8 + g4;
                bf[nt][0] = *(const uint32_t*)(sB + n * GPITCH_B + kb);
                bf[nt][1] = *(const uint32_t*)(sB + n * GPITCH_B + kb + 16);
            }
#pragma unroll
            for (int mt = 0; mt < 4; mt++)
#pragma unroll
                for (int nt = 0; nt < 8; nt++)
                    mma_f16(acc[mt][nt], af[mt][0], af[mt][1], af[mt][2], af[mt][3],
                            bf[nt][0], bf[nt][1]);
        }
        __syncthreads();
    }

#pragma unroll
    for (int mt = 0; mt < 4; mt++) {
        const int r0 = by * 128 + wr * 64 + mt * 16 + g4;
#pragma unroll
        for (int nt = 0; nt < 8; nt++) {
            const int col = bx * 128 + wc * 64 + nt * 8 + t4 * 2;
            float b0 = 0.f, b1 = 0.f;
            if (bias) { b0 = __ldg(bias + col); b1 = __ldg(bias + col + 1); }
            float v0 = acc[mt][nt][0] + b0;
            float v1 = acc[mt][nt][1] + b1;
            float v2 = acc[mt][nt][2] + b0;
            float v3 = acc[mt][nt][3] + b1;
            if (EPI == 1) {
                v0 = gelu_tanh(v0); v1 = gelu_tanh(v1);
                v2 = gelu_tanh(v2); v3 = gelu_tanh(v3);
            }
            if (OUTH) {
                __half* Ch = (__half*)Cout;
                if (r0 < M) *(__half2*)(Ch + (size_t)r0 * N + col) = __floats2half2_rn(v0, v1);
                if (r0 + 8 < M) *(__half2*)(Ch + (size_t)(r0 + 8) * N + col) = __floats2half2_rn(v2, v3);
            } else {
                float* Cf = (float*)Cout;
                if (r0 < M) *(float2*)(Cf + (size_t)r0 * N + col) = make_float2(v0, v1);
                if (r0 + 8 < M) *(float2*)(Cf + (size_t)(r0 + 8) * N + col) = make_float2(v2, v3);
            }
        }
    }
}

// ============ fused LSTM step: gates = h@w_hhT (gate-interleaved) + gatesx; cell ============
// 8-warp layout retained. A = h fp16 [512,1024]; BT = wt_lhh_perm [4096,1024]; col n = 4j+g.
__global__ __launch_bounds__(256, 2)
void lstm_step_tc(const __half* __restrict__ A, const __half* __restrict__ BT,
                  const float* __restrict__ gx, float* __restrict__ cst,
                  __half* __restrict__ hnext, float* __restrict__ lout, int t) {
    extern __shared__ char smem[];
    const uint32_t sb = (uint32_t)__cvta_generic_to_shared(smem);
    const int tid = threadIdx.x;
    const int lane = tid & 31;
    const int wid = tid >> 5;
    const int wr = wid >> 2;
    const int wc = wid & 3;
    const int bx = blockIdx.x, by = blockIdx.y;
    const int gra = by * 128;
    const int gnb = bx * 128;
    const int K = 1024, nk = 32;

    float acc[4][4][4];
#pragma unroll
    for (int mt = 0; mt < 4; mt++)
#pragma unroll
        for (int nt = 0; nt < 4; nt++)
#pragma unroll
            for (int q = 0; q < 4; q++) acc[mt][nt][q] = 0.f;

    auto load_stage = [&](int kc, int p) {
        const uint32_t sbase = sb + p * GSTAGE_B;
#pragma unroll
        for (int i = 0; i < 2; i++) {
            const int c = tid + i * 256;
            const int row = c >> 2, seg = c & 3;
            cp_async16(sbase + row * GPITCH_B + seg * 16,
                       A + (size_t)(gra + row) * K + kc * 32 + seg * 8, 16);
            cp_async16(sbase + GOP_BYTES + row * GPITCH_B + seg * 16,
                       BT + (size_t)(gnb + row) * K + kc * 32 + seg * 8, 16);
        }
    };

    load_stage(0, 0);
    cp_commit();

    for (int kc = 0; kc < nk; kc++) {
        const int p = kc & 1;
        if (kc + 1 < nk) {
            load_stage(kc + 1, p ^ 1);
            cp_commit();
            asm volatile("cp.async.wait_group 1;");
        } else {
            asm volatile("cp.async.wait_group 0;");
        }
        __syncthreads();
        const char* sA = smem + p * GSTAGE_B;
        const char* sB = sA + GOP_BYTES;
#pragma unroll
        for (int ks = 0; ks < 2; ks++) {
            const int kb = ks * 32 + (lane & 3) * 4;
            uint32_t af[4][4];
            uint32_t bf[4][2];
#pragma unroll
            for (int mt = 0; mt < 4; mt++) {
                const int r = wr * 64 + mt * 16 + (lane >> 2);
                af[mt][0] = *(const uint32_t*)(sA + r * GPITCH_B + kb);
                af[mt][1] = *(const uint32_t*)(sA + (r + 8) * GPITCH_B + kb);
                af[mt][2] = *(const uint32_t*)(sA + r * GPITCH_B + kb + 16);
                af[mt][3] = *(const uint32_t*)(sA + (r + 8) * GPITCH_B + kb + 16);
            }
#pragma unroll
            for (int nt = 0; nt < 4; nt++) {
                const int n = wc * 32 + nt * 8 + (lane >> 2);
                bf[nt][0] = *(const uint32_t*)(sB + n * GPITCH_B + kb);
                bf[nt][1] = *(const uint32_t*)(sB + n * GPITCH_B + kb + 16);
            }
#pragma unroll
            for (int mt = 0; mt < 4; mt++)
#pragma unroll
                for (int nt = 0; nt < 4; nt++)
                    mma_f16(acc[mt][nt], af[mt][0], af[mt][1], af[mt][2], af[mt][3],
                            bf[nt][0], bf[nt][1]);
        }
        __syncthreads();
    }

    // fused cell epilogue (gate-interleaved columns: col = 4j+g)
#pragma unroll
    for (int mt = 0; mt < 4; mt++) {
        const int r0 = by * 128 + wr * 64 + mt * 16 + (lane >> 2);
        const int r1 = r0 + 8;
        const int tok0 = ((r0 >> 8) << 12) + (t << 8) + (r0 & 255);
        const int tok1 = ((r1 >> 8) << 12) + (t << 8) + (r1 & 255);
#pragma unroll
        for (int nt = 0; nt < 4; nt++) {
            const int col = bx * 128 + wc * 32 + nt * 8 + (lane & 3) * 2;
            float v0 = acc[mt][nt][0] + __ldg(gx + (size_t)tok0 * 4096 + col);
            float v1 = acc[mt][nt][1] + __ldg(gx + (size_t)tok0 * 4096 + col + 1);
            float v2 = acc[mt][nt][2] + __ldg(gx + (size_t)tok1 * 4096 + col);
            float v3 = acc[mt][nt][3] + __ldg(gx + (size_t)tok1 * 4096 + col + 1);
            float p0 = __shfl_xor_sync(0xffffffffu, v0, 1);
            float p1 = __shfl_xor_sync(0xffffffffu, v1, 1);
            float p2 = __shfl_xor_sync(0xffffffffu, v2, 1);
            float p3 = __shfl_xor_sync(0xffffffffu, v3, 1);
            if (!(lane & 1)) {
                const int j = col >> 2;
                {
                    float cc = sigm(v1) * cst[r0 * 1024 + j] + sigm(v0) * tanhf(p0);
                    float hh = sigm(p1) * tanhf(cc);
                    cst[r0 * 1024 + j] = cc;
                    hnext[r0 * 1024 + j] = __float2half(hh);
                    lout[(size_t)tok0 * 1024 + j] = hh;
                }
                {
                    float cc = sigm(v3) * cst[r1 * 1024 + j] + sigm(v2) * tanhf(p2);
                    float hh = sigm(p3) * tanhf(cc);
                    cst[r1 * 1024 + j] = cc;
                    hnext[r1 * 1024 + j] = __float2half(hh);
                    lout[(size_t)tok1 * 1024 + j] = hh;
                }
            }
        }
    }
}

// ---------------- weight transpose to fp16: WT[n][k]; PERM: n -> 4*(n%1024)+(n/1024) ----
template<int PERM>
__global__ __launch_bounds__(256)
void transpose_kernel(const float* __restrict__ W, __half* __restrict__ WT, int K, int N) {
    __shared__ float t[32][33];
    const int n0 = blockIdx.x * 32, k0 = blockIdx.y * 32;
    const int tx = threadIdx.x & 31, ty = threadIdx.x >> 5;
#pragma unroll
    for (int j = 0; j < 4; j++)
        t[ty + j * 8][tx] = W[(size_t)(k0 + ty + j * 8) * N + n0 + tx];
    __syncthreads();
#pragma unroll
    for (int j = 0; j < 4; j++) {
        int n = n0 + ty + j * 8;
        int nd = PERM ? (4 * (n & 1023) + (n >> 10)) : n;
        WT[(size_t)nd * K + k0 + tx] = __float2half(t[tx][ty + j * 8]);
    }
}

// ---------------- LayerNorm + adaLN modulate (fp16 out) ----------------
__global__ __launch_bounds__(256)
void ln_mod_kernel(const float* __restrict__ x, const float* __restrict__ mod,
                   int mstride, int shift_off, int scale_off, __half* __restrict__ out) {
    __shared__ float red[16];
    const int tok = blockIdx.x;
    const int tid = threadIdx.x;
    const float* xr = x + (size_t)tok * DD;
    float v[4];
    float s = 0.f, s2 = 0.f;
#pragma unroll
    for (int k = 0; k < 4; k++) {
        float f = xr[tid + k * 256];
        v[k] = f; s += f; s2 += f * f;
    }
#pragma unroll
    for (int o = 16; o; o >>= 1) {
        s += __shfl_xor_sync(0xffffffffu, s, o);
        s2 += __shfl_xor_sync(0xffffffffu, s2, o);
    }
    if ((tid & 31) == 0) { red[tid >> 5] = s; red[8 + (tid >> 5)] = s2; }
    __syncthreads();
    if (tid == 0) {
        float a = 0.f, b = 0.f;
        for (int i = 0; i < 8; i++) { a += red[i]; b += red[8 + i]; }
        red[0] = a; red[8] = b;
    }
    __syncthreads();
    const float mean = red[0] * (1.f / DD);
    const float var = red[8] * (1.f / DD) - mean * mean;
    const float inv = rsqrtf(var + 1e-6f);
    const int bt = tok >> 8;
    const float* m = mod + (size_t)bt * mstride;
    __half* orow = out + (size_t)tok * DD;
#pragma unroll
    for (int k = 0; k < 4; k++) {
        int d = tid + k * 256;
        float ln = (v[k] - mean) * inv;
        orow[d] = __float2half(ln * (1.f + m[scale_off + d]) + m[shift_off + d]);
    }
}

// ---------------- fused gated residual add + LayerNorm + modulate ----------------
__global__ __launch_bounds__(256)
void ga_ln_kernel(const float* __restrict__ xin, const float* __restrict__ delta,
                  const float* __restrict__ modg, int gstride, int gate_off,
                  const float* __restrict__ modl, int lstride, int shift_off, int scale_off,
                  float* __restrict__ xout, __half* __restrict__ lnout) {
    __shared__ float red[16];
    const int tok = blockIdx.x;
    const int tid = threadIdx.x;
    const int bt = tok >> 8;
    const float* xr = xin + (size_t)tok * DD;
    const float* dr = delta + (size_t)tok * DD;
    const float* mg = modg + (size_t)bt * gstride + gate_off;
    float v[4];
    float s = 0.f, s2 = 0.f;
    float* xo = xout + (size_t)tok * DD;
#pragma unroll
    for (int k = 0; k < 4; k++) {
        int d = tid + k * 256;
        float f = xr[d] + mg[d] * dr[d];
        xo[d] = f;
        v[k] = f; s += f; s2 += f * f;
    }
#pragma unroll
    for (int o = 16; o; o >>= 1) {
        s += __shfl_xor_sync(0xffffffffu, s, o);
        s2 += __shfl_xor_sync(0xffffffffu, s2, o);
    }
    if ((tid & 31) == 0) { red[tid >> 5] = s; red[8 + (tid >> 5)] = s2; }
    __syncthreads();
    if (tid == 0) {
        float a = 0.f, b = 0.f;
        for (int i = 0; i < 8; i++) { a += red[i]; b += red[8 + i]; }
        red[0] = a; red[8] = b;
    }
    __syncthreads();
    const float mean = red[0] * (1.f / DD);
    const float var = red[8] * (1.f / DD) - mean * mean;
    const float inv = rsqrtf(var + 1e-6f);
    const float* ml = modl + (size_t)bt * lstride;
    __half* lo = lnout + (size_t)tok * DD;
#pragma unroll
    for (int k = 0; k < 4; k++) {
        int d = tid + k * 256;
        float ln = (v[k] - mean) * inv;
        lo[d] = __float2half(ln * (1.f + ml[scale_off + d]) + ml[shift_off + d]);
    }
}

// ---------------- gated residual add (final) ----------------
__global__ __launch_bounds__(256)
void gated_add_kernel(const float* __restrict__ xin, const float* __restrict__ delta,
                      const float* __restrict__ mod, int mstride, int gate_off,
                      float* __restrict__ xout) {
    int idx = blockIdx.x * 256 + threadIdx.x;
    int tok = idx >> 10, d = idx & 1023;
    int bt = tok >> 8;
    xout[idx] = xin[idx] + mod[(size_t)bt * mstride + gate_off + d] * delta[idx];
}

// ---------------- small utilities ----------------
__global__ void silu_kernel(const float* __restrict__ c, __half* __restrict__ out, int n) {
    int i = blockIdx.x * 256 + threadIdx.x;
    if (i < n) { float v = c[i]; out[i] = __float2half(v / (1.f + expf(-v))); }
}
__global__ void lstm_bias_kernel(const float* __restrict__ a, const float* __restrict__ b,
                                 float* __restrict__ o, int n) {
    int i = blockIdx.x * 256 + threadIdx.x;
    if (i < n) {
        int j = i >> 2, g = i & 3;
        o[i] = a[g * 1024 + j] + b[g * 1024 + j];
    }
}
__global__ void zero_state_kernel(__half* __restrict__ h0, __half* __restrict__ h1,
                                  float* __restrict__ c, int n) {
    int i = blockIdx.x * 256 + threadIdx.x;
    if (i < n) { h0[i] = __float2half(0.f); h1[i] = __float2half(0.f); c[i] = 0.f; }
}

// ======= spatial attention via mma.sync fp16 flash (L=256, dh=64, non-causal) =======
__global__ __launch_bounds__(256, 2)
void spatial_attn_tc(const __half* __restrict__ qkv, __half* __restrict__ out) {
    __shared__ __half sQ[128 * 72];
    __shared__ __half sK[64 * 72];
    __shared__ __half sVT[64 * 72];
    const int bid = blockIdx.x;
    const int qhalf = bid & 1;
    const int head = (bid >> 1) & 15;
    const int n = bid >> 5;
    const int tid = threadIdx.x;
    const int lane = tid & 31;
    const int wid = tid >> 5;
    const int g4 = lane >> 2, t4 = lane & 3;
    const size_t rowbase = (size_t)n * 256;

#pragma unroll
    for (int i = 0; i < 4; i++) {
        int idx = tid + i * 256;
        int row = idx >> 3, seg = idx & 7;
        *(uint4*)&sQ[row * 72 + seg * 8] =
            *(const uint4*)(qkv + (rowbase + qhalf * 128 + row) * 3072 + head * 64 + seg * 8);
    }
    __syncthreads();

    uint32_t af[4][4];
    {
        const int r = wid * 16 + g4;
#pragma unroll
        for (int ks = 0; ks < 4; ks++) {
            af[ks][0] = *(const uint32_t*)&sQ[r * 72 + ks * 16 + t4 * 2];
            af[ks][1] = *(const uint32_t*)&sQ[(r + 8) * 72 + ks * 16 + t4 * 2];
            af[ks][2] = *(const uint32_t*)&sQ[r * 72 + ks * 16 + 8 + t4 * 2];
            af[ks][3] = *(const uint32_t*)&sQ[(r + 8) * 72 + ks * 16 + 8 + t4 * 2];
        }
    }

    float O[8][4];
#pragma unroll
    for (int i = 0; i < 8; i++)
#pragma unroll
        for (int q = 0; q < 4; q++) O[i][q] = 0.f;
    float m0 = -1e30f, m1 = -1e30f, l0 = 0.f, l1 = 0.f;

    for (int kt = 0; kt < 4; kt++) {
#pragma unroll
        for (int i = 0; i < 2; i++) {
            int idx = tid + i * 256;
            int row = idx >> 3, seg = idx & 7;
            const __half* src = qkv + (rowbase + kt * 64 + row) * 3072 + 1024 + head * 64 + seg * 8;
            *(uint4*)&sK[row * 72 + seg * 8] = *(const uint4*)src;
            __half vv[8];
            *(uint4*)vv = *(const uint4*)(src + 1024);
#pragma unroll
            for (int jj = 0; jj < 8; jj++) sVT[(seg * 8 + jj) * 72 + row] = vv[jj];
        }
        __syncthreads();

        float sc[8][4];
#pragma unroll
        for (int nt = 0; nt < 8; nt++) {
#pragma unroll
            for (int q = 0; q < 4; q++) sc[nt][q] = 0.f;
#pragma unroll
            for (int ks = 0; ks < 4; ks++) {
                uint32_t b0 = *(const uint32_t*)&sK[(nt * 8 + g4) * 72 + ks * 16 + t4 * 2];
                uint32_t b1 = *(const uint32_t*)&sK[(nt * 8 + g4) * 72 + ks * 16 + 8 + t4 * 2];
                mma_f16(sc[nt], af[ks][0], af[ks][1], af[ks][2], af[ks][3], b0, b1);
            }
        }

        float mx0 = -1e30f, mx1 = -1e30f;
#pragma unroll
        for (int nt = 0; nt < 8; nt++) {
            sc[nt][0] *= 0.125f; sc[nt][1] *= 0.125f;
            sc[nt][2] *= 0.125f; sc[nt][3] *= 0.125f;
            mx0 = fmaxf(mx0, fmaxf(sc[nt][0], sc[nt][1]));
            mx1 = fmaxf(mx1, fmaxf(sc[nt][2], sc[nt][3]));
        }
        mx0 = fmaxf(mx0, __shfl_xor_sync(0xffffffffu, mx0, 1));
        mx0 = fmaxf(mx0, __shfl_xor_sync(0xffffffffu, mx0, 2));
        mx1 = fmaxf(mx1, __shfl_xor_sync(0xffffffffu, mx1, 1));
        mx1 = fmaxf(mx1, __shfl_xor_sync(0xffffffffu, mx1, 2));
        const float mn0 = fmaxf(m0, mx0), mn1 = fmaxf(m1, mx1);
        const float al0 = __expf(m0 - mn0), al1 = __expf(m1 - mn1);
        m0 = mn0; m1 = mn1;

        float sum0 = 0.f, sum1 = 0.f;
        uint32_t aP[8][2];
#pragma unroll
        for (int nt = 0; nt < 8; nt++) {
            float p0 = __expf(sc[nt][0] - mn0);
            float p1 = __expf(sc[nt][1] - mn0);
            float p2 = __expf(sc[nt][2] - mn1);
            float p3 = __expf(sc[nt][3] - mn1);
            sum0 += p0 + p1; sum1 += p2 + p3;
            aP[nt][0] = h2_as_u32(__floats2half2_rn(p0, p1));
            aP[nt][1] = h2_as_u32(__floats2half2_rn(p2, p3));
        }
        sum0 += __shfl_xor_sync(0xffffffffu, sum0, 1);
        sum0 += __shfl_xor_sync(0xffffffffu, sum0, 2);
        sum1 += __shfl_xor_sync(0xffffffffu, sum1, 1);
        sum1 += __shfl_xor_sync(0xffffffffu, sum1, 2);
        l0 = l0 * al0 + sum0;
        l1 = l1 * al1 + sum1;
#pragma unroll
        for (int nt2 = 0; nt2 < 8; nt2++) {
            O[nt2][0] *= al0; O[nt2][1] *= al0;
            O[nt2][2] *= al1; O[nt2][3] *= al1;
        }

#pragma unroll
        for (int ks2 = 0; ks2 < 4; ks2++) {
            const uint32_t a0 = aP[2 * ks2][0], a1 = aP[2 * ks2][1];
            const uint32_t a2 = aP[2 * ks2 + 1][0], a3 = aP[2 * ks2 + 1][1];
#pragma unroll
            for (int nt2 = 0; nt2 < 8; nt2++) {
                uint32_t b0 = *(const uint32_t*)&sVT[(nt2 * 8 + g4) * 72 + ks2 * 16 + t4 * 2];
                uint32_t b1 = *(const uint32_t*)&sVT[(nt2 * 8 + g4) * 72 + ks2 * 16 + 8 + t4 * 2];
                mma_f16(O[nt2], a0, a1, a2, a3, b0, b1);
            }
        }
        __syncthreads();
    }

    const float inv0 = 1.f / l0, inv1 = 1.f / l1;
    const int q0 = qhalf * 128 + wid * 16 + g4;
#pragma unroll
    for (int nt2 = 0; nt2 < 8; nt2++) {
        const int col = head * 64 + nt2 * 8 + t4 * 2;
        *(__half2*)(out + (rowbase + q0) * 1024 + col) =
            __floats2half2_rn(O[nt2][0] * inv0, O[nt2][1] * inv0);
        *(__half2*)(out + (rowbase + q0 + 8) * 1024 + col) =
            __floats2half2_rn(O[nt2][2] * inv1, O[nt2][3] * inv1);
    }
}

// ---------------- temporal attention (T=16, dh=64, causal; fp16 qkv in/out) ----------------
__global__ __launch_bounds__(128)
void temporal_attn_kernel(const __half* __restrict__ qkv, __half* __restrict__ out) {
    __shared__ float Q[16][65], K[16][65], V[16][65], S[16][17];
    const int bid = blockIdx.x;
    const int head = bid & 15;
    const int n = bid >> 4;
    const int b = n >> 8;
    const int hw = n & 255;
    const int tid = threadIdx.x;
    const size_t tokbase = (size_t)b * 4096 + hw;

    for (int i = tid; i < 16 * 64; i += 128) {
        int t = i >> 6, d = i & 63;
        size_t base = (tokbase + (size_t)t * 256) * 3072 + head * 64 + d;
        Q[t][d] = __half2float(qkv[base]);
        K[t][d] = __half2float(qkv[base + 1024]);
        V[t][d] = __half2float(qkv[base + 2048]);
    }
    __syncthreads();

    for (int idx = tid; idx < 256; idx += 128) {
        int qi = idx >> 4, kj = idx & 15;
        float s;
        if (kj <= qi) {
            float acc = 0.f;
#pragma unroll
            for (int d = 0; d < 64; d++) acc += Q[qi][d] * K[kj][d];
            s = acc * 0.125f;
        } else s = -1e30f;
        S[qi][kj] = s;
    }
    __syncthreads();

    {
        const int row = tid >> 3, c0 = tid & 7;
        float mx = fmaxf(S[row][c0], S[row][c0 + 8]);
#pragma unroll
        for (int o = 4; o; o >>= 1) mx = fmaxf(mx, __shfl_xor_sync(0xffffffffu, mx, o));
        float e0 = expf(S[row][c0] - mx), e1 = expf(S[row][c0 + 8] - mx);
        float sum = e0 + e1;
#pragma unroll
        for (int o = 4; o; o >>= 1) sum += __shfl_xor_sync(0xffffffffu, sum, o);
        float inv = 1.f / sum;
        S[row][c0] = e0 * inv;
        S[row][c0 + 8] = e1 * inv;
    }
    __syncthreads();

    for (int i = tid; i < 16 * 64; i += 128) {
        int qi = i >> 6, d = i & 63;
        float acc = 0.f;
#pragma unroll
        for (int k = 0; k < 16; k++) acc = fmaf(S[qi][k], V[k][d], acc);
        out[(tokbase + (size_t)qi * 256) * 1024 + head * 64 + d] = __float2half(acc);
    }
}

// ---------------- launch helpers ----------------
static void gemm(const __half* A, const __half* BT, const float* bias, void* C,
                 int M, int N, int K, int epi, int outh) {
    dim3 g(N / 128, (M + 127) / 128);
    if (epi == 1)      gemm_tc<1, 1><<<g, 128, GTC_SMEM_TOTAL>>>(A, BT, bias, C, M, N, K);
    else if (outh)     gemm_tc<0, 1><<<g, 128, GTC_SMEM_TOTAL>>>(A, BT, bias, C, M, N, K);
    else               gemm_tc<0, 0><<<g, 128, GTC_SMEM_TOTAL>>>(A, BT, bias, C, M, N, K);
}
static void wtrans(const float* W, __half* WT, int K, int N) {
    transpose_kernel<0><<<dim3(N / 32, K / 32), 256>>>(W, WT, K, N);
}
static void wtrans_perm(const float* W, __half* WT, int K, int N) {
    transpose_kernel<1><<<dim3(N / 32, K / 32), 256>>>(W, WT, K, N);
}

extern "C" void kernel_launch(void* const* d_in, const int* in_sizes, int n_in,
                              void* d_out, int out_size) {
    const float* x        = (const float*)d_in[0];
    const float* c        = (const float*)d_in[1];
    const float* s_ada_w  = (const float*)d_in[2];
    const float* s_ada_b  = (const float*)d_in[3];
    const float* t_ada_w  = (const float*)d_in[4];
    const float* t_ada_b  = (const float*)d_in[5];
    const float* r_ada_w  = (const float*)d_in[6];
    const float* r_ada_b  = (const float*)d_in[7];
    const float* s_qkv_w  = (const float*)d_in[8];
    const float* s_out_w  = (const float*)d_in[9];
    const float* s_out_b  = (const float*)d_in[10];
    const float* t_qkv_w  = (const float*)d_in[11];
    const float* t_out_w  = (const float*)d_in[12];
    const float* t_out_b  = (const float*)d_in[13];
    const float* s_mlp_w1 = (const float*)d_in[14];
    const float* s_mlp_b1 = (const float*)d_in[15];
    const float* s_mlp_w2 = (const float*)d_in[16];
    const float* s_mlp_b2 = (const float*)d_in[17];
    const float* t_mlp_w1 = (const float*)d_in[18];
    const float* t_mlp_b1 = (const float*)d_in[19];
    const float* t_mlp_w2 = (const float*)d_in[20];
    const float* t_mlp_b2 = (const float*)d_in[21];
    const float* lstm_w_ih = (const float*)d_in[22];
    const float* lstm_w_hh = (const float*)d_in[23];
    const float* lstm_b_ih = (const float*)d_in[24];
    const float* lstm_b_hh = (const float*)d_in[25];
    float* out = (float*)d_out;

    __half *csh, *h1h, *qkvh, *mlph, *hstateh, *hstate2h, *wTh;
    float *smod, *tmod, *rmod, *xbuf, *delta, *gatesx, *cstate, *lstmout, *lstmbias;
    cudaGetSymbolAddress((void**)&csh, g_csh);
    cudaGetSymbolAddress((void**)&smod, g_smod);
    cudaGetSymbolAddress((void**)&tmod, g_tmod);
    cudaGetSymbolAddress((void**)&rmod, g_rmod);
    cudaGetSymbolAddress((void**)&xbuf, g_xbuf);
    cudaGetSymbolAddress((void**)&h1h, g_h1h);
    cudaGetSymbolAddress((void**)&qkvh, g_qkvh);
    cudaGetSymbolAddress((void**)&delta, g_delta);
    cudaGetSymbolAddress((void**)&mlph, g_mlph);
    cudaGetSymbolAddress((void**)&gatesx, g_gatesx);
    cudaGetSymbolAddress((void**)&hstateh, g_hstateh);
    cudaGetSymbolAddress((void**)&hstate2h, g_hstate2h);
    cudaGetSymbolAddress((void**)&cstate, g_cstate);
    cudaGetSymbolAddress((void**)&lstmout, g_lstmout);
    cudaGetSymbolAddress((void**)&lstmbias, g_lstmbias);
    cudaGetSymbolAddress((void**)&wTh, g_wTh);

    const size_t MEG = 1048576;
    __half* wt_sada  = wTh + 0 * MEG;
    __half* wt_tada  = wTh + 6 * MEG;
    __half* wt_rada  = wTh + 12 * MEG;
    __half* wt_sqkv  = wTh + 15 * MEG;
    __half* wt_sout  = wTh + 18 * MEG;
    __half* wt_tqkv  = wTh + 19 * MEG;
    __half* wt_tout  = wTh + 22 * MEG;
    __half* wt_smlp1 = wTh + 23 * MEG;
    __half* wt_smlp2 = wTh + 27 * MEG;
    __half* wt_tmlp1 = wTh + 31 * MEG;
    __half* wt_tmlp2 = wTh + 35 * MEG;
    __half* wt_lih   = wTh + 39 * MEG;  // gate-interleaved [4096,1024]
    __half* wt_lhh   = wTh + 43 * MEG;  // gate-interleaved [4096,1024]

    wtrans(s_ada_w, wt_sada, 1024, 6144);
    wtrans(t_ada_w, wt_tada, 1024, 6144);
    wtrans(r_ada_w, wt_rada, 1024, 3072);
    wtrans(s_qkv_w, wt_sqkv, 1024, 3072);
    wtrans(s_out_w, wt_sout, 1024, 1024);
    wtrans(t_qkv_w, wt_tqkv, 1024, 3072);
    wtrans(t_out_w, wt_tout, 1024, 1024);
    wtrans(s_mlp_w1, wt_smlp1, 1024, 4096);
    wtrans(s_mlp_w2, wt_smlp2, 4096, 1024);
    wtrans(t_mlp_w1, wt_tmlp1, 1024, 4096);
    wtrans(t_mlp_w2, wt_tmlp2, 4096, 1024);
    wtrans_perm(lstm_w_ih, wt_lih, 1024, 4096);
    wtrans_perm(lstm_w_hh, wt_lhh, 1024, 4096);

    const int NEL = NTOK * DD;
    const int EW_BLOCKS = NEL / 256;

    // conditioning
    silu_kernel<<<(NBT * DD + 255) / 256, 256>>>(c, csh, NBT * DD);
    gemm(csh, wt_sada, s_ada_b, smod, NBT, 6 * DD, DD, 0, 0);
    gemm(csh, wt_tada, t_ada_b, tmod, NBT, 6 * DD, DD, 0, 0);
    gemm(csh, wt_rada, r_ada_b, rmod, NBT, 3 * DD, DD, 0, 0);

    // ---- spatial attention ----
    ln_mod_kernel<<<NTOK, 256>>>(x, smod, 6 * DD, 0, DD, h1h);
    gemm(h1h, wt_sqkv, nullptr, qkvh, NTOK, 3 * DD, DD, 0, 1);
    spatial_attn_tc<<<1024, 256>>>(qkvh, h1h);
    gemm(h1h, wt_sout, s_out_b, delta, NTOK, DD, DD, 0, 0);
    ga_ln_kernel<<<NTOK, 256>>>(x, delta, smod, 6 * DD, 2 * DD,
                                smod, 6 * DD, 3 * DD, 4 * DD, xbuf, h1h);

    // ---- spatial MLP ----
    gemm(h1h, wt_smlp1, s_mlp_b1, mlph, NTOK, 4 * DD, DD, 1, 1);
    gemm(mlph, wt_smlp2, s_mlp_b2, delta, NTOK, DD, 4 * DD, 0, 0);
    ga_ln_kernel<<<NTOK, 256>>>(xbuf, delta, smod, 6 * DD, 5 * DD,
                                tmod, 6 * DD, 0, DD, xbuf, h1h);

    // ---- temporal attention (causal) ----
    gemm(h1h, wt_tqkv, nullptr, qkvh, NTOK, 3 * DD, DD, 0, 1);
    temporal_attn_kernel<<<8192, 128>>>(qkvh, h1h);
    gemm(h1h, wt_tout, t_out_b, delta, NTOK, DD, DD, 0, 0);
    ga_ln_kernel<<<NTOK, 256>>>(xbuf, delta, tmod, 6 * DD, 2 * DD,
                                tmod, 6 * DD, 3 * DD, 4 * DD, xbuf, h1h);

    // ---- temporal MLP ----
    gemm(h1h, wt_tmlp1, t_mlp_b1, mlph, NTOK, 4 * DD, DD, 1, 1);
    gemm(mlph, wt_tmlp2, t_mlp_b2, delta, NTOK, DD, 4 * DD, 0, 0);
    ga_ln_kernel<<<NTOK, 256>>>(xbuf, delta, tmod, 6 * DD, 5 * DD,
                                rmod, 3 * DD, 0, DD, xbuf, h1h);

    // ---- LSTM branch (gate-interleaved, fused cell) ----
    lstm_bias_kernel<<<(4 * DD + 255) / 256, 256>>>(lstm_b_ih, lstm_b_hh, lstmbias, 4 * DD);
    gemm(h1h, wt_lih, lstmbias, gatesx, NTOK, 4 * DD, DD, 0, 0);
    zero_state_kernel<<<(NSEQ * DD + 255) / 256, 256>>>(hstateh, hstate2h, cstate, NSEQ * DD);
    {
        __half* hb[2] = {hstateh, hstate2h};
        for (int t = 0; t < TT; t++) {
            lstm_step_tc<<<dim3(32, 4), 256, GTC_SMEM_TOTAL>>>(
                hb[t & 1], wt_lhh, gatesx, cstate, hb[(t + 1) & 1], lstmout, t);
        }
    }
    gated_add_kernel<<<EW_BLOCKS, 256>>>(xbuf, lstmout, rmod, 3 * DD, 2 * DD, out);
}

// round 8
// speedup vs baseline: 5.6510x; 1.0075x over previous
#include <cuda_runtime.h>
#include <cuda_fp16.h>
#include <math.h>
#include <cstdint>

// Problem constants
#define DD   1024
#define NTOK 8192      // B*T*H*W
#define NBT  32        // B*T
#define NSEQ 512       // B*H*W
#define TT   16

// ---------------- scratch (device globals; no allocations allowed) ----------------
__device__ __half g_csh[NBT * DD];
__device__ float  g_smod[NBT * 6 * DD];
__device__ float  g_tmod[NBT * 6 * DD];
__device__ float  g_rmod[NBT * 3 * DD];
__device__ float  g_xbuf[NTOK * DD];
__device__ __half g_h1h[NTOK * DD];
__device__ __half g_qkvh[NTOK * 3 * DD];
__device__ float  g_delta[NTOK * DD];
__device__ __half g_mlph[NTOK * 4 * DD];
__device__ float  g_gatesx[NTOK * 4 * DD];
__device__ __half g_hstateh[NSEQ * DD];
__device__ __half g_hstate2h[NSEQ * DD];
__device__ float  g_cstate[NSEQ * DD];
__device__ float  g_lstmout[NTOK * DD];
__device__ float  g_lstmbias[4 * DD];
__device__ __half g_wTh[47u * 1048576u];   // transposed fp16 weights

__device__ __forceinline__ float tanh_fast(float x) {
    float r; asm("tanh.approx.f32 %0, %1;" : "=f"(r) : "f"(x)); return r;
}
__device__ __forceinline__ float gelu_tanh(float x) {
    return 0.5f * x * (1.f + tanh_fast(0.7978845608028654f * (x + 0.044715f * x * x * x)));
}
__device__ __forceinline__ float sigm(float x) { return 0.5f * (1.f + tanh_fast(0.5f * x)); }
__device__ __forceinline__ uint32_t h2_as_u32(__half2 h) {
    uint32_t u; *reinterpret_cast<__half2*>(&u) = h; return u;
}
__device__ __forceinline__ void mma_f16(float d[4], uint32_t a0, uint32_t a1, uint32_t a2,
                                        uint32_t a3, uint32_t b0, uint32_t b1) {
    asm volatile(
        "mma.sync.aligned.m16n8k16.row.col.f32.f16.f16.f32 "
        "{%0,%1,%2,%3}, {%4,%5,%6,%7}, {%8,%9}, {%0,%1,%2,%3};\n"
        : "+f"(d[0]), "+f"(d[1]), "+f"(d[2]), "+f"(d[3])
        : "r"(a0), "r"(a1), "r"(a2), "r"(a3), "r"(b0), "r"(b1));
}
__device__ __forceinline__ void cp_async16(uint32_t dst, const void* src, int szvalid) {
    asm volatile("cp.async.cg.shared.global [%0], [%1], 16, %2;"
                 :: "r"(dst), "l"(src), "r"(szvalid));
}
__device__ __forceinline__ void cp_commit() { asm volatile("cp.async.commit_group;"); }

// ================== fp16 tensor-core GEMM: C[M,N] = A[M,K] @ BT[N,K]^T ==================
// 128 threads = 4 warps (2x2), warp tile 64x64, block tile 128x128x32, 4-stage cp.async.
#define GPITCH_B   80
#define GOP_BYTES  (128 * GPITCH_B)
#define GSTAGE_B   (2 * GOP_BYTES)       // 20480 per stage
#define GTC_NSTAGE 4
#define GTC_SMEM_TOTAL (GTC_NSTAGE * GSTAGE_B)   // 81920 bytes
#define LSTM_SMEM_TOTAL (2 * GSTAGE_B)           // 40960 bytes (2-stage)

template<int EPI, int OUTH>
__global__ __launch_bounds__(128, 2)
void gemm_tc(const __half* __restrict__ A, const __half* __restrict__ BT,
             const float* __restrict__ bias, void* __restrict__ Cout,
             int M, int N, int K) {
    extern __shared__ char smem[];
    const uint32_t sb = (uint32_t)__cvta_generic_to_shared(smem);
    const int tid = threadIdx.x;
    const int lane = tid & 31;
    const int wid = tid >> 5;
    const int wr = wid >> 1;        // 0..1
    const int wc = wid & 1;         // 0..1
    const int g4 = lane >> 2, t4 = lane & 3;
    const int bx = blockIdx.x, by = blockIdx.y;
    const int gra = by * 128;
    const int gnb = bx * 128;

    float acc[4][8][4];
#pragma unroll
    for (int mt = 0; mt < 4; mt++)
#pragma unroll
        for (int nt = 0; nt < 8; nt++)
#pragma unroll
            for (int q = 0; q < 4; q++) acc[mt][nt][q] = 0.f;

    const int nk = K >> 5;

    auto load_stage = [&](int kc, int s) {
        const uint32_t sbase = sb + s * GSTAGE_B;
#pragma unroll
        for (int i = 0; i < 4; i++) {
            const int c = tid + i * 128;
            const int row = c >> 2, seg = c & 3;
            const int ga = gra + row;
            const bool ok = ga < M;
            cp_async16(sbase + row * GPITCH_B + seg * 16,
                       A + (size_t)(ok ? ga : 0) * K + kc * 32 + seg * 8, ok ? 16 : 0);
            cp_async16(sbase + GOP_BYTES + row * GPITCH_B + seg * 16,
                       BT + (size_t)(gnb + row) * K + kc * 32 + seg * 8, 16);
        }
    };

    // prologue: 3 chunks in flight (nk >= 32 always here)
    load_stage(0, 0); cp_commit();
    load_stage(1, 1); cp_commit();
    load_stage(2, 2); cp_commit();

    for (int kc = 0; kc < nk; kc++) {
        // wait until chunk kc is resident: allowed pending = min(2, nk-1-kc)
        if (kc < nk - 2)      asm volatile("cp.async.wait_group 2;");
        else if (kc == nk - 2) asm volatile("cp.async.wait_group 1;");
        else                   asm volatile("cp.async.wait_group 0;");
        __syncthreads();
        if (kc + 3 < nk) { load_stage(kc + 3, (kc + 3) & (GTC_NSTAGE - 1)); cp_commit(); }

        const char* sA = smem + (kc & (GTC_NSTAGE - 1)) * GSTAGE_B;
        const char* sB = sA + GOP_BYTES;
#pragma unroll
        for (int ks = 0; ks < 2; ks++) {
            const int kb = ks * 32 + t4 * 4;
            uint32_t af[4][4];
            uint32_t bf[8][2];
#pragma unroll
            for (int mt = 0; mt < 4; mt++) {
                const int r = wr * 64 + mt * 16 + g4;
                af[mt][0] = *(const uint32_t*)(sA + r * GPITCH_B + kb);
                af[mt][1] = *(const uint32_t*)(sA + (r + 8) * GPITCH_B + kb);
                af[mt][2] = *(const uint32_t*)(sA + r * GPITCH_B + kb + 16);
                af[mt][3] = *(const uint32_t*)(sA + (r + 8) * GPITCH_B + kb + 16);
            }
#pragma unroll
            for (int nt = 0; nt < 8; nt++) {
                const int n = wc * 64 + nt * 8 + g4;
                bf[nt][0] = *(const uint32_t*)(sB + n * GPITCH_B + kb);
                bf[nt][1] = *(const uint32_t*)(sB + n * GPITCH_B + kb + 16);
            }
#pragma unroll
            for (int mt = 0; mt < 4; mt++)
#pragma unroll
                for (int nt = 0; nt < 8; nt++)
                    mma_f16(acc[mt][nt], af[mt][0], af[mt][1], af[mt][2], af[mt][3],
                            bf[nt][0], bf[nt][1]);
        }
    }

#pragma unroll
    for (int mt = 0; mt < 4; mt++) {
        const int r0 = by * 128 + wr * 64 + mt * 16 + g4;
#pragma unroll
        for (int nt = 0; nt < 8; nt++) {
            const int col = bx * 128 + wc * 64 + nt * 8 + t4 * 2;
            float b0 = 0.f, b1 = 0.f;
            if (bias) { b0 = __ldg(bias + col); b1 = __ldg(bias + col + 1); }
            float v0 = acc[mt][nt][0] + b0;
            float v1 = acc[mt][nt][1] + b1;
            float v2 = acc[mt][nt][2] + b0;
            float v3 = acc[mt][nt][3] + b1;
            if (EPI == 1) {
                v0 = gelu_tanh(v0); v1 = gelu_tanh(v1);
                v2 = gelu_tanh(v2); v3 = gelu_tanh(v3);
            }
            if (OUTH) {
                __half* Ch = (__half*)Cout;
                if (r0 < M) *(__half2*)(Ch + (size_t)r0 * N + col) = __floats2half2_rn(v0, v1);
                if (r0 + 8 < M) *(__half2*)(Ch + (size_t)(r0 + 8) * N + col) = __floats2half2_rn(v2, v3);
            } else {
                float* Cf = (float*)Cout;
                if (r0 < M) *(float2*)(Cf + (size_t)r0 * N + col) = make_float2(v0, v1);
                if (r0 + 8 < M) *(float2*)(Cf + (size_t)(r0 + 8) * N + col) = make_float2(v2, v3);
            }
        }
    }
}

// ============ fused LSTM step: gates = h@w_hhT (gate-interleaved) + gatesx; cell ============
// 8-warp layout, 2-stage. A = h fp16 [512,1024]; BT = wt_lhh_perm [4096,1024]; col n = 4j+g.
__global__ __launch_bounds__(256, 2)
void lstm_step_tc(const __half* __restrict__ A, const __half* __restrict__ BT,
                  const float* __restrict__ gx, float* __restrict__ cst,
                  __half* __restrict__ hnext, float* __restrict__ lout, int t) {
    extern __shared__ char smem[];
    const uint32_t sb = (uint32_t)__cvta_generic_to_shared(smem);
    const int tid = threadIdx.x;
    const int lane = tid & 31;
    const int wid = tid >> 5;
    const int wr = wid >> 2;
    const int wc = wid & 3;
    const int bx = blockIdx.x, by = blockIdx.y;
    const int gra = by * 128;
    const int gnb = bx * 128;
    const int K = 1024, nk = 32;

    float acc[4][4][4];
#pragma unroll
    for (int mt = 0; mt < 4; mt++)
#pragma unroll
        for (int nt = 0; nt < 4; nt++)
#pragma unroll
            for (int q = 0; q < 4; q++) acc[mt][nt][q] = 0.f;

    auto load_stage = [&](int kc, int p) {
        const uint32_t sbase = sb + p * GSTAGE_B;
#pragma unroll
        for (int i = 0; i < 2; i++) {
            const int c = tid + i * 256;
            const int row = c >> 2, seg = c & 3;
            cp_async16(sbase + row * GPITCH_B + seg * 16,
                       A + (size_t)(gra + row) * K + kc * 32 + seg * 8, 16);
            cp_async16(sbase + GOP_BYTES + row * GPITCH_B + seg * 16,
                       BT + (size_t)(gnb + row) * K + kc * 32 + seg * 8, 16);
        }
    };

    load_stage(0, 0);
    cp_commit();

    for (int kc = 0; kc < nk; kc++) {
        const int p = kc & 1;
        if (kc + 1 < nk) {
            load_stage(kc + 1, p ^ 1);
            cp_commit();
            asm volatile("cp.async.wait_group 1;");
        } else {
            asm volatile("cp.async.wait_group 0;");
        }
        __syncthreads();
        const char* sA = smem + p * GSTAGE_B;
        const char* sB = sA + GOP_BYTES;
#pragma unroll
        for (int ks = 0; ks < 2; ks++) {
            const int kb = ks * 32 + (lane & 3) * 4;
            uint32_t af[4][4];
            uint32_t bf[4][2];
#pragma unroll
            for (int mt = 0; mt < 4; mt++) {
                const int r = wr * 64 + mt * 16 + (lane >> 2);
                af[mt][0] = *(const uint32_t*)(sA + r * GPITCH_B + kb);
                af[mt][1] = *(const uint32_t*)(sA + (r + 8) * GPITCH_B + kb);
                af[mt][2] = *(const uint32_t*)(sA + r * GPITCH_B + kb + 16);
                af[mt][3] = *(const uint32_t*)(sA + (r + 8) * GPITCH_B + kb + 16);
            }
#pragma unroll
            for (int nt = 0; nt < 4; nt++) {
                const int n = wc * 32 + nt * 8 + (lane >> 2);
                bf[nt][0] = *(const uint32_t*)(sB + n * GPITCH_B + kb);
                bf[nt][1] = *(const uint32_t*)(sB + n * GPITCH_B + kb + 16);
            }
#pragma unroll
            for (int mt = 0; mt < 4; mt++)
#pragma unroll
                for (int nt = 0; nt < 4; nt++)
                    mma_f16(acc[mt][nt], af[mt][0], af[mt][1], af[mt][2], af[mt][3],
                            bf[nt][0], bf[nt][1]);
        }
        __syncthreads();
    }

    // fused cell epilogue (gate-interleaved columns: col = 4j+g)
#pragma unroll
    for (int mt = 0; mt < 4; mt++) {
        const int r0 = by * 128 + wr * 64 + mt * 16 + (lane >> 2);
        const int r1 = r0 + 8;
        const int tok0 = ((r0 >> 8) << 12) + (t << 8) + (r0 & 255);
        const int tok1 = ((r1 >> 8) << 12) + (t << 8) + (r1 & 255);
#pragma unroll
        for (int nt = 0; nt < 4; nt++) {
            const int col = bx * 128 + wc * 32 + nt * 8 + (lane & 3) * 2;
            float v0 = acc[mt][nt][0] + __ldg(gx + (size_t)tok0 * 4096 + col);
            float v1 = acc[mt][nt][1] + __ldg(gx + (size_t)tok0 * 4096 + col + 1);
            float v2 = acc[mt][nt][2] + __ldg(gx + (size_t)tok1 * 4096 + col);
            float v3 = acc[mt][nt][3] + __ldg(gx + (size_t)tok1 * 4096 + col + 1);
            float p0 = __shfl_xor_sync(0xffffffffu, v0, 1);
            float p1 = __shfl_xor_sync(0xffffffffu, v1, 1);
            float p2 = __shfl_xor_sync(0xffffffffu, v2, 1);
            float p3 = __shfl_xor_sync(0xffffffffu, v3, 1);
            if (!(lane & 1)) {
                const int j = col >> 2;
                {
                    float cc = sigm(v1) * cst[r0 * 1024 + j] + sigm(v0) * tanh_fast(p0);
                    float hh = sigm(p1) * tanh_fast(cc);
                    cst[r0 * 1024 + j] = cc;
                    hnext[r0 * 1024 + j] = __float2half(hh);
                    lout[(size_t)tok0 * 1024 + j] = hh;
                }
                {
                    float cc = sigm(v3) * cst[r1 * 1024 + j] + sigm(v2) * tanh_fast(p2);
                    float hh = sigm(p3) * tanh_fast(cc);
                    cst[r1 * 1024 + j] = cc;
                    hnext[r1 * 1024 + j] = __float2half(hh);
                    lout[(size_t)tok1 * 1024 + j] = hh;
                }
            }
        }
    }
}

// ---------------- weight transpose to fp16: WT[n][k]; PERM: n -> 4*(n%1024)+(n/1024) ----
template<int PERM>
__global__ __launch_bounds__(256)
void transpose_kernel(const float* __restrict__ W, __half* __restrict__ WT, int K, int N) {
    __shared__ float t[32][33];
    const int n0 = blockIdx.x * 32, k0 = blockIdx.y * 32;
    const int tx = threadIdx.x & 31, ty = threadIdx.x >> 5;
#pragma unroll
    for (int j = 0; j < 4; j++)
        t[ty + j * 8][tx] = W[(size_t)(k0 + ty + j * 8) * N + n0 + tx];
    __syncthreads();
#pragma unroll
    for (int j = 0; j < 4; j++) {
        int n = n0 + ty + j * 8;
        int nd = PERM ? (4 * (n & 1023) + (n >> 10)) : n;
        WT[(size_t)nd * K + k0 + tx] = __float2half(t[tx][ty + j * 8]);
    }
}

// ---------------- LayerNorm + adaLN modulate (fp16 out) ----------------
__global__ __launch_bounds__(256)
void ln_mod_kernel(const float* __restrict__ x, const float* __restrict__ mod,
                   int mstride, int shift_off, int scale_off, __half* __restrict__ out) {
    __shared__ float red[16];
    const int tok = blockIdx.x;
    const int tid = threadIdx.x;
    const float* xr = x + (size_t)tok * DD;
    float v[4];
    float s = 0.f, s2 = 0.f;
#pragma unroll
    for (int k = 0; k < 4; k++) {
        float f = xr[tid + k * 256];
        v[k] = f; s += f; s2 += f * f;
    }
#pragma unroll
    for (int o = 16; o; o >>= 1) {
        s += __shfl_xor_sync(0xffffffffu, s, o);
        s2 += __shfl_xor_sync(0xffffffffu, s2, o);
    }
    if ((tid & 31) == 0) { red[tid >> 5] = s; red[8 + (tid >> 5)] = s2; }
    __syncthreads();
    if (tid == 0) {
        float a = 0.f, b = 0.f;
        for (int i = 0; i < 8; i++) { a += red[i]; b += red[8 + i]; }
        red[0] = a; red[8] = b;
    }
    __syncthreads();
    const float mean = red[0] * (1.f / DD);
    const float var = red[8] * (1.f / DD) - mean * mean;
    const float inv = rsqrtf(var + 1e-6f);
    const int bt = tok >> 8;
    const float* m = mod + (size_t)bt * mstride;
    __half* orow = out + (size_t)tok * DD;
#pragma unroll
    for (int k = 0; k < 4; k++) {
        int d = tid + k * 256;
        float ln = (v[k] - mean) * inv;
        orow[d] = __float2half(ln * (1.f + m[scale_off + d]) + m[shift_off + d]);
    }
}

// ---------------- fused gated residual add + LayerNorm + modulate ----------------
__global__ __launch_bounds__(256)
void ga_ln_kernel(const float* __restrict__ xin, const float* __restrict__ delta,
                  const float* __restrict__ modg, int gstride, int gate_off,
                  const float* __restrict__ modl, int lstride, int shift_off, int scale_off,
                  float* __restrict__ xout, __half* __restrict__ lnout) {
    __shared__ float red[16];
    const int tok = blockIdx.x;
    const int tid = threadIdx.x;
    const int bt = tok >> 8;
    const float* xr = xin + (size_t)tok * DD;
    const float* dr = delta + (size_t)tok * DD;
    const float* mg = modg + (size_t)bt * gstride + gate_off;
    float v[4];
    float s = 0.f, s2 = 0.f;
    float* xo = xout + (size_t)tok * DD;
#pragma unroll
    for (int k = 0; k < 4; k++) {
        int d = tid + k * 256;
        float f = xr[d] + mg[d] * dr[d];
        xo[d] = f;
        v[k] = f; s += f; s2 += f * f;
    }
#pragma unroll
    for (int o = 16; o; o >>= 1) {
        s += __shfl_xor_sync(0xffffffffu, s, o);
        s2 += __shfl_xor_sync(0xffffffffu, s2, o);
    }
    if ((tid & 31) == 0) { red[tid >> 5] = s; red[8 + (tid >> 5)] = s2; }
    __syncthreads();
    if (tid == 0) {
        float a = 0.f, b = 0.f;
        for (int i = 0; i < 8; i++) { a += red[i]; b += red[8 + i]; }
        red[0] = a; red[8] = b;
    }
    __syncthreads();
    const float mean = red[0] * (1.f / DD);
    const float var = red[8] * (1.f / DD) - mean * mean;
    const float inv = rsqrtf(var + 1e-6f);
    const float* ml = modl + (size_t)bt * lstride;
    __half* lo = lnout + (size_t)tok * DD;
#pragma unroll
    for (int k = 0; k < 4; k++) {
        int d = tid + k * 256;
        float ln = (v[k] - mean) * inv;
        lo[d] = __float2half(ln * (1.f + ml[scale_off + d]) + ml[shift_off + d]);
    }
}

// ---------------- gated residual add (final) ----------------
__global__ __launch_bounds__(256)
void gated_add_kernel(const float* __restrict__ xin, const float* __restrict__ delta,
                      const float* __restrict__ mod, int mstride, int gate_off,
                      float* __restrict__ xout) {
    int idx = blockIdx.x * 256 + threadIdx.x;
    int tok = idx >> 10, d = idx & 1023;
    int bt = tok >> 8;
    xout[idx] = xin[idx] + mod[(size_t)bt * mstride + gate_off + d] * delta[idx];
}

// ---------------- small utilities ----------------
__global__ void silu_kernel(const float* __restrict__ c, __half* __restrict__ out, int n) {
    int i = blockIdx.x * 256 + threadIdx.x;
    if (i < n) { float v = c[i]; out[i] = __float2half(v / (1.f + __expf(-v))); }
}
__global__ void lstm_bias_kernel(const float* __restrict__ a, const float* __restrict__ b,
                                 float* __restrict__ o, int n) {
    int i = blockIdx.x * 256 + threadIdx.x;
    if (i < n) {
        int j = i >> 2, g = i & 3;
        o[i] = a[g * 1024 + j] + b[g * 1024 + j];
    }
}
__global__ void zero_state_kernel(__half* __restrict__ h0, __half* __restrict__ h1,
                                  float* __restrict__ c, int n) {
    int i = blockIdx.x * 256 + threadIdx.x;
    if (i < n) { h0[i] = __float2half(0.f); h1[i] = __float2half(0.f); c[i] = 0.f; }
}

// ======= spatial attention via mma.sync fp16 flash (L=256, dh=64, non-causal) =======
__global__ __launch_bounds__(256, 2)
void spatial_attn_tc(const __half* __restrict__ qkv, __half* __restrict__ out) {
    __shared__ __half sQ[128 * 72];
    __shared__ __half sK[64 * 72];
    __shared__ __half sVT[64 * 72];
    const int bid = blockIdx.x;
    const int qhalf = bid & 1;
    const int head = (bid >> 1) & 15;
    const int n = bid >> 5;
    const int tid = threadIdx.x;
    const int lane = tid & 31;
    const int wid = tid >> 5;
    const int g4 = lane >> 2, t4 = lane & 3;
    const size_t rowbase = (size_t)n * 256;

#pragma unroll
    for (int i = 0; i < 4; i++) {
        int idx = tid + i * 256;
        int row = idx >> 3, seg = idx & 7;
        *(uint4*)&sQ[row * 72 + seg * 8] =
            *(const uint4*)(qkv + (rowbase + qhalf * 128 + row) * 3072 + head * 64 + seg * 8);
    }
    __syncthreads();

    uint32_t af[4][4];
    {
        const int r = wid * 16 + g4;
#pragma unroll
        for (int ks = 0; ks < 4; ks++) {
            af[ks][0] = *(const uint32_t*)&sQ[r * 72 + ks * 16 + t4 * 2];
            af[ks][1] = *(const uint32_t*)&sQ[(r + 8) * 72 + ks * 16 + t4 * 2];
            af[ks][2] = *(const uint32_t*)&sQ[r * 72 + ks * 16 + 8 + t4 * 2];
            af[ks][3] = *(const uint32_t*)&sQ[(r + 8) * 72 + ks * 16 + 8 + t4 * 2];
        }
    }

    float O[8][4];
#pragma unroll
    for (int i = 0; i < 8; i++)
#pragma unroll
        for (int q = 0; q < 4; q++) O[i][q] = 0.f;
    float m0 = -1e30f, m1 = -1e30f, l0 = 0.f, l1 = 0.f;

    for (int kt = 0; kt < 4; kt++) {
#pragma unroll
        for (int i = 0; i < 2; i++) {
            int idx = tid + i * 256;
            int row = idx >> 3, seg = idx & 7;
            const __half* src = qkv + (rowbase + kt * 64 + row) * 3072 + 1024 + head * 64 + seg * 8;
            *(uint4*)&sK[row * 72 + seg * 8] = *(const uint4*)src;
            __half vv[8];
            *(uint4*)vv = *(const uint4*)(src + 1024);
#pragma unroll
            for (int jj = 0; jj < 8; jj++) sVT[(seg * 8 + jj) * 72 + row] = vv[jj];
        }
        __syncthreads();

        float sc[8][4];
#pragma unroll
        for (int nt = 0; nt < 8; nt++) {
#pragma unroll
            for (int q = 0; q < 4; q++) sc[nt][q] = 0.f;
#pragma unroll
            for (int ks = 0; ks < 4; ks++) {
                uint32_t b0 = *(const uint32_t*)&sK[(nt * 8 + g4) * 72 + ks * 16 + t4 * 2];
                uint32_t b1 = *(const uint32_t*)&sK[(nt * 8 + g4) * 72 + ks * 16 + 8 + t4 * 2];
                mma_f16(sc[nt], af[ks][0], af[ks][1], af[ks][2], af[ks][3], b0, b1);
            }
        }

        float mx0 = -1e30f, mx1 = -1e30f;
#pragma unroll
        for (int nt = 0; nt < 8; nt++) {
            sc[nt][0] *= 0.125f; sc[nt][1] *= 0.125f;
            sc[nt][2] *= 0.125f; sc[nt][3] *= 0.125f;
            mx0 = fmaxf(mx0, fmaxf(sc[nt][0], sc[nt][1]));
            mx1 = fmaxf(mx1, fmaxf(sc[nt][2], sc[nt][3]));
        }
        mx0 = fmaxf(mx0, __shfl_xor_sync(0xffffffffu, mx0, 1));
        mx0 = fmaxf(mx0, __shfl_xor_sync(0xffffffffu, mx0, 2));
        mx1 = fmaxf(mx1, __shfl_xor_sync(0xffffffffu, mx1, 1));
        mx1 = fmaxf(mx1, __shfl_xor_sync(0xffffffffu, mx1, 2));
        const float mn0 = fmaxf(m0, mx0), mn1 = fmaxf(m1, mx1);
        const float al0 = __expf(m0 - mn0), al1 = __expf(m1 - mn1);
        m0 = mn0; m1 = mn1;

        float sum0 = 0.f, sum1 = 0.f;
        uint32_t aP[8][2];
#pragma unroll
        for (int nt = 0; nt < 8; nt++) {
            float p0 = __expf(sc[nt][0] - mn0);
            float p1 = __expf(sc[nt][1] - mn0);
            float p2 = __expf(sc[nt][2] - mn1);
            float p3 = __expf(sc[nt][3] - mn1);
            sum0 += p0 + p1; sum1 += p2 + p3;
            aP[nt][0] = h2_as_u32(__floats2half2_rn(p0, p1));
            aP[nt][1] = h2_as_u32(__floats2half2_rn(p2, p3));
        }
        sum0 += __shfl_xor_sync(0xffffffffu, sum0, 1);
        sum0 += __shfl_xor_sync(0xffffffffu, sum0, 2);
        sum1 += __shfl_xor_sync(0xffffffffu, sum1, 1);
        sum1 += __shfl_xor_sync(0xffffffffu, sum1, 2);
        l0 = l0 * al0 + sum0;
        l1 = l1 * al1 + sum1;
#pragma unroll
        for (int nt2 = 0; nt2 < 8; nt2++) {
            O[nt2][0] *= al0; O[nt2][1] *= al0;
            O[nt2][2] *= al1; O[nt2][3] *= al1;
        }

#pragma unroll
        for (int ks2 = 0; ks2 < 4; ks2++) {
            const uint32_t a0 = aP[2 * ks2][0], a1 = aP[2 * ks2][1];
            const uint32_t a2 = aP[2 * ks2 + 1][0], a3 = aP[2 * ks2 + 1][1];
#pragma unroll
            for (int nt2 = 0; nt2 < 8; nt2++) {
                uint32_t b0 = *(const uint32_t*)&sVT[(nt2 * 8 + g4) * 72 + ks2 * 16 + t4 * 2];
                uint32_t b1 = *(const uint32_t*)&sVT[(nt2 * 8 + g4) * 72 + ks2 * 16 + 8 + t4 * 2];
                mma_f16(O[nt2], a0, a1, a2, a3, b0, b1);
            }
        }
        __syncthreads();
    }

    const float inv0 = 1.f / l0, inv1 = 1.f / l1;
    const int q0 = qhalf * 128 + wid * 16 + g4;
#pragma unroll
    for (int nt2 = 0; nt2 < 8; nt2++) {
        const int col = head * 64 + nt2 * 8 + t4 * 2;
        *(__half2*)(out + (rowbase + q0) * 1024 + col) =
            __floats2half2_rn(O[nt2][0] * inv0, O[nt2][1] * inv0);
        *(__half2*)(out + (rowbase + q0 + 8) * 1024 + col) =
            __floats2half2_rn(O[nt2][2] * inv1, O[nt2][3] * inv1);
    }
}

// ---------------- temporal attention (T=16, dh=64, causal; fp16 qkv in/out) ----------------
__global__ __launch_bounds__(128)
void temporal_attn_kernel(const __half* __restrict__ qkv, __half* __restrict__ out) {
    __shared__ float Q[16][65], K[16][65], V[16][65], S[16][17];
    const int bid = blockIdx.x;
    const int head = bid & 15;
    const int n = bid >> 4;
    const int b = n >> 8;
    const int hw = n & 255;
    const int tid = threadIdx.x;
    const size_t tokbase = (size_t)b * 4096 + hw;

    for (int i = tid; i < 16 * 64; i += 128) {
        int t = i >> 6, d = i & 63;
        size_t base = (tokbase + (size_t)t * 256) * 3072 + head * 64 + d;
        Q[t][d] = __half2float(qkv[base]);
        K[t][d] = __half2float(qkv[base + 1024]);
        V[t][d] = __half2float(qkv[base + 2048]);
    }
    __syncthreads();

    for (int idx = tid; idx < 256; idx += 128) {
        int qi = idx >> 4, kj = idx & 15;
        float s;
        if (kj <= qi) {
            float acc = 0.f;
#pragma unroll
            for (int d = 0; d < 64; d++) acc += Q[qi][d] * K[kj][d];
            s = acc * 0.125f;
        } else s = -1e30f;
        S[qi][kj] = s;
    }
    __syncthreads();

    {
        const int row = tid >> 3, c0 = tid & 7;
        float mx = fmaxf(S[row][c0], S[row][c0 + 8]);
#pragma unroll
        for (int o = 4; o; o >>= 1) mx = fmaxf(mx, __shfl_xor_sync(0xffffffffu, mx, o));
        float e0 = __expf(S[row][c0] - mx), e1 = __expf(S[row][c0 + 8] - mx);
        float sum = e0 + e1;
#pragma unroll
        for (int o = 4; o; o >>= 1) sum += __shfl_xor_sync(0xffffffffu, sum, o);
        float inv = 1.f / sum;
        S[row][c0] = e0 * inv;
        S[row][c0 + 8] = e1 * inv;
    }
    __syncthreads();

    for (int i = tid; i < 16 * 64; i += 128) {
        int qi = i >> 6, d = i & 63;
        float acc = 0.f;
#pragma unroll
        for (int k = 0; k < 16; k++) acc = fmaf(S[qi][k], V[k][d], acc);
        out[(tokbase + (size_t)qi * 256) * 1024 + head * 64 + d] = __float2half(acc);
    }
}

// ---------------- launch helpers ----------------
static void gemm(const __half* A, const __half* BT, const float* bias, void* C,
                 int M, int N, int K, int epi, int outh) {
    dim3 g(N / 128, (M + 127) / 128);
    if (epi == 1)      gemm_tc<1, 1><<<g, 128, GTC_SMEM_TOTAL>>>(A, BT, bias, C, M, N, K);
    else if (outh)     gemm_tc<0, 1><<<g, 128, GTC_SMEM_TOTAL>>>(A, BT, bias, C, M, N, K);
    else               gemm_tc<0, 0><<<g, 128, GTC_SMEM_TOTAL>>>(A, BT, bias, C, M, N, K);
}
static void wtrans(const float* W, __half* WT, int K, int N) {
    transpose_kernel<0><<<dim3(N / 32, K / 32), 256>>>(W, WT, K, N);
}
static void wtrans_perm(const float* W, __half* WT, int K, int N) {
    transpose_kernel<1><<<dim3(N / 32, K / 32), 256>>>(W, WT, K, N);
}

extern "C" void kernel_launch(void* const* d_in, const int* in_sizes, int n_in,
                              void* d_out, int out_size) {
    const float* x        = (const float*)d_in[0];
    const float* c        = (const float*)d_in[1];
    const float* s_ada_w  = (const float*)d_in[2];
    const float* s_ada_b  = (const float*)d_in[3];
    const float* t_ada_w  = (const float*)d_in[4];
    const float* t_ada_b  = (const float*)d_in[5];
    const float* r_ada_w  = (const float*)d_in[6];
    const float* r_ada_b  = (const float*)d_in[7];
    const float* s_qkv_w  = (const float*)d_in[8];
    const float* s_out_w  = (const float*)d_in[9];
    const float* s_out_b  = (const float*)d_in[10];
    const float* t_qkv_w  = (const float*)d_in[11];
    const float* t_out_w  = (const float*)d_in[12];
    const float* t_out_b  = (const float*)d_in[13];
    const float* s_mlp_w1 = (const float*)d_in[14];
    const float* s_mlp_b1 = (const float*)d_in[15];
    const float* s_mlp_w2 = (const float*)d_in[16];
    const float* s_mlp_b2 = (const float*)d_in[17];
    const float* t_mlp_w1 = (const float*)d_in[18];
    const float* t_mlp_b1 = (const float*)d_in[19];
    const float* t_mlp_w2 = (const float*)d_in[20];
    const float* t_mlp_b2 = (const float*)d_in[21];
    const float* lstm_w_ih = (const float*)d_in[22];
    const float* lstm_w_hh = (const float*)d_in[23];
    const float* lstm_b_ih = (const float*)d_in[24];
    const float* lstm_b_hh = (const float*)d_in[25];
    float* out = (float*)d_out;

    cudaFuncSetAttribute(gemm_tc<0, 0>, cudaFuncAttributeMaxDynamicSharedMemorySize, GTC_SMEM_TOTAL);
    cudaFuncSetAttribute(gemm_tc<0, 1>, cudaFuncAttributeMaxDynamicSharedMemorySize, GTC_SMEM_TOTAL);
    cudaFuncSetAttribute(gemm_tc<1, 1>, cudaFuncAttributeMaxDynamicSharedMemorySize, GTC_SMEM_TOTAL);

    __half *csh, *h1h, *qkvh, *mlph, *hstateh, *hstate2h, *wTh;
    float *smod, *tmod, *rmod, *xbuf, *delta, *gatesx, *cstate, *lstmout, *lstmbias;
    cudaGetSymbolAddress((void**)&csh, g_csh);
    cudaGetSymbolAddress((void**)&smod, g_smod);
    cudaGetSymbolAddress((void**)&tmod, g_tmod);
    cudaGetSymbolAddress((void**)&rmod, g_rmod);
    cudaGetSymbolAddress((void**)&xbuf, g_xbuf);
    cudaGetSymbolAddress((void**)&h1h, g_h1h);
    cudaGetSymbolAddress((void**)&qkvh, g_qkvh);
    cudaGetSymbolAddress((void**)&delta, g_delta);
    cudaGetSymbolAddress((void**)&mlph, g_mlph);
    cudaGetSymbolAddress((void**)&gatesx, g_gatesx);
    cudaGetSymbolAddress((void**)&hstateh, g_hstateh);
    cudaGetSymbolAddress((void**)&hstate2h, g_hstate2h);
    cudaGetSymbolAddress((void**)&cstate, g_cstate);
    cudaGetSymbolAddress((void**)&lstmout, g_lstmout);
    cudaGetSymbolAddress((void**)&lstmbias, g_lstmbias);
    cudaGetSymbolAddress((void**)&wTh, g_wTh);

    const size_t MEG = 1048576;
    __half* wt_sada  = wTh + 0 * MEG;
    __half* wt_tada  = wTh + 6 * MEG;
    __half* wt_rada  = wTh + 12 * MEG;
    __half* wt_sqkv  = wTh + 15 * MEG;
    __half* wt_sout  = wTh + 18 * MEG;
    __half* wt_tqkv  = wTh + 19 * MEG;
    __half* wt_tout  = wTh + 22 * MEG;
    __half* wt_smlp1 = wTh + 23 * MEG;
    __half* wt_smlp2 = wTh + 27 * MEG;
    __half* wt_tmlp1 = wTh + 31 * MEG;
    __half* wt_tmlp2 = wTh + 35 * MEG;
    __half* wt_lih   = wTh + 39 * MEG;  // gate-interleaved [4096,1024]
    __half* wt_lhh   = wTh + 43 * MEG;  // gate-interleaved [4096,1024]

    wtrans(s_ada_w, wt_sada, 1024, 6144);
    wtrans(t_ada_w, wt_tada, 1024, 6144);
    wtrans(r_ada_w, wt_rada, 1024, 3072);
    wtrans(s_qkv_w, wt_sqkv, 1024, 3072);
    wtrans(s_out_w, wt_sout, 1024, 1024);
    wtrans(t_qkv_w, wt_tqkv, 1024, 3072);
    wtrans(t_out_w, wt_tout, 1024, 1024);
    wtrans(s_mlp_w1, wt_smlp1, 1024, 4096);
    wtrans(s_mlp_w2, wt_smlp2, 4096, 1024);
    wtrans(t_mlp_w1, wt_tmlp1, 1024, 4096);
    wtrans(t_mlp_w2, wt_tmlp2, 4096, 1024);
    wtrans_perm(lstm_w_ih, wt_lih, 1024, 4096);
    wtrans_perm(lstm_w_hh, wt_lhh, 1024, 4096);

    const int NEL = NTOK * DD;
    const int EW_BLOCKS = NEL / 256;

    // conditioning
    silu_kernel<<<(NBT * DD + 255) / 256, 256>>>(c, csh, NBT * DD);
    gemm(csh, wt_sada, s_ada_b, smod, NBT, 6 * DD, DD, 0, 0);
    gemm(csh, wt_tada, t_ada_b, tmod, NBT, 6 * DD, DD, 0, 0);
    gemm(csh, wt_rada, r_ada_b, rmod, NBT, 3 * DD, DD, 0, 0);

    // ---- spatial attention ----
    ln_mod_kernel<<<NTOK, 256>>>(x, smod, 6 * DD, 0, DD, h1h);
    gemm(h1h, wt_sqkv, nullptr, qkvh, NTOK, 3 * DD, DD, 0, 1);
    spatial_attn_tc<<<1024, 256>>>(qkvh, h1h);
    gemm(h1h, wt_sout, s_out_b, delta, NTOK, DD, DD, 0, 0);
    ga_ln_kernel<<<NTOK, 256>>>(x, delta, smod, 6 * DD, 2 * DD,
                                smod, 6 * DD, 3 * DD, 4 * DD, xbuf, h1h);

    // ---- spatial MLP ----
    gemm(h1h, wt_smlp1, s_mlp_b1, mlph, NTOK, 4 * DD, DD, 1, 1);
    gemm(mlph, wt_smlp2, s_mlp_b2, delta, NTOK, DD, 4 * DD, 0, 0);
    ga_ln_kernel<<<NTOK, 256>>>(xbuf, delta, smod, 6 * DD, 5 * DD,
                                tmod, 6 * DD, 0, DD, xbuf, h1h);

    // ---- temporal attention (causal) ----
    gemm(h1h, wt_tqkv, nullptr, qkvh, NTOK, 3 * DD, DD, 0, 1);
    temporal_attn_kernel<<<8192, 128>>>(qkvh, h1h);
    gemm(h1h, wt_tout, t_out_b, delta, NTOK, DD, DD, 0, 0);
    ga_ln_kernel<<<NTOK, 256>>>(xbuf, delta, tmod, 6 * DD, 2 * DD,
                                tmod, 6 * DD, 3 * DD, 4 * DD, xbuf, h1h);

    // ---- temporal MLP ----
    gemm(h1h, wt_tmlp1, t_mlp_b1, mlph, NTOK, 4 * DD, DD, 1, 1);
    gemm(mlph, wt_tmlp2, t_mlp_b2, delta, NTOK, DD, 4 * DD, 0, 0);
    ga_ln_kernel<<<NTOK, 256>>>(xbuf, delta, tmod, 6 * DD, 5 * DD,
                                rmod, 3 * DD, 0, DD, xbuf, h1h);

    // ---- LSTM branch (gate-interleaved, fused cell) ----
    lstm_bias_kernel<<<(4 * DD + 255) / 256, 256>>>(lstm_b_ih, lstm_b_hh, lstmbias, 4 * DD);
    gemm(h1h, wt_lih, lstmbias, gatesx, NTOK, 4 * DD, DD, 0, 0);
    zero_state_kernel<<<(NSEQ * DD + 255) / 256, 256>>>(hstateh, hstate2h, cstate, NSEQ * DD);
    {
        __half* hb[2] = {hstateh, hstate2h};
        for (int t = 0; t < TT; t++) {
            lstm_step_tc<<<dim3(32, 4), 256, LSTM_SMEM_TOTAL>>>(
                hb[t & 1], wt_lhh, gatesx, cstate, hb[(t + 1) & 1], lstmout, t);
        }
    }
    gated_add_kernel<<<EW_BLOCKS, 256>>>(xbuf, lstmout, rmod, 3 * DD, 2 * DD, out);
}

// round 9
// speedup vs baseline: 5.7940x; 1.0253x over previous
#include <cuda_runtime.h>
#include <cuda_fp16.h>
#include <math.h>
#include <cstdint>

// Problem constants
#define DD   1024
#define NTOK 8192      // B*T*H*W
#define NBT  32        // B*T
#define NSEQ 512       // B*H*W
#define TT   16

// ---------------- scratch (device globals; no allocations allowed) ----------------
__device__ __half g_csh[NBT * DD];
__device__ float  g_smod[NBT * 6 * DD];
__device__ float  g_tmod[NBT * 6 * DD];
__device__ float  g_rmod[NBT * 3 * DD];
__device__ float  g_xbuf[NTOK * DD];
__device__ __half g_h1h[NTOK * DD];
__device__ __half g_qkvh[NTOK * 3 * DD];
__device__ __half g_deltah[NTOK * DD];
__device__ __half g_mlph[NTOK * 4 * DD];
__device__ __half g_gatesxh[NTOK * 4 * DD];
__device__ __half g_hstateh[NSEQ * DD];
__device__ __half g_hstate2h[NSEQ * DD];
__device__ float  g_cstate[NSEQ * DD];
__device__ float  g_lstmbias[4 * DD];
__device__ __half g_wTh[47u * 1048576u];   // transposed fp16 weights

__device__ __forceinline__ float tanh_fast(float x) {
    float r; asm("tanh.approx.f32 %0, %1;" : "=f"(r) : "f"(x)); return r;
}
__device__ __forceinline__ float gelu_tanh(float x) {
    return 0.5f * x * (1.f + tanh_fast(0.7978845608028654f * (x + 0.044715f * x * x * x)));
}
__device__ __forceinline__ float sigm(float x) { return 0.5f * (1.f + tanh_fast(0.5f * x)); }
__device__ __forceinline__ uint32_t h2_as_u32(__half2 h) {
    uint32_t u; *reinterpret_cast<__half2*>(&u) = h; return u;
}
__device__ __forceinline__ void mma_f16(float d[4], uint32_t a0, uint32_t a1, uint32_t a2,
                                        uint32_t a3, uint32_t b0, uint32_t b1) {
    asm volatile(
        "mma.sync.aligned.m16n8k16.row.col.f32.f16.f16.f32 "
        "{%0,%1,%2,%3}, {%4,%5,%6,%7}, {%8,%9}, {%0,%1,%2,%3};\n"
        : "+f"(d[0]), "+f"(d[1]), "+f"(d[2]), "+f"(d[3])
        : "r"(a0), "r"(a1), "r"(a2), "r"(a3), "r"(b0), "r"(b1));
}
__device__ __forceinline__ void cp_async16(uint32_t dst, const void* src, int szvalid) {
    asm volatile("cp.async.cg.shared.global [%0], [%1], 16, %2;"
                 :: "r"(dst), "l"(src), "r"(szvalid));
}
__device__ __forceinline__ void cp_commit() { asm volatile("cp.async.commit_group;"); }

// ================== fp16 tensor-core GEMM: C[M,N] = A[M,K] @ BT[N,K]^T ==================
// 128 threads = 4 warps (2x2), warp tile 64x64, block tile 128x128x32, 4-stage cp.async.
#define GPITCH_B   80
#define GOP_BYTES  (128 * GPITCH_B)
#define GSTAGE_B   (2 * GOP_BYTES)       // 20480 per stage
#define GTC_NSTAGE 4
#define GTC_SMEM_TOTAL (GTC_NSTAGE * GSTAGE_B)   // 81920 bytes
#define LSTM_SMEM_TOTAL (2 * GSTAGE_B)           // 40960 bytes (2-stage)

template<int EPI, int OUTH>
__global__ __launch_bounds__(128, 2)
void gemm_tc(const __half* __restrict__ A, const __half* __restrict__ BT,
             const float* __restrict__ bias, void* __restrict__ Cout,
             int M, int N, int K) {
    extern __shared__ char smem[];
    const uint32_t sb = (uint32_t)__cvta_generic_to_shared(smem);
    const int tid = threadIdx.x;
    const int lane = tid & 31;
    const int wid = tid >> 5;
    const int wr = wid >> 1;
    const int wc = wid & 1;
    const int g4 = lane >> 2, t4 = lane & 3;
    const int bx = blockIdx.x, by = blockIdx.y;
    const int gra = by * 128;
    const int gnb = bx * 128;

    float acc[4][8][4];
#pragma unroll
    for (int mt = 0; mt < 4; mt++)
#pragma unroll
        for (int nt = 0; nt < 8; nt++)
#pragma unroll
            for (int q = 0; q < 4; q++) acc[mt][nt][q] = 0.f;

    const int nk = K >> 5;

    auto load_stage = [&](int kc, int s) {
        const uint32_t sbase = sb + s * GSTAGE_B;
#pragma unroll
        for (int i = 0; i < 4; i++) {
            const int c = tid + i * 128;
            const int row = c >> 2, seg = c & 3;
            const int ga = gra + row;
            const bool ok = ga < M;
            cp_async16(sbase + row * GPITCH_B + seg * 16,
                       A + (size_t)(ok ? ga : 0) * K + kc * 32 + seg * 8, ok ? 16 : 0);
            cp_async16(sbase + GOP_BYTES + row * GPITCH_B + seg * 16,
                       BT + (size_t)(gnb + row) * K + kc * 32 + seg * 8, 16);
        }
    };

    load_stage(0, 0); cp_commit();
    load_stage(1, 1); cp_commit();
    load_stage(2, 2); cp_commit();

    for (int kc = 0; kc < nk; kc++) {
        if (kc < nk - 2)       asm volatile("cp.async.wait_group 2;");
        else if (kc == nk - 2) asm volatile("cp.async.wait_group 1;");
        else                   asm volatile("cp.async.wait_group 0;");
        __syncthreads();
        if (kc + 3 < nk) { load_stage(kc + 3, (kc + 3) & (GTC_NSTAGE - 1)); cp_commit(); }

        const char* sA = smem + (kc & (GTC_NSTAGE - 1)) * GSTAGE_B;
        const char* sB = sA + GOP_BYTES;
#pragma unroll
        for (int ks = 0; ks < 2; ks++) {
            const int kb = ks * 32 + t4 * 4;
            uint32_t af[4][4];
            uint32_t bf[8][2];
#pragma unroll
            for (int mt = 0; mt < 4; mt++) {
                const int r = wr * 64 + mt * 16 + g4;
                af[mt][0] = *(const uint32_t*)(sA + r * GPITCH_B + kb);
                af[mt][1] = *(const uint32_t*)(sA + (r + 8) * GPITCH_B + kb);
                af[mt][2] = *(const uint32_t*)(sA + r * GPITCH_B + kb + 16);
                af[mt][3] = *(const uint32_t*)(sA + (r + 8) * GPITCH_B + kb + 16);
            }
#pragma unroll
            for (int nt = 0; nt < 8; nt++) {
                const int n = wc * 64 + nt * 8 + g4;
                bf[nt][0] = *(const uint32_t*)(sB + n * GPITCH_B + kb);
                bf[nt][1] = *(const uint32_t*)(sB + n * GPITCH_B + kb + 16);
            }
#pragma unroll
            for (int mt = 0; mt < 4; mt++)
#pragma unroll
                for (int nt = 0; nt < 8; nt++)
                    mma_f16(acc[mt][nt], af[mt][0], af[mt][1], af[mt][2], af[mt][3],
                            bf[nt][0], bf[nt][1]);
        }
    }

#pragma unroll
    for (int mt = 0; mt < 4; mt++) {
        const int r0 = by * 128 + wr * 64 + mt * 16 + g4;
#pragma unroll
        for (int nt = 0; nt < 8; nt++) {
            const int col = bx * 128 + wc * 64 + nt * 8 + t4 * 2;
            float b0 = 0.f, b1 = 0.f;
            if (bias) { b0 = __ldg(bias + col); b1 = __ldg(bias + col + 1); }
            float v0 = acc[mt][nt][0] + b0;
            float v1 = acc[mt][nt][1] + b1;
            float v2 = acc[mt][nt][2] + b0;
            float v3 = acc[mt][nt][3] + b1;
            if (EPI == 1) {
                v0 = gelu_tanh(v0); v1 = gelu_tanh(v1);
                v2 = gelu_tanh(v2); v3 = gelu_tanh(v3);
            }
            if (OUTH) {
                __half* Ch = (__half*)Cout;
                if (r0 < M) *(__half2*)(Ch + (size_t)r0 * N + col) = __floats2half2_rn(v0, v1);
                if (r0 + 8 < M) *(__half2*)(Ch + (size_t)(r0 + 8) * N + col) = __floats2half2_rn(v2, v3);
            } else {
                float* Cf = (float*)Cout;
                if (r0 < M) *(float2*)(Cf + (size_t)r0 * N + col) = make_float2(v0, v1);
                if (r0 + 8 < M) *(float2*)(Cf + (size_t)(r0 + 8) * N + col) = make_float2(v2, v3);
            }
        }
    }
}

// ============ fused LSTM step: gates = h@w_hhT + gatesx; cell; out = xbuf + r_gate*h ============
// 8-warp layout, 2-stage. A = h fp16 [512,1024]; BT = wt_lhh_perm [4096,1024]; col n = 4j+g.
__global__ __launch_bounds__(256, 2)
void lstm_step_tc(const __half* __restrict__ A, const __half* __restrict__ BT,
                  const __half* __restrict__ gx, float* __restrict__ cst,
                  __half* __restrict__ hnext, const float* __restrict__ xbuf,
                  const float* __restrict__ rmod, float* __restrict__ outp, int t) {
    extern __shared__ char smem[];
    const uint32_t sb = (uint32_t)__cvta_generic_to_shared(smem);
    const int tid = threadIdx.x;
    const int lane = tid & 31;
    const int wid = tid >> 5;
    const int wr = wid >> 2;
    const int wc = wid & 3;
    const int bx = blockIdx.x, by = blockIdx.y;
    const int gra = by * 128;
    const int gnb = bx * 128;
    const int K = 1024, nk = 32;

    float acc[4][4][4];
#pragma unroll
    for (int mt = 0; mt < 4; mt++)
#pragma unroll
        for (int nt = 0; nt < 4; nt++)
#pragma unroll
            for (int q = 0; q < 4; q++) acc[mt][nt][q] = 0.f;

    auto load_stage = [&](int kc, int p) {
        const uint32_t sbase = sb + p * GSTAGE_B;
#pragma unroll
        for (int i = 0; i < 2; i++) {
            const int c = tid + i * 256;
            const int row = c >> 2, seg = c & 3;
            cp_async16(sbase + row * GPITCH_B + seg * 16,
                       A + (size_t)(gra + row) * K + kc * 32 + seg * 8, 16);
            cp_async16(sbase + GOP_BYTES + row * GPITCH_B + seg * 16,
                       BT + (size_t)(gnb + row) * K + kc * 32 + seg * 8, 16);
        }
    };

    load_stage(0, 0);
    cp_commit();

    for (int kc = 0; kc < nk; kc++) {
        const int p = kc & 1;
        if (kc + 1 < nk) {
            load_stage(kc + 1, p ^ 1);
            cp_commit();
            asm volatile("cp.async.wait_group 1;");
        } else {
            asm volatile("cp.async.wait_group 0;");
        }
        __syncthreads();
        const char* sA = smem + p * GSTAGE_B;
        const char* sB = sA + GOP_BYTES;
#pragma unroll
        for (int ks = 0; ks < 2; ks++) {
            const int kb = ks * 32 + (lane & 3) * 4;
            uint32_t af[4][4];
            uint32_t bf[4][2];
#pragma unroll
            for (int mt = 0; mt < 4; mt++) {
                const int r = wr * 64 + mt * 16 + (lane >> 2);
                af[mt][0] = *(const uint32_t*)(sA + r * GPITCH_B + kb);
                af[mt][1] = *(const uint32_t*)(sA + (r + 8) * GPITCH_B + kb);
                af[mt][2] = *(const uint32_t*)(sA + r * GPITCH_B + kb + 16);
                af[mt][3] = *(const uint32_t*)(sA + (r + 8) * GPITCH_B + kb + 16);
            }
#pragma unroll
            for (int nt = 0; nt < 4; nt++) {
                const int n = wc * 32 + nt * 8 + (lane >> 2);
                bf[nt][0] = *(const uint32_t*)(sB + n * GPITCH_B + kb);
                bf[nt][1] = *(const uint32_t*)(sB + n * GPITCH_B + kb + 16);
            }
#pragma unroll
            for (int mt = 0; mt < 4; mt++)
#pragma unroll
                for (int nt = 0; nt < 4; nt++)
                    mma_f16(acc[mt][nt], af[mt][0], af[mt][1], af[mt][2], af[mt][3],
                            bf[nt][0], bf[nt][1]);
        }
        __syncthreads();
    }

    // fused cell epilogue (gate-interleaved columns: col = 4j+g), fused gated residual out
#pragma unroll
    for (int mt = 0; mt < 4; mt++) {
        const int r0 = by * 128 + wr * 64 + mt * 16 + (lane >> 2);
        const int r1 = r0 + 8;
        const int tok0 = ((r0 >> 8) << 12) + (t << 8) + (r0 & 255);
        const int tok1 = ((r1 >> 8) << 12) + (t << 8) + (r1 & 255);
        const int bt0 = tok0 >> 8, bt1 = tok1 >> 8;
#pragma unroll
        for (int nt = 0; nt < 4; nt++) {
            const int col = bx * 128 + wc * 32 + nt * 8 + (lane & 3) * 2;
            __half2 gx0 = *(const __half2*)(gx + (size_t)tok0 * 4096 + col);
            __half2 gx1 = *(const __half2*)(gx + (size_t)tok1 * 4096 + col);
            float v0 = acc[mt][nt][0] + __half2float(__low2half(gx0));
            float v1 = acc[mt][nt][1] + __half2float(__high2half(gx0));
            float v2 = acc[mt][nt][2] + __half2float(__low2half(gx1));
            float v3 = acc[mt][nt][3] + __half2float(__high2half(gx1));
            float p0 = __shfl_xor_sync(0xffffffffu, v0, 1);
            float p1 = __shfl_xor_sync(0xffffffffu, v1, 1);
            float p2 = __shfl_xor_sync(0xffffffffu, v2, 1);
            float p3 = __shfl_xor_sync(0xffffffffu, v3, 1);
            if (!(lane & 1)) {
                const int j = col >> 2;
                {
                    float cc = sigm(v1) * cst[r0 * 1024 + j] + sigm(v0) * tanh_fast(p0);
                    float hh = sigm(p1) * tanh_fast(cc);
                    cst[r0 * 1024 + j] = cc;
                    hnext[r0 * 1024 + j] = __float2half(hh);
                    float rg = rmod[bt0 * 3072 + 2048 + j];
                    outp[(size_t)tok0 * 1024 + j] = xbuf[(size_t)tok0 * 1024 + j] + rg * hh;
                }
                {
                    float cc = sigm(v3) * cst[r1 * 1024 + j] + sigm(v2) * tanh_fast(p2);
                    float hh = sigm(p3) * tanh_fast(cc);
                    cst[r1 * 1024 + j] = cc;
                    hnext[r1 * 1024 + j] = __float2half(hh);
                    float rg = rmod[bt1 * 3072 + 2048 + j];
                    outp[(size_t)tok1 * 1024 + j] = xbuf[(size_t)tok1 * 1024 + j] + rg * hh;
                }
            }
        }
    }
}

// ---------------- batched weight transpose: all matrices in one launch ----------------
struct TransDesc { const float* W; __half* WT; int K; int N; int perm; int tileStart; };
struct TransArgs { TransDesc d[13]; };

__global__ __launch_bounds__(256)
void transpose_all_kernel(TransArgs a) {
    __shared__ float t[32][33];
    const int bid = blockIdx.x;
    int i = 0;
#pragma unroll
    for (int k = 0; k < 12; k++) if (bid >= a.d[k + 1].tileStart) i = k + 1;
    const TransDesc& td = a.d[i];
    const int local = bid - td.tileStart;
    const int ntx = td.N / 32;
    const int n0 = (local % ntx) * 32, k0 = (local / ntx) * 32;
    const int tx = threadIdx.x & 31, ty = threadIdx.x >> 5;
#pragma unroll
    for (int j = 0; j < 4; j++)
        t[ty + j * 8][tx] = td.W[(size_t)(k0 + ty + j * 8) * td.N + n0 + tx];
    __syncthreads();
#pragma unroll
    for (int j = 0; j < 4; j++) {
        int n = n0 + ty + j * 8;
        int nd = td.perm ? (4 * (n & 1023) + (n >> 10)) : n;
        td.WT[(size_t)nd * td.K + k0 + tx] = __float2half(t[tx][ty + j * 8]);
    }
}

// ---------------- LayerNorm + adaLN modulate (fp16 out) ----------------
__global__ __launch_bounds__(256)
void ln_mod_kernel(const float* __restrict__ x, const float* __restrict__ mod,
                   int mstride, int shift_off, int scale_off, __half* __restrict__ out) {
    __shared__ float red[16];
    const int tok = blockIdx.x;
    const int tid = threadIdx.x;
    const float* xr = x + (size_t)tok * DD;
    float v[4];
    float s = 0.f, s2 = 0.f;
#pragma unroll
    for (int k = 0; k < 4; k++) {
        float f = xr[tid + k * 256];
        v[k] = f; s += f; s2 += f * f;
    }
#pragma unroll
    for (int o = 16; o; o >>= 1) {
        s += __shfl_xor_sync(0xffffffffu, s, o);
        s2 += __shfl_xor_sync(0xffffffffu, s2, o);
    }
    if ((tid & 31) == 0) { red[tid >> 5] = s; red[8 + (tid >> 5)] = s2; }
    __syncthreads();
    if (tid == 0) {
        float a = 0.f, b = 0.f;
        for (int i = 0; i < 8; i++) { a += red[i]; b += red[8 + i]; }
        red[0] = a; red[8] = b;
    }
    __syncthreads();
    const float mean = red[0] * (1.f / DD);
    const float var = red[8] * (1.f / DD) - mean * mean;
    const float inv = rsqrtf(var + 1e-6f);
    const int bt = tok >> 8;
    const float* m = mod + (size_t)bt * mstride;
    __half* orow = out + (size_t)tok * DD;
#pragma unroll
    for (int k = 0; k < 4; k++) {
        int d = tid + k * 256;
        float ln = (v[k] - mean) * inv;
        orow[d] = __float2half(ln * (1.f + m[scale_off + d]) + m[shift_off + d]);
    }
}

// ---------------- fused gated residual add + LayerNorm + modulate (fp16 delta) ----------------
__global__ __launch_bounds__(256)
void ga_ln_kernel(const float* __restrict__ xin, const __half* __restrict__ delta,
                  const float* __restrict__ modg, int gstride, int gate_off,
                  const float* __restrict__ modl, int lstride, int shift_off, int scale_off,
                  float* __restrict__ xout, __half* __restrict__ lnout) {
    __shared__ float red[16];
    const int tok = blockIdx.x;
    const int tid = threadIdx.x;
    const int bt = tok >> 8;
    const float* xr = xin + (size_t)tok * DD;
    const __half* dr = delta + (size_t)tok * DD;
    const float* mg = modg + (size_t)bt * gstride + gate_off;
    float v[4];
    float s = 0.f, s2 = 0.f;
    float* xo = xout + (size_t)tok * DD;
#pragma unroll
    for (int k = 0; k < 4; k++) {
        int d = tid + k * 256;
        float f = xr[d] + mg[d] * __half2float(dr[d]);
        xo[d] = f;
        v[k] = f; s += f; s2 += f * f;
    }
#pragma unroll
    for (int o = 16; o; o >>= 1) {
        s += __shfl_xor_sync(0xffffffffu, s, o);
        s2 += __shfl_xor_sync(0xffffffffu, s2, o);
    }
    if ((tid & 31) == 0) { red[tid >> 5] = s; red[8 + (tid >> 5)] = s2; }
    __syncthreads();
    if (tid == 0) {
        float a = 0.f, b = 0.f;
        for (int i = 0; i < 8; i++) { a += red[i]; b += red[8 + i]; }
        red[0] = a; red[8] = b;
    }
    __syncthreads();
    const float mean = red[0] * (1.f / DD);
    const float var = red[8] * (1.f / DD) - mean * mean;
    const float inv = rsqrtf(var + 1e-6f);
    const float* ml = modl + (size_t)bt * lstride;
    __half* lo = lnout + (size_t)tok * DD;
#pragma unroll
    for (int k = 0; k < 4; k++) {
        int d = tid + k * 256;
        float ln = (v[k] - mean) * inv;
        lo[d] = __float2half(ln * (1.f + ml[scale_off + d]) + ml[shift_off + d]);
    }
}

// ---------------- small utilities ----------------
__global__ void silu_kernel(const float* __restrict__ c, __half* __restrict__ out, int n) {
    int i = blockIdx.x * 256 + threadIdx.x;
    if (i < n) { float v = c[i]; out[i] = __float2half(v / (1.f + __expf(-v))); }
}
__global__ void lstm_bias_kernel(const float* __restrict__ a, const float* __restrict__ b,
                                 float* __restrict__ o, int n) {
    int i = blockIdx.x * 256 + threadIdx.x;
    if (i < n) {
        int j = i >> 2, g = i & 3;
        o[i] = a[g * 1024 + j] + b[g * 1024 + j];
    }
}
__global__ void zero_state_kernel(__half* __restrict__ h0, __half* __restrict__ h1,
                                  float* __restrict__ c, int n) {
    int i = blockIdx.x * 256 + threadIdx.x;
    if (i < n) { h0[i] = __float2half(0.f); h1[i] = __float2half(0.f); c[i] = 0.f; }
}

// ======= spatial attention via mma.sync fp16 flash (L=256, dh=64, non-causal) =======
__global__ __launch_bounds__(256, 2)
void spatial_attn_tc(const __half* __restrict__ qkv, __half* __restrict__ out) {
    __shared__ __half sQ[128 * 72];
    __shared__ __half sK[64 * 72];
    __shared__ __half sVT[64 * 72];
    const int bid = blockIdx.x;
    const int qhalf = bid & 1;
    const int head = (bid >> 1) & 15;
    const int n = bid >> 5;
    const int tid = threadIdx.x;
    const int lane = tid & 31;
    const int wid = tid >> 5;
    const int g4 = lane >> 2, t4 = lane & 3;
    const size_t rowbase = (size_t)n * 256;

#pragma unroll
    for (int i = 0; i < 4; i++) {
        int idx = tid + i * 256;
        int row = idx >> 3, seg = idx & 7;
        *(uint4*)&sQ[row * 72 + seg * 8] =
            *(const uint4*)(qkv + (rowbase + qhalf * 128 + row) * 3072 + head * 64 + seg * 8);
    }
    __syncthreads();

    uint32_t af[4][4];
    {
        const int r = wid * 16 + g4;
#pragma unroll
        for (int ks = 0; ks < 4; ks++) {
            af[ks][0] = *(const uint32_t*)&sQ[r * 72 + ks * 16 + t4 * 2];
            af[ks][1] = *(const uint32_t*)&sQ[(r + 8) * 72 + ks * 16 + t4 * 2];
            af[ks][2] = *(const uint32_t*)&sQ[r * 72 + ks * 16 + 8 + t4 * 2];
            af[ks][3] = *(const uint32_t*)&sQ[(r + 8) * 72 + ks * 16 + 8 + t4 * 2];
        }
    }

    float O[8][4];
#pragma unroll
    for (int i = 0; i < 8; i++)
#pragma unroll
        for (int q = 0; q < 4; q++) O[i][q] = 0.f;
    float m0 = -1e30f, m1 = -1e30f, l0 = 0.f, l1 = 0.f;

    for (int kt = 0; kt < 4; kt++) {
#pragma unroll
        for (int i = 0; i < 2; i++) {
            int idx = tid + i * 256;
            int row = idx >> 3, seg = idx & 7;
            const __half* src = qkv + (rowbase + kt * 64 + row) * 3072 + 1024 + head * 64 + seg * 8;
            *(uint4*)&sK[row * 72 + seg * 8] = *(const uint4*)src;
            __half vv[8];
            *(uint4*)vv = *(const uint4*)(src + 1024);
#pragma unroll
            for (int jj = 0; jj < 8; jj++) sVT[(seg * 8 + jj) * 72 + row] = vv[jj];
        }
        __syncthreads();

        float sc[8][4];
#pragma unroll
        for (int nt = 0; nt < 8; nt++) {
#pragma unroll
            for (int q = 0; q < 4; q++) sc[nt][q] = 0.f;
#pragma unroll
            for (int ks = 0; ks < 4; ks++) {
                uint32_t b0 = *(const uint32_t*)&sK[(nt * 8 + g4) * 72 + ks * 16 + t4 * 2];
                uint32_t b1 = *(const uint32_t*)&sK[(nt * 8 + g4) * 72 + ks * 16 + 8 + t4 * 2];
                mma_f16(sc[nt], af[ks][0], af[ks][1], af[ks][2], af[ks][3], b0, b1);
            }
        }

        float mx0 = -1e30f, mx1 = -1e30f;
#pragma unroll
        for (int nt = 0; nt < 8; nt++) {
            sc[nt][0] *= 0.125f; sc[nt][1] *= 0.125f;
            sc[nt][2] *= 0.125f; sc[nt][3] *= 0.125f;
            mx0 = fmaxf(mx0, fmaxf(sc[nt][0], sc[nt][1]));
            mx1 = fmaxf(mx1, fmaxf(sc[nt][2], sc[nt][3]));
        }
        mx0 = fmaxf(mx0, __shfl_xor_sync(0xffffffffu, mx0, 1));
        mx0 = fmaxf(mx0, __shfl_xor_sync(0xffffffffu, mx0, 2));
        mx1 = fmaxf(mx1, __shfl_xor_sync(0xffffffffu, mx1, 1));
        mx1 = fmaxf(mx1, __shfl_xor_sync(0xffffffffu, mx1, 2));
        const float mn0 = fmaxf(m0, mx0), mn1 = fmaxf(m1, mx1);
        const float al0 = __expf(m0 - mn0), al1 = __expf(m1 - mn1);
        m0 = mn0; m1 = mn1;

        float sum0 = 0.f, sum1 = 0.f;
        uint32_t aP[8][2];
#pragma unroll
        for (int nt = 0; nt < 8; nt++) {
            float p0 = __expf(sc[nt][0] - mn0);
            float p1 = __expf(sc[nt][1] - mn0);
            float p2 = __expf(sc[nt][2] - mn1);
            float p3 = __expf(sc[nt][3] - mn1);
            sum0 += p0 + p1; sum1 += p2 + p3;
            aP[nt][0] = h2_as_u32(__floats2half2_rn(p0, p1));
            aP[nt][1] = h2_as_u32(__floats2half2_rn(p2, p3));
        }
        sum0 += __shfl_xor_sync(0xffffffffu, sum0, 1);
        sum0 += __shfl_xor_sync(0xffffffffu, sum0, 2);
        sum1 += __shfl_xor_sync(0xffffffffu, sum1, 1);
        sum1 += __shfl_xor_sync(0xffffffffu, sum1, 2);
        l0 = l0 * al0 + sum0;
        l1 = l1 * al1 + sum1;
#pragma unroll
        for (int nt2 = 0; nt2 < 8; nt2++) {
            O[nt2][0] *= al0; O[nt2][1] *= al0;
            O[nt2][2] *= al1; O[nt2][3] *= al1;
        }

#pragma unroll
        for (int ks2 = 0; ks2 < 4; ks2++) {
            const uint32_t a0 = aP[2 * ks2][0], a1 = aP[2 * ks2][1];
            const uint32_t a2 = aP[2 * ks2 + 1][0], a3 = aP[2 * ks2 + 1][1];
#pragma unroll
            for (int nt2 = 0; nt2 < 8; nt2++) {
                uint32_t b0 = *(const uint32_t*)&sVT[(nt2 * 8 + g4) * 72 + ks2 * 16 + t4 * 2];
                uint32_t b1 = *(const uint32_t*)&sVT[(nt2 * 8 + g4) * 72 + ks2 * 16 + 8 + t4 * 2];
                mma_f16(O[nt2], a0, a1, a2, a3, b0, b1);
            }
        }
        __syncthreads();
    }

    const float inv0 = 1.f / l0, inv1 = 1.f / l1;
    const int q0 = qhalf * 128 + wid * 16 + g4;
#pragma unroll
    for (int nt2 = 0; nt2 < 8; nt2++) {
        const int col = head * 64 + nt2 * 8 + t4 * 2;
        *(__half2*)(out + (rowbase + q0) * 1024 + col) =
            __floats2half2_rn(O[nt2][0] * inv0, O[nt2][1] * inv0);
        *(__half2*)(out + (rowbase + q0 + 8) * 1024 + col) =
            __floats2half2_rn(O[nt2][2] * inv1, O[nt2][3] * inv1);
    }
}

// ---------------- temporal attention (T=16, dh=64, causal; fp16 qkv in/out) ----------------
__global__ __launch_bounds__(128)
void temporal_attn_kernel(const __half* __restrict__ qkv, __half* __restrict__ out) {
    __shared__ float Q[16][65], K[16][65], V[16][65], S[16][17];
    const int bid = blockIdx.x;
    const int head = bid & 15;
    const int n = bid >> 4;
    const int b = n >> 8;
    const int hw = n & 255;
    const int tid = threadIdx.x;
    const size_t tokbase = (size_t)b * 4096 + hw;

    for (int i = tid; i < 16 * 64; i += 128) {
        int t = i >> 6, d = i & 63;
        size_t base = (tokbase + (size_t)t * 256) * 3072 + head * 64 + d;
        Q[t][d] = __half2float(qkv[base]);
        K[t][d] = __half2float(qkv[base + 1024]);
        V[t][d] = __half2float(qkv[base + 2048]);
    }
    __syncthreads();

    for (int idx = tid; idx < 256; idx += 128) {
        int qi = idx >> 4, kj = idx & 15;
        float s;
        if (kj <= qi) {
            float acc = 0.f;
#pragma unroll
            for (int d = 0; d < 64; d++) acc += Q[qi][d] * K[kj][d];
            s = acc * 0.125f;
        } else s = -1e30f;
        S[qi][kj] = s;
    }
    __syncthreads();

    {
        const int row = tid >> 3, c0 = tid & 7;
        float mx = fmaxf(S[row][c0], S[row][c0 + 8]);
#pragma unroll
        for (int o = 4; o; o >>= 1) mx = fmaxf(mx, __shfl_xor_sync(0xffffffffu, mx, o));
        float e0 = __expf(S[row][c0] - mx), e1 = __expf(S[row][c0 + 8] - mx);
        float sum = e0 + e1;
#pragma unroll
        for (int o = 4; o; o >>= 1) sum += __shfl_xor_sync(0xffffffffu, sum, o);
        float inv = 1.f / sum;
        S[row][c0] = e0 * inv;
        S[row][c0 + 8] = e1 * inv;
    }
    __syncthreads();

    for (int i = tid; i < 16 * 64; i += 128) {
        int qi = i >> 6, d = i & 63;
        float acc = 0.f;
#pragma unroll
        for (int k = 0; k < 16; k++) acc = fmaf(S[qi][k], V[k][d], acc);
        out[(tokbase + (size_t)qi * 256) * 1024 + head * 64 + d] = __float2half(acc);
    }
}

// ---------------- launch helpers ----------------
static void gemm(const __half* A, const __half* BT, const float* bias, void* C,
                 int M, int N, int K, int epi, int outh) {
    dim3 g(N / 128, (M + 127) / 128);
    if (epi == 1)      gemm_tc<1, 1><<<g, 128, GTC_SMEM_TOTAL>>>(A, BT, bias, C, M, N, K);
    else if (outh)     gemm_tc<0, 1><<<g, 128, GTC_SMEM_TOTAL>>>(A, BT, bias, C, M, N, K);
    else               gemm_tc<0, 0><<<g, 128, GTC_SMEM_TOTAL>>>(A, BT, bias, C, M, N, K);
}

extern "C" void kernel_launch(void* const* d_in, const int* in_sizes, int n_in,
                              void* d_out, int out_size) {
    const float* x        = (const float*)d_in[0];
    const float* c        = (const float*)d_in[1];
    const float* s_ada_w  = (const float*)d_in[2];
    const float* s_ada_b  = (const float*)d_in[3];
    const float* t_ada_w  = (const float*)d_in[4];
    const float* t_ada_b  = (const float*)d_in[5];
    const float* r_ada_w  = (const float*)d_in[6];
    const float* r_ada_b  = (const float*)d_in[7];
    const float* s_qkv_w  = (const float*)d_in[8];
    const float* s_out_w  = (const float*)d_in[9];
    const float* s_out_b  = (const float*)d_in[10];
    const float* t_qkv_w  = (const float*)d_in[11];
    const float* t_out_w  = (const float*)d_in[12];
    const float* t_out_b  = (const float*)d_in[13];
    const float* s_mlp_w1 = (const float*)d_in[14];
    const float* s_mlp_b1 = (const float*)d_in[15];
    const float* s_mlp_w2 = (const float*)d_in[16];
    const float* s_mlp_b2 = (const float*)d_in[17];
    const float* t_mlp_w1 = (const float*)d_in[18];
    const float* t_mlp_b1 = (const float*)d_in[19];
    const float* t_mlp_w2 = (const float*)d_in[20];
    const float* t_mlp_b2 = (const float*)d_in[21];
    const float* lstm_w_ih = (const float*)d_in[22];
    const float* lstm_w_hh = (const float*)d_in[23];
    const float* lstm_b_ih = (const float*)d_in[24];
    const float* lstm_b_hh = (const float*)d_in[25];
    float* out = (float*)d_out;

    cudaFuncSetAttribute(gemm_tc<0, 0>, cudaFuncAttributeMaxDynamicSharedMemorySize, GTC_SMEM_TOTAL);
    cudaFuncSetAttribute(gemm_tc<0, 1>, cudaFuncAttributeMaxDynamicSharedMemorySize, GTC_SMEM_TOTAL);
    cudaFuncSetAttribute(gemm_tc<1, 1>, cudaFuncAttributeMaxDynamicSharedMemorySize, GTC_SMEM_TOTAL);

    __half *csh, *h1h, *qkvh, *deltah, *mlph, *gatesxh, *hstateh, *hstate2h, *wTh;
    float *smod, *tmod, *rmod, *xbuf, *cstate, *lstmbias;
    cudaGetSymbolAddress((void**)&csh, g_csh);
    cudaGetSymbolAddress((void**)&smod, g_smod);
    cudaGetSymbolAddress((void**)&tmod, g_tmod);
    cudaGetSymbolAddress((void**)&rmod, g_rmod);
    cudaGetSymbolAddress((void**)&xbuf, g_xbuf);
    cudaGetSymbolAddress((void**)&h1h, g_h1h);
    cudaGetSymbolAddress((void**)&qkvh, g_qkvh);
    cudaGetSymbolAddress((void**)&deltah, g_deltah);
    cudaGetSymbolAddress((void**)&mlph, g_mlph);
    cudaGetSymbolAddress((void**)&gatesxh, g_gatesxh);
    cudaGetSymbolAddress((void**)&hstateh, g_hstateh);
    cudaGetSymbolAddress((void**)&hstate2h, g_hstate2h);
    cudaGetSymbolAddress((void**)&cstate, g_cstate);
    cudaGetSymbolAddress((void**)&lstmbias, g_lstmbias);
    cudaGetSymbolAddress((void**)&wTh, g_wTh);

    const size_t MEG = 1048576;
    __half* wt_sada  = wTh + 0 * MEG;
    __half* wt_tada  = wTh + 6 * MEG;
    __half* wt_rada  = wTh + 12 * MEG;
    __half* wt_sqkv  = wTh + 15 * MEG;
    __half* wt_sout  = wTh + 18 * MEG;
    __half* wt_tqkv  = wTh + 19 * MEG;
    __half* wt_tout  = wTh + 22 * MEG;
    __half* wt_smlp1 = wTh + 23 * MEG;
    __half* wt_smlp2 = wTh + 27 * MEG;
    __half* wt_tmlp1 = wTh + 31 * MEG;
    __half* wt_tmlp2 = wTh + 35 * MEG;
    __half* wt_lih   = wTh + 39 * MEG;  // gate-interleaved [4096,1024]
    __half* wt_lhh   = wTh + 43 * MEG;  // gate-interleaved [4096,1024]

    // batched transpose: all 13 matrices, one launch
    {
        TransArgs ta;
        auto set = [&](int i, const float* W, __half* WT, int K, int N, int perm, int start) {
            ta.d[i].W = W; ta.d[i].WT = WT; ta.d[i].K = K; ta.d[i].N = N;
            ta.d[i].perm = perm; ta.d[i].tileStart = start;
        };
        int s = 0;
        set(0,  s_ada_w,  wt_sada,  1024, 6144, 0, s); s += (6144 / 32) * (1024 / 32);
        set(1,  t_ada_w,  wt_tada,  1024, 6144, 0, s); s += (6144 / 32) * (1024 / 32);
        set(2,  r_ada_w,  wt_rada,  1024, 3072, 0, s); s += (3072 / 32) * (1024 / 32);
        set(3,  s_qkv_w,  wt_sqkv,  1024, 3072, 0, s); s += (3072 / 32) * (1024 / 32);
        set(4,  s_out_w,  wt_sout,  1024, 1024, 0, s); s += (1024 / 32) * (1024 / 32);
        set(5,  t_qkv_w,  wt_tqkv,  1024, 3072, 0, s); s += (3072 / 32) * (1024 / 32);
        set(6,  t_out_w,  wt_tout,  1024, 1024, 0, s); s += (1024 / 32) * (1024 / 32);
        set(7,  s_mlp_w1, wt_smlp1, 1024, 4096, 0, s); s += (4096 / 32) * (1024 / 32);
        set(8,  s_mlp_w2, wt_smlp2, 4096, 1024, 0, s); s += (1024 / 32) * (4096 / 32);
        set(9,  t_mlp_w1, wt_tmlp1, 1024, 4096, 0, s); s += (4096 / 32) * (1024 / 32);
        set(10, t_mlp_w2, wt_tmlp2, 4096, 1024, 0, s); s += (1024 / 32) * (4096 / 32);
        set(11, lstm_w_ih, wt_lih,  1024, 4096, 1, s); s += (4096 / 32) * (1024 / 32);
        set(12, lstm_w_hh, wt_lhh,  1024, 4096, 1, s); s += (4096 / 32) * (1024 / 32);
        transpose_all_kernel<<<s, 256>>>(ta);
    }

    // conditioning
    silu_kernel<<<(NBT * DD + 255) / 256, 256>>>(c, csh, NBT * DD);
    gemm(csh, wt_sada, s_ada_b, smod, NBT, 6 * DD, DD, 0, 0);
    gemm(csh, wt_tada, t_ada_b, tmod, NBT, 6 * DD, DD, 0, 0);
    gemm(csh, wt_rada, r_ada_b, rmod, NBT, 3 * DD, DD, 0, 0);

    // ---- spatial attention ----
    ln_mod_kernel<<<NTOK, 256>>>(x, smod, 6 * DD, 0, DD, h1h);
    gemm(h1h, wt_sqkv, nullptr, qkvh, NTOK, 3 * DD, DD, 0, 1);
    spatial_attn_tc<<<1024, 256>>>(qkvh, h1h);
    gemm(h1h, wt_sout, s_out_b, deltah, NTOK, DD, DD, 0, 1);
    ga_ln_kernel<<<NTOK, 256>>>(x, deltah, smod, 6 * DD, 2 * DD,
                                smod, 6 * DD, 3 * DD, 4 * DD, xbuf, h1h);

    // ---- spatial MLP ----
    gemm(h1h, wt_smlp1, s_mlp_b1, mlph, NTOK, 4 * DD, DD, 1, 1);
    gemm(mlph, wt_smlp2, s_mlp_b2, deltah, NTOK, DD, 4 * DD, 0, 1);
    ga_ln_kernel<<<NTOK, 256>>>(xbuf, deltah, smod, 6 * DD, 5 * DD,
                                tmod, 6 * DD, 0, DD, xbuf, h1h);

    // ---- temporal attention (causal) ----
    gemm(h1h, wt_tqkv, nullptr, qkvh, NTOK, 3 * DD, DD, 0, 1);
    temporal_attn_kernel<<<8192, 128>>>(qkvh, h1h);
    gemm(h1h, wt_tout, t_out_b, deltah, NTOK, DD, DD, 0, 1);
    ga_ln_kernel<<<NTOK, 256>>>(xbuf, deltah, tmod, 6 * DD, 2 * DD,
                                tmod, 6 * DD, 3 * DD, 4 * DD, xbuf, h1h);

    // ---- temporal MLP ----
    gemm(h1h, wt_tmlp1, t_mlp_b1, mlph, NTOK, 4 * DD, DD, 1, 1);
    gemm(mlph, wt_tmlp2, t_mlp_b2, deltah, NTOK, DD, 4 * DD, 0, 1);
    ga_ln_kernel<<<NTOK, 256>>>(xbuf, deltah, tmod, 6 * DD, 5 * DD,
                                rmod, 3 * DD, 0, DD, xbuf, h1h);

    // ---- LSTM branch (gate-interleaved, fused cell + fused gated residual out) ----
    lstm_bias_kernel<<<(4 * DD + 255) / 256, 256>>>(lstm_b_ih, lstm_b_hh, lstmbias, 4 * DD);
    gemm(h1h, wt_lih, lstmbias, gatesxh, NTOK, 4 * DD, DD, 0, 1);
    zero_state_kernel<<<(NSEQ * DD + 255) / 256, 256>>>(hstateh, hstate2h, cstate, NSEQ * DD);
    {
        __half* hb[2] = {hstateh, hstate2h};
        for (int t = 0; t < TT; t++) {
            lstm_step_tc<<<dim3(32, 4), 256, LSTM_SMEM_TOTAL>>>(
                hb[t & 1], wt_lhh, gatesxh, cstate, hb[(t + 1) & 1], xbuf, rmod, out, t);
        }
    }
}

// round 10
// speedup vs baseline: 5.9307x; 1.0236x over previous
#include <cuda_runtime.h>
#include <cuda_fp16.h>
#include <math.h>
#include <cstdint>

// Problem constants
#define DD   1024
#define NTOK 8192      // B*T*H*W
#define NBT  32        // B*T
#define NSEQ 512       // B*H*W
#define TT   16
#define MODW 15360     // 6*DD + 6*DD + 3*DD combined ada width

// ---------------- scratch (device globals; no allocations allowed) ----------------
__device__ __half g_csh[NBT * DD];
__device__ float  g_modall[NBT * MODW];
__device__ float  g_adab[MODW];
__device__ float  g_xbuf[NTOK * DD];
__device__ __half g_h1h[NTOK * DD];
__device__ __half g_qkvh[NTOK * 3 * DD];
__device__ __half g_deltah[NTOK * DD];
__device__ __half g_mlph[NTOK * 4 * DD];
__device__ __half g_gatesxh[NTOK * 4 * DD];
__device__ __half g_hstateh[NSEQ * DD];
__device__ __half g_hstate2h[NSEQ * DD];
__device__ float  g_cstate[NSEQ * DD];
__device__ float  g_lstmbias[4 * DD];
__device__ __half g_wTh[47u * 1048576u];   // transposed fp16 weights

__device__ __forceinline__ float tanh_fast(float x) {
    float r; asm("tanh.approx.f32 %0, %1;" : "=f"(r) : "f"(x)); return r;
}
__device__ __forceinline__ float gelu_tanh(float x) {
    return 0.5f * x * (1.f + tanh_fast(0.7978845608028654f * (x + 0.044715f * x * x * x)));
}
__device__ __forceinline__ float sigm(float x) { return 0.5f * (1.f + tanh_fast(0.5f * x)); }
__device__ __forceinline__ uint32_t h2_as_u32(__half2 h) {
    uint32_t u; *reinterpret_cast<__half2*>(&u) = h; return u;
}
__device__ __forceinline__ void mma_f16(float d[4], uint32_t a0, uint32_t a1, uint32_t a2,
                                        uint32_t a3, uint32_t b0, uint32_t b1) {
    asm volatile(
        "mma.sync.aligned.m16n8k16.row.col.f32.f16.f16.f32 "
        "{%0,%1,%2,%3}, {%4,%5,%6,%7}, {%8,%9}, {%0,%1,%2,%3};\n"
        : "+f"(d[0]), "+f"(d[1]), "+f"(d[2]), "+f"(d[3])
        : "r"(a0), "r"(a1), "r"(a2), "r"(a3), "r"(b0), "r"(b1));
}
__device__ __forceinline__ void cp_async16(uint32_t dst, const void* src, int szvalid) {
    asm volatile("cp.async.cg.shared.global [%0], [%1], 16, %2;"
                 :: "r"(dst), "l"(src), "r"(szvalid));
}
__device__ __forceinline__ void cp_commit() { asm volatile("cp.async.commit_group;"); }

// ================== fp16 tensor-core GEMM: C[M,N] = A[M,K] @ BT[N,K]^T ==================
// 128 threads = 4 warps (2x2), warp tile 64x64, block tile 128x128x32, 4-stage cp.async.
#define GPITCH_B   80
#define GOP_BYTES  (128 * GPITCH_B)
#define GSTAGE_B   (2 * GOP_BYTES)       // 20480 per stage
#define GTC_NSTAGE 4
#define GTC_SMEM_TOTAL (GTC_NSTAGE * GSTAGE_B)   // 81920 bytes

template<int EPI, int OUTH>
__global__ __launch_bounds__(128, 2)
void gemm_tc(const __half* __restrict__ A, const __half* __restrict__ BT,
             const float* __restrict__ bias, void* __restrict__ Cout,
             int M, int N, int K) {
    extern __shared__ char smem[];
    const uint32_t sb = (uint32_t)__cvta_generic_to_shared(smem);
    const int tid = threadIdx.x;
    const int lane = tid & 31;
    const int wid = tid >> 5;
    const int wr = wid >> 1;
    const int wc = wid & 1;
    const int g4 = lane >> 2, t4 = lane & 3;
    const int bx = blockIdx.x, by = blockIdx.y;
    const int gra = by * 128;
    const int gnb = bx * 128;

    float acc[4][8][4];
#pragma unroll
    for (int mt = 0; mt < 4; mt++)
#pragma unroll
        for (int nt = 0; nt < 8; nt++)
#pragma unroll
            for (int q = 0; q < 4; q++) acc[mt][nt][q] = 0.f;

    const int nk = K >> 5;

    auto load_stage = [&](int kc, int s) {
        const uint32_t sbase = sb + s * GSTAGE_B;
#pragma unroll
        for (int i = 0; i < 4; i++) {
            const int c = tid + i * 128;
            const int row = c >> 2, seg = c & 3;
            const int ga = gra + row;
            const bool ok = ga < M;
            cp_async16(sbase + row * GPITCH_B + seg * 16,
                       A + (size_t)(ok ? ga : 0) * K + kc * 32 + seg * 8, ok ? 16 : 0);
            cp_async16(sbase + GOP_BYTES + row * GPITCH_B + seg * 16,
                       BT + (size_t)(gnb + row) * K + kc * 32 + seg * 8, 16);
        }
    };

    load_stage(0, 0); cp_commit();
    load_stage(1, 1); cp_commit();
    load_stage(2, 2); cp_commit();

    for (int kc = 0; kc < nk; kc++) {
        if (kc < nk - 2)       asm volatile("cp.async.wait_group 2;");
        else if (kc == nk - 2) asm volatile("cp.async.wait_group 1;");
        else                   asm volatile("cp.async.wait_group 0;");
        __syncthreads();
        if (kc + 3 < nk) { load_stage(kc + 3, (kc + 3) & (GTC_NSTAGE - 1)); cp_commit(); }

        const char* sA = smem + (kc & (GTC_NSTAGE - 1)) * GSTAGE_B;
        const char* sB = sA + GOP_BYTES;
#pragma unroll
        for (int ks = 0; ks < 2; ks++) {
            const int kb = ks * 32 + t4 * 4;
            uint32_t af[4][4];
            uint32_t bf[8][2];
#pragma unroll
            for (int mt = 0; mt < 4; mt++) {
                const int r = wr * 64 + mt * 16 + g4;
                af[mt][0] = *(const uint32_t*)(sA + r * GPITCH_B + kb);
                af[mt][1] = *(const uint32_t*)(sA + (r + 8) * GPITCH_B + kb);
                af[mt][2] = *(const uint32_t*)(sA + r * GPITCH_B + kb + 16);
                af[mt][3] = *(const uint32_t*)(sA + (r + 8) * GPITCH_B + kb + 16);
            }
#pragma unroll
            for (int nt = 0; nt < 8; nt++) {
                const int n = wc * 64 + nt * 8 + g4;
                bf[nt][0] = *(const uint32_t*)(sB + n * GPITCH_B + kb);
                bf[nt][1] = *(const uint32_t*)(sB + n * GPITCH_B + kb + 16);
            }
#pragma unroll
            for (int mt = 0; mt < 4; mt++)
#pragma unroll
                for (int nt = 0; nt < 8; nt++)
                    mma_f16(acc[mt][nt], af[mt][0], af[mt][1], af[mt][2], af[mt][3],
                            bf[nt][0], bf[nt][1]);
        }
    }

#pragma unroll
    for (int mt = 0; mt < 4; mt++) {
        const int r0 = by * 128 + wr * 64 + mt * 16 + g4;
#pragma unroll
        for (int nt = 0; nt < 8; nt++) {
            const int col = bx * 128 + wc * 64 + nt * 8 + t4 * 2;
            float b0 = 0.f, b1 = 0.f;
            if (bias) { b0 = __ldg(bias + col); b1 = __ldg(bias + col + 1); }
            float v0 = acc[mt][nt][0] + b0;
            float v1 = acc[mt][nt][1] + b1;
            float v2 = acc[mt][nt][2] + b0;
            float v3 = acc[mt][nt][3] + b1;
            if (EPI == 1) {
                v0 = gelu_tanh(v0); v1 = gelu_tanh(v1);
                v2 = gelu_tanh(v2); v3 = gelu_tanh(v3);
            }
            if (OUTH) {
                __half* Ch = (__half*)Cout;
                if (r0 < M) *(__half2*)(Ch + (size_t)r0 * N + col) = __floats2half2_rn(v0, v1);
                if (r0 + 8 < M) *(__half2*)(Ch + (size_t)(r0 + 8) * N + col) = __floats2half2_rn(v2, v3);
            } else {
                float* Cf = (float*)Cout;
                if (r0 < M) *(float2*)(Cf + (size_t)r0 * N + col) = make_float2(v0, v1);
                if (r0 + 8 < M) *(float2*)(Cf + (size_t)(r0 + 8) * N + col) = make_float2(v2, v3);
            }
        }
    }
}

// ============ fused LSTM step: gates = h@w_hhT + gatesx; cell; out = xbuf + r_gate*h ============
// 64x128 block tile, 4 warps (2x2, warp tile 32x64), grid (32, 8) = 256 CTAs, 2-stage.
// A = h fp16 [512,1024]; BT = wt_lhh_perm [4096,1024]; col n = 4j+g. rmod stride MODW.
#define LSA_OP   (64 * GPITCH_B)      // 5120
#define LSB_OP   (128 * GPITCH_B)     // 10240
#define LSTAGE_B (LSA_OP + LSB_OP)    // 15360
#define LSTM_SMEM_TOTAL (2 * LSTAGE_B)  // 30720

__global__ __launch_bounds__(128, 2)
void lstm_step_tc(const __half* __restrict__ A, const __half* __restrict__ BT,
                  const __half* __restrict__ gx, float* __restrict__ cst,
                  __half* __restrict__ hnext, const float* __restrict__ xbuf,
                  const float* __restrict__ rmod, float* __restrict__ outp, int t) {
    extern __shared__ char smem[];
    const uint32_t sb = (uint32_t)__cvta_generic_to_shared(smem);
    const int tid = threadIdx.x;
    const int lane = tid & 31;
    const int wid = tid >> 5;
    const int wr = wid >> 1;        // 0..1 (32-row groups)
    const int wc = wid & 1;         // 0..1 (64-col groups)
    const int g4 = lane >> 2, t4 = lane & 3;
    const int bx = blockIdx.x, by = blockIdx.y;
    const int gra = by * 64;
    const int gnb = bx * 128;
    const int K = 1024, nk = 32;

    float acc[2][8][4];
#pragma unroll
    for (int mt = 0; mt < 2; mt++)
#pragma unroll
        for (int nt = 0; nt < 8; nt++)
#pragma unroll
            for (int q = 0; q < 4; q++) acc[mt][nt][q] = 0.f;

    auto load_stage = [&](int kc, int p) {
        const uint32_t sbase = sb + p * LSTAGE_B;
        // A: 64 rows x 4 segs = 256 chunks
#pragma unroll
        for (int i = 0; i < 2; i++) {
            const int c = tid + i * 128;
            const int row = c >> 2, seg = c & 3;
            cp_async16(sbase + row * GPITCH_B + seg * 16,
                       A + (size_t)(gra + row) * K + kc * 32 + seg * 8, 16);
        }
        // B: 128 rows x 4 segs = 512 chunks
#pragma unroll
        for (int i = 0; i < 4; i++) {
            const int c = tid + i * 128;
            const int row = c >> 2, seg = c & 3;
            cp_async16(sbase + LSA_OP + row * GPITCH_B + seg * 16,
                       BT + (size_t)(gnb + row) * K + kc * 32 + seg * 8, 16);
        }
    };

    load_stage(0, 0);
    cp_commit();

    for (int kc = 0; kc < nk; kc++) {
        const int p = kc & 1;
        if (kc + 1 < nk) {
            load_stage(kc + 1, p ^ 1);
            cp_commit();
            asm volatile("cp.async.wait_group 1;");
        } else {
            asm volatile("cp.async.wait_group 0;");
        }
        __syncthreads();
        const char* sA = smem + p * LSTAGE_B;
        const char* sB = sA + LSA_OP;
#pragma unroll
        for (int ks = 0; ks < 2; ks++) {
            const int kb = ks * 32 + t4 * 4;
            uint32_t af[2][4];
            uint32_t bf[8][2];
#pragma unroll
            for (int mt = 0; mt < 2; mt++) {
                const int r = wr * 32 + mt * 16 + g4;
                af[mt][0] = *(const uint32_t*)(sA + r * GPITCH_B + kb);
                af[mt][1] = *(const uint32_t*)(sA + (r + 8) * GPITCH_B + kb);
                af[mt][2] = *(const uint32_t*)(sA + r * GPITCH_B + kb + 16);
                af[mt][3] = *(const uint32_t*)(sA + (r + 8) * GPITCH_B + kb + 16);
            }
#pragma unroll
            for (int nt = 0; nt < 8; nt++) {
                const int n = wc * 64 + nt * 8 + g4;
                bf[nt][0] = *(const uint32_t*)(sB + n * GPITCH_B + kb);
                bf[nt][1] = *(const uint32_t*)(sB + n * GPITCH_B + kb + 16);
            }
#pragma unroll
            for (int mt = 0; mt < 2; mt++)
#pragma unroll
                for (int nt = 0; nt < 8; nt++)
                    mma_f16(acc[mt][nt], af[mt][0], af[mt][1], af[mt][2], af[mt][3],
                            bf[nt][0], bf[nt][1]);
        }
        __syncthreads();
    }

    // fused cell epilogue (gate-interleaved columns: col = 4j+g), fused gated residual out
#pragma unroll
    for (int mt = 0; mt < 2; mt++) {
        const int r0 = by * 64 + wr * 32 + mt * 16 + g4;
        const int r1 = r0 + 8;
        const int tok0 = ((r0 >> 8) << 12) + (t << 8) + (r0 & 255);
        const int tok1 = ((r1 >> 8) << 12) + (t << 8) + (r1 & 255);
        const int bt0 = tok0 >> 8, bt1 = tok1 >> 8;
#pragma unroll
        for (int nt = 0; nt < 8; nt++) {
            const int col = bx * 128 + wc * 64 + nt * 8 + t4 * 2;
            __half2 gx0 = *(const __half2*)(gx + (size_t)tok0 * 4096 + col);
            __half2 gx1 = *(const __half2*)(gx + (size_t)tok1 * 4096 + col);
            float v0 = acc[mt][nt][0] + __half2float(__low2half(gx0));
            float v1 = acc[mt][nt][1] + __half2float(__high2half(gx0));
            float v2 = acc[mt][nt][2] + __half2float(__low2half(gx1));
            float v3 = acc[mt][nt][3] + __half2float(__high2half(gx1));
            float p0 = __shfl_xor_sync(0xffffffffu, v0, 1);
            float p1 = __shfl_xor_sync(0xffffffffu, v1, 1);
            float p2 = __shfl_xor_sync(0xffffffffu, v2, 1);
            float p3 = __shfl_xor_sync(0xffffffffu, v3, 1);
            if (!(lane & 1)) {
                const int j = col >> 2;
                {
                    float cc = sigm(v1) * cst[r0 * 1024 + j] + sigm(v0) * tanh_fast(p0);
                    float hh = sigm(p1) * tanh_fast(cc);
                    cst[r0 * 1024 + j] = cc;
                    hnext[r0 * 1024 + j] = __float2half(hh);
                    float rg = rmod[bt0 * MODW + 2048 + j];
                    outp[(size_t)tok0 * 1024 + j] = xbuf[(size_t)tok0 * 1024 + j] + rg * hh;
                }
                {
                    float cc = sigm(v3) * cst[r1 * 1024 + j] + sigm(v2) * tanh_fast(p2);
                    float hh = sigm(p3) * tanh_fast(cc);
                    cst[r1 * 1024 + j] = cc;
                    hnext[r1 * 1024 + j] = __float2half(hh);
                    float rg = rmod[bt1 * MODW + 2048 + j];
                    outp[(size_t)tok1 * 1024 + j] = xbuf[(size_t)tok1 * 1024 + j] + rg * hh;
                }
            }
        }
    }
}

// ---------------- batched weight transpose: all matrices in one launch ----------------
struct TransDesc { const float* W; __half* WT; int K; int N; int perm; int tileStart; };
struct TransArgs { TransDesc d[13]; };

__global__ __launch_bounds__(256)
void transpose_all_kernel(TransArgs a) {
    __shared__ float t[32][33];
    const int bid = blockIdx.x;
    int i = 0;
#pragma unroll
    for (int k = 0; k < 12; k++) if (bid >= a.d[k + 1].tileStart) i = k + 1;
    const TransDesc& td = a.d[i];
    const int local = bid - td.tileStart;
    const int ntx = td.N / 32;
    const int n0 = (local % ntx) * 32, k0 = (local / ntx) * 32;
    const int tx = threadIdx.x & 31, ty = threadIdx.x >> 5;
#pragma unroll
    for (int j = 0; j < 4; j++)
        t[ty + j * 8][tx] = td.W[(size_t)(k0 + ty + j * 8) * td.N + n0 + tx];
    __syncthreads();
#pragma unroll
    for (int j = 0; j < 4; j++) {
        int n = n0 + ty + j * 8;
        int nd = td.perm ? (4 * (n & 1023) + (n >> 10)) : n;
        td.WT[(size_t)nd * td.K + k0 + tx] = __float2half(t[tx][ty + j * 8]);
    }
}

// ---------------- LayerNorm + adaLN modulate (fp16 out) ----------------
__global__ __launch_bounds__(256)
void ln_mod_kernel(const float* __restrict__ x, const float* __restrict__ mod,
                   int mstride, int shift_off, int scale_off, __half* __restrict__ out) {
    __shared__ float red[16];
    const int tok = blockIdx.x;
    const int tid = threadIdx.x;
    const float* xr = x + (size_t)tok * DD;
    float v[4];
    float s = 0.f, s2 = 0.f;
#pragma unroll
    for (int k = 0; k < 4; k++) {
        float f = xr[tid + k * 256];
        v[k] = f; s += f; s2 += f * f;
    }
#pragma unroll
    for (int o = 16; o; o >>= 1) {
        s += __shfl_xor_sync(0xffffffffu, s, o);
        s2 += __shfl_xor_sync(0xffffffffu, s2, o);
    }
    if ((tid & 31) == 0) { red[tid >> 5] = s; red[8 + (tid >> 5)] = s2; }
    __syncthreads();
    if (tid == 0) {
        float a = 0.f, b = 0.f;
        for (int i = 0; i < 8; i++) { a += red[i]; b += red[8 + i]; }
        red[0] = a; red[8] = b;
    }
    __syncthreads();
    const float mean = red[0] * (1.f / DD);
    const float var = red[8] * (1.f / DD) - mean * mean;
    const float inv = rsqrtf(var + 1e-6f);
    const int bt = tok >> 8;
    const float* m = mod + (size_t)bt * mstride;
    __half* orow = out + (size_t)tok * DD;
#pragma unroll
    for (int k = 0; k < 4; k++) {
        int d = tid + k * 256;
        float ln = (v[k] - mean) * inv;
        orow[d] = __float2half(ln * (1.f + m[scale_off + d]) + m[shift_off + d]);
    }
}

// ---------------- fused gated residual add + LayerNorm + modulate (fp16 delta) ----------------
__global__ __launch_bounds__(256)
void ga_ln_kernel(const float* __restrict__ xin, const __half* __restrict__ delta,
                  const float* __restrict__ modg, int gstride, int gate_off,
                  const float* __restrict__ modl, int lstride, int shift_off, int scale_off,
                  float* __restrict__ xout, __half* __restrict__ lnout) {
    __shared__ float red[16];
    const int tok = blockIdx.x;
    const int tid = threadIdx.x;
    const int bt = tok >> 8;
    const float* xr = xin + (size_t)tok * DD;
    const __half* dr = delta + (size_t)tok * DD;
    const float* mg = modg + (size_t)bt * gstride + gate_off;
    float v[4];
    float s = 0.f, s2 = 0.f;
    float* xo = xout + (size_t)tok * DD;
#pragma unroll
    for (int k = 0; k < 4; k++) {
        int d = tid + k * 256;
        float f = xr[d] + mg[d] * __half2float(dr[d]);
        xo[d] = f;
        v[k] = f; s += f; s2 += f * f;
    }
#pragma unroll
    for (int o = 16; o; o >>= 1) {
        s += __shfl_xor_sync(0xffffffffu, s, o);
        s2 += __shfl_xor_sync(0xffffffffu, s2, o);
    }
    if ((tid & 31) == 0) { red[tid >> 5] = s; red[8 + (tid >> 5)] = s2; }
    __syncthreads();
    if (tid == 0) {
        float a = 0.f, b = 0.f;
        for (int i = 0; i < 8; i++) { a += red[i]; b += red[8 + i]; }
        red[0] = a; red[8] = b;
    }
    __syncthreads();
    const float mean = red[0] * (1.f / DD);
    const float var = red[8] * (1.f / DD) - mean * mean;
    const float inv = rsqrtf(var + 1e-6f);
    const float* ml = modl + (size_t)bt * lstride;
    __half* lo = lnout + (size_t)tok * DD;
#pragma unroll
    for (int k = 0; k < 4; k++) {
        int d = tid + k * 256;
        float ln = (v[k] - mean) * inv;
        lo[d] = __float2half(ln * (1.f + ml[scale_off + d]) + ml[shift_off + d]);
    }
}

// ---------------- small utilities ----------------
__global__ void silu_kernel(const float* __restrict__ c, __half* __restrict__ out, int n) {
    int i = blockIdx.x * 256 + threadIdx.x;
    if (i < n) { float v = c[i]; out[i] = __float2half(v / (1.f + __expf(-v))); }
}
__global__ void ada_bias_kernel(const float* __restrict__ sbp, const float* __restrict__ tbp,
                                const float* __restrict__ rbp, float* __restrict__ o) {
    int i = blockIdx.x * 256 + threadIdx.x;
    if (i < MODW) {
        if (i < 6144) o[i] = sbp[i];
        else if (i < 12288) o[i] = tbp[i - 6144];
        else o[i] = rbp[i - 12288];
    }
}
__global__ void lstm_bias_kernel(const float* __restrict__ a, const float* __restrict__ b,
                                 float* __restrict__ o, int n) {
    int i = blockIdx.x * 256 + threadIdx.x;
    if (i < n) {
        int j = i >> 2, g = i & 3;
        o[i] = a[g * 1024 + j] + b[g * 1024 + j];
    }
}
__global__ void zero_state_kernel(__half* __restrict__ h0, __half* __restrict__ h1,
                                  float* __restrict__ c, int n) {
    int i = blockIdx.x * 256 + threadIdx.x;
    if (i < n) { h0[i] = __float2half(0.f); h1[i] = __float2half(0.f); c[i] = 0.f; }
}

// ======= spatial attention via mma.sync fp16 flash (L=256, dh=64, non-causal) =======
__global__ __launch_bounds__(256, 2)
void spatial_attn_tc(const __half* __restrict__ qkv, __half* __restrict__ out) {
    __shared__ __half sQ[128 * 72];
    __shared__ __half sK[64 * 72];
    __shared__ __half sVT[64 * 72];
    const int bid = blockIdx.x;
    const int qhalf = bid & 1;
    const int head = (bid >> 1) & 15;
    const int n = bid >> 5;
    const int tid = threadIdx.x;
    const int lane = tid & 31;
    const int wid = tid >> 5;
    const int g4 = lane >> 2, t4 = lane & 3;
    const size_t rowbase = (size_t)n * 256;

#pragma unroll
    for (int i = 0; i < 4; i++) {
        int idx = tid + i * 256;
        int row = idx >> 3, seg = idx & 7;
        *(uint4*)&sQ[row * 72 + seg * 8] =
            *(const uint4*)(qkv + (rowbase + qhalf * 128 + row) * 3072 + head * 64 + seg * 8);
    }
    __syncthreads();

    uint32_t af[4][4];
    {
        const int r = wid * 16 + g4;
#pragma unroll
        for (int ks = 0; ks < 4; ks++) {
            af[ks][0] = *(const uint32_t*)&sQ[r * 72 + ks * 16 + t4 * 2];
            af[ks][1] = *(const uint32_t*)&sQ[(r + 8) * 72 + ks * 16 + t4 * 2];
            af[ks][2] = *(const uint32_t*)&sQ[r * 72 + ks * 16 + 8 + t4 * 2];
            af[ks][3] = *(const uint32_t*)&sQ[(r + 8) * 72 + ks * 16 + 8 + t4 * 2];
        }
    }

    float O[8][4];
#pragma unroll
    for (int i = 0; i < 8; i++)
#pragma unroll
        for (int q = 0; q < 4; q++) O[i][q] = 0.f;
    float m0 = -1e30f, m1 = -1e30f, l0 = 0.f, l1 = 0.f;

    for (int kt = 0; kt < 4; kt++) {
#pragma unroll
        for (int i = 0; i < 2; i++) {
            int idx = tid + i * 256;
            int row = idx >> 3, seg = idx & 7;
            const __half* src = qkv + (rowbase + kt * 64 + row) * 3072 + 1024 + head * 64 + seg * 8;
            *(uint4*)&sK[row * 72 + seg * 8] = *(const uint4*)src;
            __half vv[8];
            *(uint4*)vv = *(const uint4*)(src + 1024);
#pragma unroll
            for (int jj = 0; jj < 8; jj++) sVT[(seg * 8 + jj) * 72 + row] = vv[jj];
        }
        __syncthreads();

        float sc[8][4];
#pragma unroll
        for (int nt = 0; nt < 8; nt++) {
#pragma unroll
            for (int q = 0; q < 4; q++) sc[nt][q] = 0.f;
#pragma unroll
            for (int ks = 0; ks < 4; ks++) {
                uint32_t b0 = *(const uint32_t*)&sK[(nt * 8 + g4) * 72 + ks * 16 + t4 * 2];
                uint32_t b1 = *(const uint32_t*)&sK[(nt * 8 + g4) * 72 + ks * 16 + 8 + t4 * 2];
                mma_f16(sc[nt], af[ks][0], af[ks][1], af[ks][2], af[ks][3], b0, b1);
            }
        }

        float mx0 = -1e30f, mx1 = -1e30f;
#pragma unroll
        for (int nt = 0; nt < 8; nt++) {
            sc[nt][0] *= 0.125f; sc[nt][1] *= 0.125f;
            sc[nt][2] *= 0.125f; sc[nt][3] *= 0.125f;
            mx0 = fmaxf(mx0, fmaxf(sc[nt][0], sc[nt][1]));
            mx1 = fmaxf(mx1, fmaxf(sc[nt][2], sc[nt][3]));
        }
        mx0 = fmaxf(mx0, __shfl_xor_sync(0xffffffffu, mx0, 1));
        mx0 = fmaxf(mx0, __shfl_xor_sync(0xffffffffu, mx0, 2));
        mx1 = fmaxf(mx1, __shfl_xor_sync(0xffffffffu, mx1, 1));
        mx1 = fmaxf(mx1, __shfl_xor_sync(0xffffffffu, mx1, 2));
        const float mn0 = fmaxf(m0, mx0), mn1 = fmaxf(m1, mx1);
        const float al0 = __expf(m0 - mn0), al1 = __expf(m1 - mn1);
        m0 = mn0; m1 = mn1;

        float sum0 = 0.f, sum1 = 0.f;
        uint32_t aP[8][2];
#pragma unroll
        for (int nt = 0; nt < 8; nt++) {
            float p0 = __expf(sc[nt][0] - mn0);
            float p1 = __expf(sc[nt][1] - mn0);
            float p2 = __expf(sc[nt][2] - mn1);
            float p3 = __expf(sc[nt][3] - mn1);
            sum0 += p0 + p1; sum1 += p2 + p3;
            aP[nt][0] = h2_as_u32(__floats2half2_rn(p0, p1));
            aP[nt][1] = h2_as_u32(__floats2half2_rn(p2, p3));
        }
        sum0 += __shfl_xor_sync(0xffffffffu, sum0, 1);
        sum0 += __shfl_xor_sync(0xffffffffu, sum0, 2);
        sum1 += __shfl_xor_sync(0xffffffffu, sum1, 1);
        sum1 += __shfl_xor_sync(0xffffffffu, sum1, 2);
        l0 = l0 * al0 + sum0;
        l1 = l1 * al1 + sum1;
#pragma unroll
        for (int nt2 = 0; nt2 < 8; nt2++) {
            O[nt2][0] *= al0; O[nt2][1] *= al0;
            O[nt2][2] *= al1; O[nt2][3] *= al1;
        }

#pragma unroll
        for (int ks2 = 0; ks2 < 4; ks2++) {
            const uint32_t a0 = aP[2 * ks2][0], a1 = aP[2 * ks2][1];
            const uint32_t a2 = aP[2 * ks2 + 1][0], a3 = aP[2 * ks2 + 1][1];
#pragma unroll
            for (int nt2 = 0; nt2 < 8; nt2++) {
                uint32_t b0 = *(const uint32_t*)&sVT[(nt2 * 8 + g4) * 72 + ks2 * 16 + t4 * 2];
                uint32_t b1 = *(const uint32_t*)&sVT[(nt2 * 8 + g4) * 72 + ks2 * 16 + 8 + t4 * 2];
                mma_f16(O[nt2], a0, a1, a2, a3, b0, b1);
            }
        }
        __syncthreads();
    }

    const float inv0 = 1.f / l0, inv1 = 1.f / l1;
    const int q0 = qhalf * 128 + wid * 16 + g4;
#pragma unroll
    for (int nt2 = 0; nt2 < 8; nt2++) {
        const int col = head * 64 + nt2 * 8 + t4 * 2;
        *(__half2*)(out + (rowbase + q0) * 1024 + col) =
            __floats2half2_rn(O[nt2][0] * inv0, O[nt2][1] * inv0);
        *(__half2*)(out + (rowbase + q0 + 8) * 1024 + col) =
            __floats2half2_rn(O[nt2][2] * inv1, O[nt2][3] * inv1);
    }
}

// ---------------- temporal attention (T=16, dh=64, causal; fp16 qkv in/out) ----------------
__global__ __launch_bounds__(128)
void temporal_attn_kernel(const __half* __restrict__ qkv, __half* __restrict__ out) {
    __shared__ float Q[16][65], K[16][65], V[16][65], S[16][17];
    const int bid = blockIdx.x;
    const int head = bid & 15;
    const int n = bid >> 4;
    const int b = n >> 8;
    const int hw = n & 255;
    const int tid = threadIdx.x;
    const size_t tokbase = (size_t)b * 4096 + hw;

    for (int i = tid; i < 16 * 64; i += 128) {
        int t = i >> 6, d = i & 63;
        size_t base = (tokbase + (size_t)t * 256) * 3072 + head * 64 + d;
        Q[t][d] = __half2float(qkv[base]);
        K[t][d] = __half2float(qkv[base + 1024]);
        V[t][d] = __half2float(qkv[base + 2048]);
    }
    __syncthreads();

    for (int idx = tid; idx < 256; idx += 128) {
        int qi = idx >> 4, kj = idx & 15;
        float s;
        if (kj <= qi) {
            float acc = 0.f;
#pragma unroll
            for (int d = 0; d < 64; d++) acc += Q[qi][d] * K[kj][d];
            s = acc * 0.125f;
        } else s = -1e30f;
        S[qi][kj] = s;
    }
    __syncthreads();

    {
        const int row = tid >> 3, c0 = tid & 7;
        float mx = fmaxf(S[row][c0], S[row][c0 + 8]);
#pragma unroll
        for (int o = 4; o; o >>= 1) mx = fmaxf(mx, __shfl_xor_sync(0xffffffffu, mx, o));
        float e0 = __expf(S[row][c0] - mx), e1 = __expf(S[row][c0 + 8] - mx);
        float sum = e0 + e1;
#pragma unroll
        for (int o = 4; o; o >>= 1) sum += __shfl_xor_sync(0xffffffffu, sum, o);
        float inv = 1.f / sum;
        S[row][c0] = e0 * inv;
        S[row][c0 + 8] = e1 * inv;
    }
    __syncthreads();

    for (int i = tid; i < 16 * 64; i += 128) {
        int qi = i >> 6, d = i & 63;
        float acc = 0.f;
#pragma unroll
        for (int k = 0; k < 16; k++) acc = fmaf(S[qi][k], V[k][d], acc);
        out[(tokbase + (size_t)qi * 256) * 1024 + head * 64 + d] = __float2half(acc);
    }
}

// ---------------- launch helpers ----------------
static void gemm(const __half* A, const __half* BT, const float* bias, void* C,
                 int M, int N, int K, int epi, int outh) {
    dim3 g(N / 128, (M + 127) / 128);
    if (epi == 1)      gemm_tc<1, 1><<<g, 128, GTC_SMEM_TOTAL>>>(A, BT, bias, C, M, N, K);
    else if (outh)     gemm_tc<0, 1><<<g, 128, GTC_SMEM_TOTAL>>>(A, BT, bias, C, M, N, K);
    else               gemm_tc<0, 0><<<g, 128, GTC_SMEM_TOTAL>>>(A, BT, bias, C, M, N, K);
}

extern "C" void kernel_launch(void* const* d_in, const int* in_sizes, int n_in,
                              void* d_out, int out_size) {
    const float* x        = (const float*)d_in[0];
    const float* c        = (const float*)d_in[1];
    const float* s_ada_w  = (const float*)d_in[2];
    const float* s_ada_b  = (const float*)d_in[3];
    const float* t_ada_w  = (const float*)d_in[4];
    const float* t_ada_b  = (const float*)d_in[5];
    const float* r_ada_w  = (const float*)d_in[6];
    const float* r_ada_b  = (const float*)d_in[7];
    const float* s_qkv_w  = (const float*)d_in[8];
    const float* s_out_w  = (const float*)d_in[9];
    const float* s_out_b  = (const float*)d_in[10];
    const float* t_qkv_w  = (const float*)d_in[11];
    const float* t_out_w  = (const float*)d_in[12];
    const float* t_out_b  = (const float*)d_in[13];
    const float* s_mlp_w1 = (const float*)d_in[14];
    const float* s_mlp_b1 = (const float*)d_in[15];
    const float* s_mlp_w2 = (const float*)d_in[16];
    const float* s_mlp_b2 = (const float*)d_in[17];
    const float* t_mlp_w1 = (const float*)d_in[18];
    const float* t_mlp_b1 = (const float*)d_in[19];
    const float* t_mlp_w2 = (const float*)d_in[20];
    const float* t_mlp_b2 = (const float*)d_in[21];
    const float* lstm_w_ih = (const float*)d_in[22];
    const float* lstm_w_hh = (const float*)d_in[23];
    const float* lstm_b_ih = (const float*)d_in[24];
    const float* lstm_b_hh = (const float*)d_in[25];
    float* out = (float*)d_out;

    cudaFuncSetAttribute(gemm_tc<0, 0>, cudaFuncAttributeMaxDynamicSharedMemorySize, GTC_SMEM_TOTAL);
    cudaFuncSetAttribute(gemm_tc<0, 1>, cudaFuncAttributeMaxDynamicSharedMemorySize, GTC_SMEM_TOTAL);
    cudaFuncSetAttribute(gemm_tc<1, 1>, cudaFuncAttributeMaxDynamicSharedMemorySize, GTC_SMEM_TOTAL);

    __half *csh, *h1h, *qkvh, *deltah, *mlph, *gatesxh, *hstateh, *hstate2h, *wTh;
    float *modall, *adab, *xbuf, *cstate, *lstmbias;
    cudaGetSymbolAddress((void**)&csh, g_csh);
    cudaGetSymbolAddress((void**)&modall, g_modall);
    cudaGetSymbolAddress((void**)&adab, g_adab);
    cudaGetSymbolAddress((void**)&xbuf, g_xbuf);
    cudaGetSymbolAddress((void**)&h1h, g_h1h);
    cudaGetSymbolAddress((void**)&qkvh, g_qkvh);
    cudaGetSymbolAddress((void**)&deltah, g_deltah);
    cudaGetSymbolAddress((void**)&mlph, g_mlph);
    cudaGetSymbolAddress((void**)&gatesxh, g_gatesxh);
    cudaGetSymbolAddress((void**)&hstateh, g_hstateh);
    cudaGetSymbolAddress((void**)&hstate2h, g_hstate2h);
    cudaGetSymbolAddress((void**)&cstate, g_cstate);
    cudaGetSymbolAddress((void**)&lstmbias, g_lstmbias);
    cudaGetSymbolAddress((void**)&wTh, g_wTh);

    float* smod = modall;              // stride MODW, offsets 0..5*DD
    float* tmod = modall + 6144;       // stride MODW
    float* rmod = modall + 12288;      // stride MODW

    const size_t MEG = 1048576;
    __half* wt_ada   = wTh + 0 * MEG;   // [15360,1024]: sada|tada|rada contiguous
    __half* wt_sqkv  = wTh + 15 * MEG;
    __half* wt_sout  = wTh + 18 * MEG;
    __half* wt_tqkv  = wTh + 19 * MEG;
    __half* wt_tout  = wTh + 22 * MEG;
    __half* wt_smlp1 = wTh + 23 * MEG;
    __half* wt_smlp2 = wTh + 27 * MEG;
    __half* wt_tmlp1 = wTh + 31 * MEG;
    __half* wt_tmlp2 = wTh + 35 * MEG;
    __half* wt_lih   = wTh + 39 * MEG;  // gate-interleaved [4096,1024]
    __half* wt_lhh   = wTh + 43 * MEG;  // gate-interleaved [4096,1024]

    // batched transpose: all 13 matrices, one launch
    {
        TransArgs ta;
        auto set = [&](int i, const float* W, __half* WT, int K, int N, int perm, int start) {
            ta.d[i].W = W; ta.d[i].WT = WT; ta.d[i].K = K; ta.d[i].N = N;
            ta.d[i].perm = perm; ta.d[i].tileStart = start;
        };
        int s = 0;
        set(0,  s_ada_w,  wt_ada,            1024, 6144, 0, s); s += (6144 / 32) * 32;
        set(1,  t_ada_w,  wt_ada + 6 * MEG,  1024, 6144, 0, s); s += (6144 / 32) * 32;
        set(2,  r_ada_w,  wt_ada + 12 * MEG, 1024, 3072, 0, s); s += (3072 / 32) * 32;
        set(3,  s_qkv_w,  wt_sqkv,  1024, 3072, 0, s); s += (3072 / 32) * 32;
        set(4,  s_out_w,  wt_sout,  1024, 1024, 0, s); s += (1024 / 32) * 32;
        set(5,  t_qkv_w,  wt_tqkv,  1024, 3072, 0, s); s += (3072 / 32) * 32;
        set(6,  t_out_w,  wt_tout,  1024, 1024, 0, s); s += (1024 / 32) * 32;
        set(7,  s_mlp_w1, wt_smlp1, 1024, 4096, 0, s); s += (4096 / 32) * 32;
        set(8,  s_mlp_w2, wt_smlp2, 4096, 1024, 0, s); s += (1024 / 32) * 128;
        set(9,  t_mlp_w1, wt_tmlp1, 1024, 4096, 0, s); s += (4096 / 32) * 32;
        set(10, t_mlp_w2, wt_tmlp2, 4096, 1024, 0, s); s += (1024 / 32) * 128;
        set(11, lstm_w_ih, wt_lih,  1024, 4096, 1, s); s += (4096 / 32) * 32;
        set(12, lstm_w_hh, wt_lhh,  1024, 4096, 1, s); s += (4096 / 32) * 32;
        transpose_all_kernel<<<s, 256>>>(ta);
    }

    // conditioning (single merged ada GEMM)
    silu_kernel<<<(NBT * DD + 255) / 256, 256>>>(c, csh, NBT * DD);
    ada_bias_kernel<<<(MODW + 255) / 256, 256>>>(s_ada_b, t_ada_b, r_ada_b, adab);
    gemm(csh, wt_ada, adab, modall, NBT, MODW, DD, 0, 0);

    // ---- spatial attention ----
    ln_mod_kernel<<<NTOK, 256>>>(x, smod, MODW, 0, DD, h1h);
    gemm(h1h, wt_sqkv, nullptr, qkvh, NTOK, 3 * DD, DD, 0, 1);
    spatial_attn_tc<<<1024, 256>>>(qkvh, h1h);
    gemm(h1h, wt_sout, s_out_b, deltah, NTOK, DD, DD, 0, 1);
    ga_ln_kernel<<<NTOK, 256>>>(x, deltah, smod, MODW, 2 * DD,
                                smod, MODW, 3 * DD, 4 * DD, xbuf, h1h);

    // ---- spatial MLP ----
    gemm(h1h, wt_smlp1, s_mlp_b1, mlph, NTOK, 4 * DD, DD, 1, 1);
    gemm(mlph, wt_smlp2, s_mlp_b2, deltah, NTOK, DD, 4 * DD, 0, 1);
    ga_ln_kernel<<<NTOK, 256>>>(xbuf, deltah, smod, MODW, 5 * DD,
                                tmod, MODW, 0, DD, xbuf, h1h);

    // ---- temporal attention (causal) ----
    gemm(h1h, wt_tqkv, nullptr, qkvh, NTOK, 3 * DD, DD, 0, 1);
    temporal_attn_kernel<<<8192, 128>>>(qkvh, h1h);
    gemm(h1h, wt_tout, t_out_b, deltah, NTOK, DD, DD, 0, 1);
    ga_ln_kernel<<<NTOK, 256>>>(xbuf, deltah, tmod, MODW, 2 * DD,
                                tmod, MODW, 3 * DD, 4 * DD, xbuf, h1h);

    // ---- temporal MLP ----
    gemm(h1h, wt_tmlp1, t_mlp_b1, mlph, NTOK, 4 * DD, DD, 1, 1);
    gemm(mlph, wt_tmlp2, t_mlp_b2, deltah, NTOK, DD, 4 * DD, 0, 1);
    ga_ln_kernel<<<NTOK, 256>>>(xbuf, deltah, tmod, MODW, 5 * DD,
                                rmod, MODW, 0, DD, xbuf, h1h);

    // ---- LSTM branch (gate-interleaved, fused cell + fused gated residual out) ----
    lstm_bias_kernel<<<(4 * DD + 255) / 256, 256>>>(lstm_b_ih, lstm_b_hh, lstmbias, 4 * DD);
    gemm(h1h, wt_lih, lstmbias, gatesxh, NTOK, 4 * DD, DD, 0, 1);
    zero_state_kernel<<<(NSEQ * DD + 255) / 256, 256>>>(hstateh, hstate2h, cstate, NSEQ * DD);
    {
        __half* hb[2] = {hstateh, hstate2h};
        for (int t = 0; t < TT; t++) {
            lstm_step_tc<<<dim3(32, 8), 128, LSTM_SMEM_TOTAL>>>(
                hb[t & 1], wt_lhh, gatesxh, cstate, hb[(t + 1) & 1], xbuf, rmod, out, t);
        }
    }
}

// round 11
// speedup vs baseline: 5.9358x; 1.0009x over previous
#include <cuda_runtime.h>
#include <cuda_fp16.h>
#include <math.h>
#include <cstdint>

// Problem constants
#define DD   1024
#define NTOK 8192      // B*T*H*W
#define NBT  32        // B*T
#define NSEQ 512       // B*H*W
#define TT   16
#define MODW 15360     // 6*DD + 6*DD + 3*DD combined ada width

// ---------------- scratch (device globals; no allocations allowed) ----------------
__device__ __half g_csh[NBT * DD];
__device__ float  g_modall[NBT * MODW];
__device__ float  g_adab[MODW];
__device__ float  g_xbuf[NTOK * DD];
__device__ __half g_h1h[NTOK * DD];
__device__ __half g_qkvh[NTOK * 3 * DD];
__device__ __half g_deltah[NTOK * DD];
__device__ __half g_mlph[NTOK * 4 * DD];
__device__ __half g_gatesxh[NTOK * 4 * DD];
__device__ __half g_hstateh[NSEQ * DD];
__device__ __half g_hstate2h[NSEQ * DD];
__device__ float  g_cstate[NSEQ * DD];
__device__ float  g_lstmbias[4 * DD];
__device__ unsigned int g_lstm_bar;
__device__ __half g_wTh[47u * 1048576u];   // transposed fp16 weights

__device__ __forceinline__ float tanh_fast(float x) {
    float r; asm("tanh.approx.f32 %0, %1;" : "=f"(r) : "f"(x)); return r;
}
__device__ __forceinline__ float gelu_tanh(float x) {
    return 0.5f * x * (1.f + tanh_fast(0.7978845608028654f * (x + 0.044715f * x * x * x)));
}
__device__ __forceinline__ float sigm(float x) { return 0.5f * (1.f + tanh_fast(0.5f * x)); }
__device__ __forceinline__ uint32_t h2_as_u32(__half2 h) {
    uint32_t u; *reinterpret_cast<__half2*>(&u) = h; return u;
}
__device__ __forceinline__ void mma_f16(float d[4], uint32_t a0, uint32_t a1, uint32_t a2,
                                        uint32_t a3, uint32_t b0, uint32_t b1) {
    asm volatile(
        "mma.sync.aligned.m16n8k16.row.col.f32.f16.f16.f32 "
        "{%0,%1,%2,%3}, {%4,%5,%6,%7}, {%8,%9}, {%0,%1,%2,%3};\n"
        : "+f"(d[0]), "+f"(d[1]), "+f"(d[2]), "+f"(d[3])
        : "r"(a0), "r"(a1), "r"(a2), "r"(a3), "r"(b0), "r"(b1));
}
__device__ __forceinline__ void cp_async16(uint32_t dst, const void* src, int szvalid) {
    asm volatile("cp.async.cg.shared.global [%0], [%1], 16, %2;"
                 :: "r"(dst), "l"(src), "r"(szvalid));
}
__device__ __forceinline__ void cp_commit() { asm volatile("cp.async.commit_group;"); }

// ================== fp16 tensor-core GEMM: C[M,N] = A[M,K] @ BT[N,K]^T ==================
// 128 threads = 4 warps (2x2), warp tile 64x64, block tile 128x128x32, 4-stage cp.async.
#define GPITCH_B   80
#define GOP_BYTES  (128 * GPITCH_B)
#define GSTAGE_B   (2 * GOP_BYTES)       // 20480 per stage
#define GTC_NSTAGE 4
#define GTC_SMEM_TOTAL (GTC_NSTAGE * GSTAGE_B)   // 81920 bytes

template<int EPI, int OUTH>
__global__ __launch_bounds__(128, 2)
void gemm_tc(const __half* __restrict__ A, const __half* __restrict__ BT,
             const float* __restrict__ bias, void* __restrict__ Cout,
             int M, int N, int K) {
    extern __shared__ char smem[];
    const uint32_t sb = (uint32_t)__cvta_generic_to_shared(smem);
    const int tid = threadIdx.x;
    const int lane = tid & 31;
    const int wid = tid >> 5;
    const int wr = wid >> 1;
    const int wc = wid & 1;
    const int g4 = lane >> 2, t4 = lane & 3;
    const int bx = blockIdx.x, by = blockIdx.y;
    const int gra = by * 128;
    const int gnb = bx * 128;

    float acc[4][8][4];
#pragma unroll
    for (int mt = 0; mt < 4; mt++)
#pragma unroll
        for (int nt = 0; nt < 8; nt++)
#pragma unroll
            for (int q = 0; q < 4; q++) acc[mt][nt][q] = 0.f;

    const int nk = K >> 5;

    auto load_stage = [&](int kc, int s) {
        const uint32_t sbase = sb + s * GSTAGE_B;
#pragma unroll
        for (int i = 0; i < 4; i++) {
            const int c = tid + i * 128;
            const int row = c >> 2, seg = c & 3;
            const int ga = gra + row;
            const bool ok = ga < M;
            cp_async16(sbase + row * GPITCH_B + seg * 16,
                       A + (size_t)(ok ? ga : 0) * K + kc * 32 + seg * 8, ok ? 16 : 0);
            cp_async16(sbase + GOP_BYTES + row * GPITCH_B + seg * 16,
                       BT + (size_t)(gnb + row) * K + kc * 32 + seg * 8, 16);
        }
    };

    load_stage(0, 0); cp_commit();
    load_stage(1, 1); cp_commit();
    load_stage(2, 2); cp_commit();

    for (int kc = 0; kc < nk; kc++) {
        if (kc < nk - 2)       asm volatile("cp.async.wait_group 2;");
        else if (kc == nk - 2) asm volatile("cp.async.wait_group 1;");
        else                   asm volatile("cp.async.wait_group 0;");
        __syncthreads();
        if (kc + 3 < nk) { load_stage(kc + 3, (kc + 3) & (GTC_NSTAGE - 1)); cp_commit(); }

        const char* sA = smem + (kc & (GTC_NSTAGE - 1)) * GSTAGE_B;
        const char* sB = sA + GOP_BYTES;
#pragma unroll
        for (int ks = 0; ks < 2; ks++) {
            const int kb = ks * 32 + t4 * 4;
            uint32_t af[4][4];
            uint32_t bf[8][2];
#pragma unroll
            for (int mt = 0; mt < 4; mt++) {
                const int r = wr * 64 + mt * 16 + g4;
                af[mt][0] = *(const uint32_t*)(sA + r * GPITCH_B + kb);
                af[mt][1] = *(const uint32_t*)(sA + (r + 8) * GPITCH_B + kb);
                af[mt][2] = *(const uint32_t*)(sA + r * GPITCH_B + kb + 16);
                af[mt][3] = *(const uint32_t*)(sA + (r + 8) * GPITCH_B + kb + 16);
            }
#pragma unroll
            for (int nt = 0; nt < 8; nt++) {
                const int n = wc * 64 + nt * 8 + g4;
                bf[nt][0] = *(const uint32_t*)(sB + n * GPITCH_B + kb);
                bf[nt][1] = *(const uint32_t*)(sB + n * GPITCH_B + kb + 16);
            }
#pragma unroll
            for (int mt = 0; mt < 4; mt++)
#pragma unroll
                for (int nt = 0; nt < 8; nt++)
                    mma_f16(acc[mt][nt], af[mt][0], af[mt][1], af[mt][2], af[mt][3],
                            bf[nt][0], bf[nt][1]);
        }
    }

#pragma unroll
    for (int mt = 0; mt < 4; mt++) {
        const int r0 = by * 128 + wr * 64 + mt * 16 + g4;
#pragma unroll
        for (int nt = 0; nt < 8; nt++) {
            const int col = bx * 128 + wc * 64 + nt * 8 + t4 * 2;
            float b0 = 0.f, b1 = 0.f;
            if (bias) { b0 = __ldg(bias + col); b1 = __ldg(bias + col + 1); }
            float v0 = acc[mt][nt][0] + b0;
            float v1 = acc[mt][nt][1] + b1;
            float v2 = acc[mt][nt][2] + b0;
            float v3 = acc[mt][nt][3] + b1;
            if (EPI == 1) {
                v0 = gelu_tanh(v0); v1 = gelu_tanh(v1);
                v2 = gelu_tanh(v2); v3 = gelu_tanh(v3);
            }
            if (OUTH) {
                __half* Ch = (__half*)Cout;
                if (r0 < M) *(__half2*)(Ch + (size_t)r0 * N + col) = __floats2half2_rn(v0, v1);
                if (r0 + 8 < M) *(__half2*)(Ch + (size_t)(r0 + 8) * N + col) = __floats2half2_rn(v2, v3);
            } else {
                float* Cf = (float*)Cout;
                if (r0 < M) *(float2*)(Cf + (size_t)r0 * N + col) = make_float2(v0, v1);
                if (r0 + 8 < M) *(float2*)(Cf + (size_t)(r0 + 8) * N + col) = make_float2(v2, v3);
            }
        }
    }
}

// ============ persistent fused LSTM: all 16 steps in one launch ============
// 64x128 block tile, 4 warps (2x2, warp tile 32x64), grid (32, 8) = 256 CTAs, 2-stage.
// All 256 CTAs co-resident (occ 2/SM x 148 SM = 296 slots); device-wide spin barrier
// between steps (counter zeroed by setup kernel each replay; monotone targets).
// t=0: h==0 so gates = gatesx (skip mainloop); c_prev = 0 (no zero-init needed).
#define LSA_OP   (64 * GPITCH_B)      // 5120
#define LSB_OP   (128 * GPITCH_B)     // 10240
#define LSTAGE_B (LSA_OP + LSB_OP)    // 15360
#define LSTM_SMEM_TOTAL (2 * LSTAGE_B)  // 30720

__global__ __launch_bounds__(128, 2)
void lstm_persist_tc(__half* __restrict__ h0buf, __half* __restrict__ h1buf,
                     const __half* __restrict__ BT, const __half* __restrict__ gx,
                     float* __restrict__ cst, const float* __restrict__ xbuf,
                     const float* __restrict__ rmod, float* __restrict__ outp) {
    extern __shared__ char smem[];
    const uint32_t sb = (uint32_t)__cvta_generic_to_shared(smem);
    const int tid = threadIdx.x;
    const int lane = tid & 31;
    const int wid = tid >> 5;
    const int wr = wid >> 1;
    const int wc = wid & 1;
    const int g4 = lane >> 2, t4 = lane & 3;
    const int bx = blockIdx.x, by = blockIdx.y;
    const int gra = by * 64;
    const int gnb = bx * 128;
    const int K = 1024, nk = 32;

    for (int t = 0; t < TT; t++) {
        const __half* A = (t & 1) ? h1buf : h0buf;
        __half* hnext = (t & 1) ? h0buf : h1buf;

        float acc[2][8][4];
#pragma unroll
        for (int mt = 0; mt < 2; mt++)
#pragma unroll
            for (int nt = 0; nt < 8; nt++)
#pragma unroll
                for (int q = 0; q < 4; q++) acc[mt][nt][q] = 0.f;

        if (t > 0) {
            auto load_stage = [&](int kc, int p) {
                const uint32_t sbase = sb + p * LSTAGE_B;
#pragma unroll
                for (int i = 0; i < 2; i++) {
                    const int c = tid + i * 128;
                    const int row = c >> 2, seg = c & 3;
                    cp_async16(sbase + row * GPITCH_B + seg * 16,
                               A + (size_t)(gra + row) * K + kc * 32 + seg * 8, 16);
                }
#pragma unroll
                for (int i = 0; i < 4; i++) {
                    const int c = tid + i * 128;
                    const int row = c >> 2, seg = c & 3;
                    cp_async16(sbase + LSA_OP + row * GPITCH_B + seg * 16,
                               BT + (size_t)(gnb + row) * K + kc * 32 + seg * 8, 16);
                }
            };

            load_stage(0, 0);
            cp_commit();

            for (int kc = 0; kc < nk; kc++) {
                const int p = kc & 1;
                if (kc + 1 < nk) {
                    load_stage(kc + 1, p ^ 1);
                    cp_commit();
                    asm volatile("cp.async.wait_group 1;");
                } else {
                    asm volatile("cp.async.wait_group 0;");
                }
                __syncthreads();
                const char* sA = smem + p * LSTAGE_B;
                const char* sB = sA + LSA_OP;
#pragma unroll
                for (int ks = 0; ks < 2; ks++) {
                    const int kb = ks * 32 + t4 * 4;
                    uint32_t af[2][4];
                    uint32_t bf[8][2];
#pragma unroll
                    for (int mt = 0; mt < 2; mt++) {
                        const int r = wr * 32 + mt * 16 + g4;
                        af[mt][0] = *(const uint32_t*)(sA + r * GPITCH_B + kb);
                        af[mt][1] = *(const uint32_t*)(sA + (r + 8) * GPITCH_B + kb);
                        af[mt][2] = *(const uint32_t*)(sA + r * GPITCH_B + kb + 16);
                        af[mt][3] = *(const uint32_t*)(sA + (r + 8) * GPITCH_B + kb + 16);
                    }
#pragma unroll
                    for (int nt = 0; nt < 8; nt++) {
                        const int n = wc * 64 + nt * 8 + g4;
                        bf[nt][0] = *(const uint32_t*)(sB + n * GPITCH_B + kb);
                        bf[nt][1] = *(const uint32_t*)(sB + n * GPITCH_B + kb + 16);
                    }
#pragma unroll
                    for (int mt = 0; mt < 2; mt++)
#pragma unroll
                        for (int nt = 0; nt < 8; nt++)
                            mma_f16(acc[mt][nt], af[mt][0], af[mt][1], af[mt][2], af[mt][3],
                                    bf[nt][0], bf[nt][1]);
                }
                __syncthreads();
            }
        }

        // fused cell epilogue (gate-interleaved columns: col = 4j+g), fused gated residual out
#pragma unroll
        for (int mt = 0; mt < 2; mt++) {
            const int r0 = by * 64 + wr * 32 + mt * 16 + g4;
            const int r1 = r0 + 8;
            const int tok0 = ((r0 >> 8) << 12) + (t << 8) + (r0 & 255);
            const int tok1 = ((r1 >> 8) << 12) + (t << 8) + (r1 & 255);
            const int bt0 = tok0 >> 8, bt1 = tok1 >> 8;
#pragma unroll
            for (int nt = 0; nt < 8; nt++) {
                const int col = bx * 128 + wc * 64 + nt * 8 + t4 * 2;
                __half2 gx0 = *(const __half2*)(gx + (size_t)tok0 * 4096 + col);
                __half2 gx1 = *(const __half2*)(gx + (size_t)tok1 * 4096 + col);
                float v0 = acc[mt][nt][0] + __half2float(__low2half(gx0));
                float v1 = acc[mt][nt][1] + __half2float(__high2half(gx0));
                float v2 = acc[mt][nt][2] + __half2float(__low2half(gx1));
                float v3 = acc[mt][nt][3] + __half2float(__high2half(gx1));
                float p0 = __shfl_xor_sync(0xffffffffu, v0, 1);
                float p1 = __shfl_xor_sync(0xffffffffu, v1, 1);
                float p2 = __shfl_xor_sync(0xffffffffu, v2, 1);
                float p3 = __shfl_xor_sync(0xffffffffu, v3, 1);
                if (!(lane & 1)) {
                    const int j = col >> 2;
                    {
                        float cprev = (t == 0) ? 0.f : cst[r0 * 1024 + j];
                        float cc = sigm(v1) * cprev + sigm(v0) * tanh_fast(p0);
                        float hh = sigm(p1) * tanh_fast(cc);
                        cst[r0 * 1024 + j] = cc;
                        hnext[r0 * 1024 + j] = __float2half(hh);
                        float rg = rmod[bt0 * MODW + 2048 + j];
                        outp[(size_t)tok0 * 1024 + j] = xbuf[(size_t)tok0 * 1024 + j] + rg * hh;
                    }
                    {
                        float cprev = (t == 0) ? 0.f : cst[r1 * 1024 + j];
                        float cc = sigm(v3) * cprev + sigm(v2) * tanh_fast(p2);
                        float hh = sigm(p3) * tanh_fast(cc);
                        cst[r1 * 1024 + j] = cc;
                        hnext[r1 * 1024 + j] = __float2half(hh);
                        float rg = rmod[bt1 * MODW + 2048 + j];
                        outp[(size_t)tok1 * 1024 + j] = xbuf[(size_t)tok1 * 1024 + j] + rg * hh;
                    }
                }
            }
        }

        // device-wide barrier between steps (skip after last step)
        if (t < TT - 1) {
            __syncthreads();
            if (tid == 0) {
                __threadfence();
                atomicAdd(&g_lstm_bar, 1u);
                const unsigned int target = 256u * (unsigned int)(t + 1);
                while (atomicAdd(&g_lstm_bar, 0u) < target) {}
                __threadfence();
            }
            __syncthreads();
        }
    }
}

// ---------------- batched weight transpose: all matrices in one launch ----------------
struct TransDesc { const float* W; __half* WT; int K; int N; int perm; int tileStart; };
struct TransArgs { TransDesc d[13]; };

__global__ __launch_bounds__(256)
void transpose_all_kernel(TransArgs a) {
    __shared__ float t[32][33];
    const int bid = blockIdx.x;
    int i = 0;
#pragma unroll
    for (int k = 0; k < 12; k++) if (bid >= a.d[k + 1].tileStart) i = k + 1;
    const TransDesc& td = a.d[i];
    const int local = bid - td.tileStart;
    const int ntx = td.N / 32;
    const int n0 = (local % ntx) * 32, k0 = (local / ntx) * 32;
    const int tx = threadIdx.x & 31, ty = threadIdx.x >> 5;
#pragma unroll
    for (int j = 0; j < 4; j++)
        t[ty + j * 8][tx] = td.W[(size_t)(k0 + ty + j * 8) * td.N + n0 + tx];
    __syncthreads();
#pragma unroll
    for (int j = 0; j < 4; j++) {
        int n = n0 + ty + j * 8;
        int nd = td.perm ? (4 * (n & 1023) + (n >> 10)) : n;
        td.WT[(size_t)nd * td.K + k0 + tx] = __float2half(t[tx][ty + j * 8]);
    }
}

// ---------------- LayerNorm + adaLN modulate (fp16 out) ----------------
__global__ __launch_bounds__(256)
void ln_mod_kernel(const float* __restrict__ x, const float* __restrict__ mod,
                   int mstride, int shift_off, int scale_off, __half* __restrict__ out) {
    __shared__ float red[16];
    const int tok = blockIdx.x;
    const int tid = threadIdx.x;
    const float* xr = x + (size_t)tok * DD;
    float v[4];
    float s = 0.f, s2 = 0.f;
#pragma unroll
    for (int k = 0; k < 4; k++) {
        float f = xr[tid + k * 256];
        v[k] = f; s += f; s2 += f * f;
    }
#pragma unroll
    for (int o = 16; o; o >>= 1) {
        s += __shfl_xor_sync(0xffffffffu, s, o);
        s2 += __shfl_xor_sync(0xffffffffu, s2, o);
    }
    if ((tid & 31) == 0) { red[tid >> 5] = s; red[8 + (tid >> 5)] = s2; }
    __syncthreads();
    if (tid == 0) {
        float a = 0.f, b = 0.f;
        for (int i = 0; i < 8; i++) { a += red[i]; b += red[8 + i]; }
        red[0] = a; red[8] = b;
    }
    __syncthreads();
    const float mean = red[0] * (1.f / DD);
    const float var = red[8] * (1.f / DD) - mean * mean;
    const float inv = rsqrtf(var + 1e-6f);
    const int bt = tok >> 8;
    const float* m = mod + (size_t)bt * mstride;
    __half* orow = out + (size_t)tok * DD;
#pragma unroll
    for (int k = 0; k < 4; k++) {
        int d = tid + k * 256;
        float ln = (v[k] - mean) * inv;
        orow[d] = __float2half(ln * (1.f + m[scale_off + d]) + m[shift_off + d]);
    }
}

// ---------------- fused gated residual add + LayerNorm + modulate (fp16 delta) ----------------
__global__ __launch_bounds__(256)
void ga_ln_kernel(const float* __restrict__ xin, const __half* __restrict__ delta,
                  const float* __restrict__ modg, int gstride, int gate_off,
                  const float* __restrict__ modl, int lstride, int shift_off, int scale_off,
                  float* __restrict__ xout, __half* __restrict__ lnout) {
    __shared__ float red[16];
    const int tok = blockIdx.x;
    const int tid = threadIdx.x;
    const int bt = tok >> 8;
    const float* xr = xin + (size_t)tok * DD;
    const __half* dr = delta + (size_t)tok * DD;
    const float* mg = modg + (size_t)bt * gstride + gate_off;
    float v[4];
    float s = 0.f, s2 = 0.f;
    float* xo = xout + (size_t)tok * DD;
#pragma unroll
    for (int k = 0; k < 4; k++) {
        int d = tid + k * 256;
        float f = xr[d] + mg[d] * __half2float(dr[d]);
        xo[d] = f;
        v[k] = f; s += f; s2 += f * f;
    }
#pragma unroll
    for (int o = 16; o; o >>= 1) {
        s += __shfl_xor_sync(0xffffffffu, s, o);
        s2 += __shfl_xor_sync(0xffffffffu, s2, o);
    }
    if ((tid & 31) == 0) { red[tid >> 5] = s; red[8 + (tid >> 5)] = s2; }
    __syncthreads();
    if (tid == 0) {
        float a = 0.f, b = 0.f;
        for (int i = 0; i < 8; i++) { a += red[i]; b += red[8 + i]; }
        red[0] = a; red[8] = b;
    }
    __syncthreads();
    const float mean = red[0] * (1.f / DD);
    const float var = red[8] * (1.f / DD) - mean * mean;
    const float inv = rsqrtf(var + 1e-6f);
    const float* ml = modl + (size_t)bt * lstride;
    __half* lo = lnout + (size_t)tok * DD;
#pragma unroll
    for (int k = 0; k < 4; k++) {
        int d = tid + k * 256;
        float ln = (v[k] - mean) * inv;
        lo[d] = __float2half(ln * (1.f + ml[scale_off + d]) + ml[shift_off + d]);
    }
}

// ---------------- setup: silu + combined ada bias + permuted lstm bias + barrier reset ----
__global__ void setup_kernel(const float* __restrict__ c, __half* __restrict__ csh,
                             const float* __restrict__ sbp, const float* __restrict__ tbp,
                             const float* __restrict__ rbp, float* __restrict__ adab,
                             const float* __restrict__ lba, const float* __restrict__ lbb,
                             float* __restrict__ lbias) {
    int i = blockIdx.x * 256 + threadIdx.x;
    if (i == 0) g_lstm_bar = 0u;
    if (i < NBT * DD) {
        float v = c[i];
        csh[i] = __float2half(v / (1.f + __expf(-v)));
    }
    if (i < MODW) {
        float b;
        if (i < 6144) b = sbp[i];
        else if (i < 12288) b = tbp[i - 6144];
        else b = rbp[i - 12288];
        adab[i] = b;
    }
    if (i < 4 * DD) {
        int j = i >> 2, g = i & 3;
        lbias[i] = lba[g * 1024 + j] + lbb[g * 1024 + j];
    }
}

// ======= spatial attention via mma.sync fp16 flash (L=256, dh=64, non-causal) =======
__global__ __launch_bounds__(256, 2)
void spatial_attn_tc(const __half* __restrict__ qkv, __half* __restrict__ out) {
    __shared__ __half sQ[128 * 72];
    __shared__ __half sK[64 * 72];
    __shared__ __half sVT[64 * 72];
    const int bid = blockIdx.x;
    const int qhalf = bid & 1;
    const int head = (bid >> 1) & 15;
    const int n = bid >> 5;
    const int tid = threadIdx.x;
    const int lane = tid & 31;
    const int wid = tid >> 5;
    const int g4 = lane >> 2, t4 = lane & 3;
    const size_t rowbase = (size_t)n * 256;

#pragma unroll
    for (int i = 0; i < 4; i++) {
        int idx = tid + i * 256;
        int row = idx >> 3, seg = idx & 7;
        *(uint4*)&sQ[row * 72 + seg * 8] =
            *(const uint4*)(qkv + (rowbase + qhalf * 128 + row) * 3072 + head * 64 + seg * 8);
    }
    __syncthreads();

    uint32_t af[4][4];
    {
        const int r = wid * 16 + g4;
#pragma unroll
        for (int ks = 0; ks < 4; ks++) {
            af[ks][0] = *(const uint32_t*)&sQ[r * 72 + ks * 16 + t4 * 2];
            af[ks][1] = *(const uint32_t*)&sQ[(r + 8) * 72 + ks * 16 + t4 * 2];
            af[ks][2] = *(const uint32_t*)&sQ[r * 72 + ks * 16 + 8 + t4 * 2];
            af[ks][3] = *(const uint32_t*)&sQ[(r + 8) * 72 + ks * 16 + 8 + t4 * 2];
        }
    }

    float O[8][4];
#pragma unroll
    for (int i = 0; i < 8; i++)
#pragma unroll
        for (int q = 0; q < 4; q++) O[i][q] = 0.f;
    float m0 = -1e30f, m1 = -1e30f, l0 = 0.f, l1 = 0.f;

    for (int kt = 0; kt < 4; kt++) {
#pragma unroll
        for (int i = 0; i < 2; i++) {
            int idx = tid + i * 256;
            int row = idx >> 3, seg = idx & 7;
            const __half* src = qkv + (rowbase + kt * 64 + row) * 3072 + 1024 + head * 64 + seg * 8;
            *(uint4*)&sK[row * 72 + seg * 8] = *(const uint4*)src;
            __half vv[8];
            *(uint4*)vv = *(const uint4*)(src + 1024);
#pragma unroll
            for (int jj = 0; jj < 8; jj++) sVT[(seg * 8 + jj) * 72 + row] = vv[jj];
        }
        __syncthreads();

        float sc[8][4];
#pragma unroll
        for (int nt = 0; nt < 8; nt++) {
#pragma unroll
            for (int q = 0; q < 4; q++) sc[nt][q] = 0.f;
#pragma unroll
            for (int ks = 0; ks < 4; ks++) {
                uint32_t b0 = *(const uint32_t*)&sK[(nt * 8 + g4) * 72 + ks * 16 + t4 * 2];
                uint32_t b1 = *(const uint32_t*)&sK[(nt * 8 + g4) * 72 + ks * 16 + 8 + t4 * 2];
                mma_f16(sc[nt], af[ks][0], af[ks][1], af[ks][2], af[ks][3], b0, b1);
            }
        }

        float mx0 = -1e30f, mx1 = -1e30f;
#pragma unroll
        for (int nt = 0; nt < 8; nt++) {
            sc[nt][0] *= 0.125f; sc[nt][1] *= 0.125f;
            sc[nt][2] *= 0.125f; sc[nt][3] *= 0.125f;
            mx0 = fmaxf(mx0, fmaxf(sc[nt][0], sc[nt][1]));
            mx1 = fmaxf(mx1, fmaxf(sc[nt][2], sc[nt][3]));
        }
        mx0 = fmaxf(mx0, __shfl_xor_sync(0xffffffffu, mx0, 1));
        mx0 = fmaxf(mx0, __shfl_xor_sync(0xffffffffu, mx0, 2));
        mx1 = fmaxf(mx1, __shfl_xor_sync(0xffffffffu, mx1, 1));
        mx1 = fmaxf(mx1, __shfl_xor_sync(0xffffffffu, mx1, 2));
        const float mn0 = fmaxf(m0, mx0), mn1 = fmaxf(m1, mx1);
        const float al0 = __expf(m0 - mn0), al1 = __expf(m1 - mn1);
        m0 = mn0; m1 = mn1;

        float sum0 = 0.f, sum1 = 0.f;
        uint32_t aP[8][2];
#pragma unroll
        for (int nt = 0; nt < 8; nt++) {
            float p0 = __expf(sc[nt][0] - mn0);
            float p1 = __expf(sc[nt][1] - mn0);
            float p2 = __expf(sc[nt][2] - mn1);
            float p3 = __expf(sc[nt][3] - mn1);
            sum0 += p0 + p1; sum1 += p2 + p3;
            aP[nt][0] = h2_as_u32(__floats2half2_rn(p0, p1));
            aP[nt][1] = h2_as_u32(__floats2half2_rn(p2, p3));
        }
        sum0 += __shfl_xor_sync(0xffffffffu, sum0, 1);
        sum0 += __shfl_xor_sync(0xffffffffu, sum0, 2);
        sum1 += __shfl_xor_sync(0xffffffffu, sum1, 1);
        sum1 += __shfl_xor_sync(0xffffffffu, sum1, 2);
        l0 = l0 * al0 + sum0;
        l1 = l1 * al1 + sum1;
#pragma unroll
        for (int nt2 = 0; nt2 < 8; nt2++) {
            O[nt2][0] *= al0; O[nt2][1] *= al0;
            O[nt2][2] *= al1; O[nt2][3] *= al1;
        }

#pragma unroll
        for (int ks2 = 0; ks2 < 4; ks2++) {
            const uint32_t a0 = aP[2 * ks2][0], a1 = aP[2 * ks2][1];
            const uint32_t a2 = aP[2 * ks2 + 1][0], a3 = aP[2 * ks2 + 1][1];
#pragma unroll
            for (int nt2 = 0; nt2 < 8; nt2++) {
                uint32_t b0 = *(const uint32_t*)&sVT[(nt2 * 8 + g4) * 72 + ks2 * 16 + t4 * 2];
                uint32_t b1 = *(const uint32_t*)&sVT[(nt2 * 8 + g4) * 72 + ks2 * 16 + 8 + t4 * 2];
                mma_f16(O[nt2], a0, a1, a2, a3, b0, b1);
            }
        }
        __syncthreads();
    }

    const float inv0 = 1.f / l0, inv1 = 1.f / l1;
    const int q0 = qhalf * 128 + wid * 16 + g4;
#pragma unroll
    for (int nt2 = 0; nt2 < 8; nt2++) {
        const int col = head * 64 + nt2 * 8 + t4 * 2;
        *(__half2*)(out + (rowbase + q0) * 1024 + col) =
            __floats2half2_rn(O[nt2][0] * inv0, O[nt2][1] * inv0);
        *(__half2*)(out + (rowbase + q0 + 8) * 1024 + col) =
            __floats2half2_rn(O[nt2][2] * inv1, O[nt2][3] * inv1);
    }
}

// ---------------- temporal attention (T=16, dh=64, causal; fp16 qkv in/out) ----------------
__global__ __launch_bounds__(128)
void temporal_attn_kernel(const __half* __restrict__ qkv, __half* __restrict__ out) {
    __shared__ float Q[16][65], K[16][65], V[16][65], S[16][17];
    const int bid = blockIdx.x;
    const int head = bid & 15;
    const int n = bid >> 4;
    const int b = n >> 8;
    const int hw = n & 255;
    const int tid = threadIdx.x;
    const size_t tokbase = (size_t)b * 4096 + hw;

    for (int i = tid; i < 16 * 64; i += 128) {
        int t = i >> 6, d = i & 63;
        size_t base = (tokbase + (size_t)t * 256) * 3072 + head * 64 + d;
        Q[t][d] = __half2float(qkv[base]);
        K[t][d] = __half2float(qkv[base + 1024]);
        V[t][d] = __half2float(qkv[base + 2048]);
    }
    __syncthreads();

    for (int idx = tid; idx < 256; idx += 128) {
        int qi = idx >> 4, kj = idx & 15;
        float s;
        if (kj <= qi) {
            float acc = 0.f;
#pragma unroll
            for (int d = 0; d < 64; d++) acc += Q[qi][d] * K[kj][d];
            s = acc * 0.125f;
        } else s = -1e30f;
        S[qi][kj] = s;
    }
    __syncthreads();

    {
        const int row = tid >> 3, c0 = tid & 7;
        float mx = fmaxf(S[row][c0], S[row][c0 + 8]);
#pragma unroll
        for (int o = 4; o; o >>= 1) mx = fmaxf(mx, __shfl_xor_sync(0xffffffffu, mx, o));
        float e0 = __expf(S[row][c0] - mx), e1 = __expf(S[row][c0 + 8] - mx);
        float sum = e0 + e1;
#pragma unroll
        for (int o = 4; o; o >>= 1) sum += __shfl_xor_sync(0xffffffffu, sum, o);
        float inv = 1.f / sum;
        S[row][c0] = e0 * inv;
        S[row][c0 + 8] = e1 * inv;
    }
    __syncthreads();

    for (int i = tid; i < 16 * 64; i += 128) {
        int qi = i >> 6, d = i & 63;
        float acc = 0.f;
#pragma unroll
        for (int k = 0; k < 16; k++) acc = fmaf(S[qi][k], V[k][d], acc);
        out[(tokbase + (size_t)qi * 256) * 1024 + head * 64 + d] = __float2half(acc);
    }
}

// ---------------- launch helpers ----------------
static void gemm(const __half* A, const __half* BT, const float* bias, void* C,
                 int M, int N, int K, int epi, int outh) {
    dim3 g(N / 128, (M + 127) / 128);
    if (epi == 1)      gemm_tc<1, 1><<<g, 128, GTC_SMEM_TOTAL>>>(A, BT, bias, C, M, N, K);
    else if (outh)     gemm_tc<0, 1><<<g, 128, GTC_SMEM_TOTAL>>>(A, BT, bias, C, M, N, K);
    else               gemm_tc<0, 0><<<g, 128, GTC_SMEM_TOTAL>>>(A, BT, bias, C, M, N, K);
}

extern "C" void kernel_launch(void* const* d_in, const int* in_sizes, int n_in,
                              void* d_out, int out_size) {
    const float* x        = (const float*)d_in[0];
    const float* c        = (const float*)d_in[1];
    const float* s_ada_w  = (const float*)d_in[2];
    const float* s_ada_b  = (const float*)d_in[3];
    const float* t_ada_w  = (const float*)d_in[4];
    const float* t_ada_b  = (const float*)d_in[5];
    const float* r_ada_w  = (const float*)d_in[6];
    const float* r_ada_b  = (const float*)d_in[7];
    const float* s_qkv_w  = (const float*)d_in[8];
    const float* s_out_w  = (const float*)d_in[9];
    const float* s_out_b  = (const float*)d_in[10];
    const float* t_qkv_w  = (const float*)d_in[11];
    const float* t_out_w  = (const float*)d_in[12];
    const float* t_out_b  = (const float*)d_in[13];
    const float* s_mlp_w1 = (const float*)d_in[14];
    const float* s_mlp_b1 = (const float*)d_in[15];
    const float* s_mlp_w2 = (const float*)d_in[16];
    const float* s_mlp_b2 = (const float*)d_in[17];
    const float* t_mlp_w1 = (const float*)d_in[18];
    const float* t_mlp_b1 = (const float*)d_in[19];
    const float* t_mlp_w2 = (const float*)d_in[20];
    const float* t_mlp_b2 = (const float*)d_in[21];
    const float* lstm_w_ih = (const float*)d_in[22];
    const float* lstm_w_hh = (const float*)d_in[23];
    const float* lstm_b_ih = (const float*)d_in[24];
    const float* lstm_b_hh = (const float*)d_in[25];
    float* out = (float*)d_out;

    cudaFuncSetAttribute(gemm_tc<0, 0>, cudaFuncAttributeMaxDynamicSharedMemorySize, GTC_SMEM_TOTAL);
    cudaFuncSetAttribute(gemm_tc<0, 1>, cudaFuncAttributeMaxDynamicSharedMemorySize, GTC_SMEM_TOTAL);
    cudaFuncSetAttribute(gemm_tc<1, 1>, cudaFuncAttributeMaxDynamicSharedMemorySize, GTC_SMEM_TOTAL);
    cudaFuncSetAttribute(lstm_persist_tc, cudaFuncAttributeMaxDynamicSharedMemorySize, LSTM_SMEM_TOTAL);

    __half *csh, *h1h, *qkvh, *deltah, *mlph, *gatesxh, *hstateh, *hstate2h, *wTh;
    float *modall, *adab, *xbuf, *cstate, *lstmbias;
    cudaGetSymbolAddress((void**)&csh, g_csh);
    cudaGetSymbolAddress((void**)&modall, g_modall);
    cudaGetSymbolAddress((void**)&adab, g_adab);
    cudaGetSymbolAddress((void**)&xbuf, g_xbuf);
    cudaGetSymbolAddress((void**)&h1h, g_h1h);
    cudaGetSymbolAddress((void**)&qkvh, g_qkvh);
    cudaGetSymbolAddress((void**)&deltah, g_deltah);
    cudaGetSymbolAddress((void**)&mlph, g_mlph);
    cudaGetSymbolAddress((void**)&gatesxh, g_gatesxh);
    cudaGetSymbolAddress((void**)&hstateh, g_hstateh);
    cudaGetSymbolAddress((void**)&hstate2h, g_hstate2h);
    cudaGetSymbolAddress((void**)&cstate, g_cstate);
    cudaGetSymbolAddress((void**)&lstmbias, g_lstmbias);
    cudaGetSymbolAddress((void**)&wTh, g_wTh);

    float* smod = modall;              // stride MODW
    float* tmod = modall + 6144;       // stride MODW
    float* rmod = modall + 12288;      // stride MODW

    const size_t MEG = 1048576;
    __half* wt_ada   = wTh + 0 * MEG;   // [15360,1024]: sada|tada|rada contiguous
    __half* wt_sqkv  = wTh + 15 * MEG;
    __half* wt_sout  = wTh + 18 * MEG;
    __half* wt_tqkv  = wTh + 19 * MEG;
    __half* wt_tout  = wTh + 22 * MEG;
    __half* wt_smlp1 = wTh + 23 * MEG;
    __half* wt_smlp2 = wTh + 27 * MEG;
    __half* wt_tmlp1 = wTh + 31 * MEG;
    __half* wt_tmlp2 = wTh + 35 * MEG;
    __half* wt_lih   = wTh + 39 * MEG;  // gate-interleaved [4096,1024]
    __half* wt_lhh   = wTh + 43 * MEG;  // gate-interleaved [4096,1024]

    // batched transpose: all 13 matrices, one launch
    {
        TransArgs ta;
        auto set = [&](int i, const float* W, __half* WT, int K, int N, int perm, int start) {
            ta.d[i].W = W; ta.d[i].WT = WT; ta.d[i].K = K; ta.d[i].N = N;
            ta.d[i].perm = perm; ta.d[i].tileStart = start;
        };
        int s = 0;
        set(0,  s_ada_w,  wt_ada,            1024, 6144, 0, s); s += (6144 / 32) * 32;
        set(1,  t_ada_w,  wt_ada + 6 * MEG,  1024, 6144, 0, s); s += (6144 / 32) * 32;
        set(2,  r_ada_w,  wt_ada + 12 * MEG, 1024, 3072, 0, s); s += (3072 / 32) * 32;
        set(3,  s_qkv_w,  wt_sqkv,  1024, 3072, 0, s); s += (3072 / 32) * 32;
        set(4,  s_out_w,  wt_sout,  1024, 1024, 0, s); s += (1024 / 32) * 32;
        set(5,  t_qkv_w,  wt_tqkv,  1024, 3072, 0, s); s += (3072 / 32) * 32;
        set(6,  t_out_w,  wt_tout,  1024, 1024, 0, s); s += (1024 / 32) * 32;
        set(7,  s_mlp_w1, wt_smlp1, 1024, 4096, 0, s); s += (4096 / 32) * 32;
        set(8,  s_mlp_w2, wt_smlp2, 4096, 1024, 0, s); s += (1024 / 32) * 128;
        set(9,  t_mlp_w1, wt_tmlp1, 1024, 4096, 0, s); s += (4096 / 32) * 32;
        set(10, t_mlp_w2, wt_tmlp2, 4096, 1024, 0, s); s += (1024 / 32) * 128;
        set(11, lstm_w_ih, wt_lih,  1024, 4096, 1, s); s += (4096 / 32) * 32;
        set(12, lstm_w_hh, wt_lhh,  1024, 4096, 1, s); s += (4096 / 32) * 32;
        transpose_all_kernel<<<s, 256>>>(ta);
    }

    // setup (silu + ada bias concat + lstm bias permute + barrier reset)
    setup_kernel<<<(NBT * DD + 255) / 256, 256>>>(c, csh, s_ada_b, t_ada_b, r_ada_b, adab,
                                                  lstm_b_ih, lstm_b_hh, lstmbias);
    gemm(csh, wt_ada, adab, modall, NBT, MODW, DD, 0, 0);

    // ---- spatial attention ----
    ln_mod_kernel<<<NTOK, 256>>>(x, smod, MODW, 0, DD, h1h);
    gemm(h1h, wt_sqkv, nullptr, qkvh, NTOK, 3 * DD, DD, 0, 1);
    spatial_attn_tc<<<1024, 256>>>(qkvh, h1h);
    gemm(h1h, wt_sout, s_out_b, deltah, NTOK, DD, DD, 0, 1);
    ga_ln_kernel<<<NTOK, 256>>>(x, deltah, smod, MODW, 2 * DD,
                                smod, MODW, 3 * DD, 4 * DD, xbuf, h1h);

    // ---- spatial MLP ----
    gemm(h1h, wt_smlp1, s_mlp_b1, mlph, NTOK, 4 * DD, DD, 1, 1);
    gemm(mlph, wt_smlp2, s_mlp_b2, deltah, NTOK, DD, 4 * DD, 0, 1);
    ga_ln_kernel<<<NTOK, 256>>>(xbuf, deltah, smod, MODW, 5 * DD,
                                tmod, MODW, 0, DD, xbuf, h1h);

    // ---- temporal attention (causal) ----
    gemm(h1h, wt_tqkv, nullptr, qkvh, NTOK, 3 * DD, DD, 0, 1);
    temporal_attn_kernel<<<8192, 128>>>(qkvh, h1h);
    gemm(h1h, wt_tout, t_out_b, deltah, NTOK, DD, DD, 0, 1);
    ga_ln_kernel<<<NTOK, 256>>>(xbuf, deltah, tmod, MODW, 2 * DD,
                                tmod, MODW, 3 * DD, 4 * DD, xbuf, h1h);

    // ---- temporal MLP ----
    gemm(h1h, wt_tmlp1, t_mlp_b1, mlph, NTOK, 4 * DD, DD, 1, 1);
    gemm(mlph, wt_tmlp2, t_mlp_b2, deltah, NTOK, DD, 4 * DD, 0, 1);
    ga_ln_kernel<<<NTOK, 256>>>(xbuf, deltah, tmod, MODW, 5 * DD,
                                rmod, MODW, 0, DD, xbuf, h1h);

    // ---- LSTM branch: persistent kernel, all 16 steps ----
    gemm(h1h, wt_lih, lstmbias, gatesxh, NTOK, 4 * DD, DD, 0, 1);
    lstm_persist_tc<<<dim3(32, 8), 128, LSTM_SMEM_TOTAL>>>(
        hstateh, hstate2h, wt_lhh, gatesxh, cstate, xbuf, rmod, out);
}

// round 12
// speedup vs baseline: 5.9556x; 1.0033x over previous
#include <cuda_runtime.h>
#include <cuda_fp16.h>
#include <math.h>
#include <cstdint>

// Problem constants
#define DD   1024
#define NTOK 8192      // B*T*H*W
#define NBT  32        // B*T
#define NSEQ 512       // B*H*W
#define TT   16
#define MODW 15360     // 6*DD + 6*DD + 3*DD combined ada width

// ---------------- scratch (device globals; no allocations allowed) ----------------
__device__ __half g_csh[NBT * DD];
__device__ float  g_modall[NBT * MODW];
__device__ float  g_adab[MODW];
__device__ __half g_xbufh[NTOK * DD];
__device__ __half g_h1h[NTOK * DD];
__device__ __half g_qkvh[NTOK * 3 * DD];
__device__ __half g_deltah[NTOK * DD];
__device__ __half g_mlph[NTOK * 4 * DD];
__device__ __half g_gatesxh[NTOK * 4 * DD];
__device__ __half g_hstateh[NSEQ * DD];
__device__ __half g_hstate2h[NSEQ * DD];
__device__ float  g_cstate[NSEQ * DD];
__device__ float  g_lstmbias[4 * DD];
__device__ unsigned int g_lstm_bar;
__device__ __half g_wTh[47u * 1048576u];   // transposed fp16 weights

__device__ __forceinline__ float tanh_fast(float x) {
    float r; asm("tanh.approx.f32 %0, %1;" : "=f"(r) : "f"(x)); return r;
}
__device__ __forceinline__ float gelu_tanh(float x) {
    return 0.5f * x * (1.f + tanh_fast(0.7978845608028654f * (x + 0.044715f * x * x * x)));
}
__device__ __forceinline__ float sigm(float x) { return 0.5f * (1.f + tanh_fast(0.5f * x)); }
__device__ __forceinline__ uint32_t h2_as_u32(__half2 h) {
    uint32_t u; *reinterpret_cast<__half2*>(&u) = h; return u;
}
__device__ __forceinline__ void mma_f16(float d[4], uint32_t a0, uint32_t a1, uint32_t a2,
                                        uint32_t a3, uint32_t b0, uint32_t b1) {
    asm volatile(
        "mma.sync.aligned.m16n8k16.row.col.f32.f16.f16.f32 "
        "{%0,%1,%2,%3}, {%4,%5,%6,%7}, {%8,%9}, {%0,%1,%2,%3};\n"
        : "+f"(d[0]), "+f"(d[1]), "+f"(d[2]), "+f"(d[3])
        : "r"(a0), "r"(a1), "r"(a2), "r"(a3), "r"(b0), "r"(b1));
}
__device__ __forceinline__ void cp_async16(uint32_t dst, const void* src, int szvalid) {
    asm volatile("cp.async.cg.shared.global [%0], [%1], 16, %2;"
                 :: "r"(dst), "l"(src), "r"(szvalid));
}
__device__ __forceinline__ void cp_commit() { asm volatile("cp.async.commit_group;"); }

// ================== fp16 tensor-core GEMM: C[M,N] = A[M,K] @ BT[N,K]^T ==================
// 128 threads = 4 warps (2x2), warp tile 64x64, block tile 128x128x32, 4-stage cp.async.
#define GPITCH_B   80
#define GOP_BYTES  (128 * GPITCH_B)
#define GSTAGE_B   (2 * GOP_BYTES)       // 20480 per stage
#define GTC_NSTAGE 4
#define GTC_SMEM_TOTAL (GTC_NSTAGE * GSTAGE_B)   // 81920 bytes

template<int EPI, int OUTH>
__global__ __launch_bounds__(128, 2)
void gemm_tc(const __half* __restrict__ A, const __half* __restrict__ BT,
             const float* __restrict__ bias, void* __restrict__ Cout,
             int M, int N, int K) {
    extern __shared__ char smem[];
    const uint32_t sb = (uint32_t)__cvta_generic_to_shared(smem);
    const int tid = threadIdx.x;
    const int lane = tid & 31;
    const int wid = tid >> 5;
    const int wr = wid >> 1;
    const int wc = wid & 1;
    const int g4 = lane >> 2, t4 = lane & 3;
    const int bx = blockIdx.x, by = blockIdx.y;
    const int gra = by * 128;
    const int gnb = bx * 128;

    float acc[4][8][4];
#pragma unroll
    for (int mt = 0; mt < 4; mt++)
#pragma unroll
        for (int nt = 0; nt < 8; nt++)
#pragma unroll
            for (int q = 0; q < 4; q++) acc[mt][nt][q] = 0.f;

    const int nk = K >> 5;

    auto load_stage = [&](int kc, int s) {
        const uint32_t sbase = sb + s * GSTAGE_B;
#pragma unroll
        for (int i = 0; i < 4; i++) {
            const int c = tid + i * 128;
            const int row = c >> 2, seg = c & 3;
            const int ga = gra + row;
            const bool ok = ga < M;
            cp_async16(sbase + row * GPITCH_B + seg * 16,
                       A + (size_t)(ok ? ga : 0) * K + kc * 32 + seg * 8, ok ? 16 : 0);
            cp_async16(sbase + GOP_BYTES + row * GPITCH_B + seg * 16,
                       BT + (size_t)(gnb + row) * K + kc * 32 + seg * 8, 16);
        }
    };

    load_stage(0, 0); cp_commit();
    load_stage(1, 1); cp_commit();
    load_stage(2, 2); cp_commit();

    for (int kc = 0; kc < nk; kc++) {
        if (kc < nk - 2)       asm volatile("cp.async.wait_group 2;");
        else if (kc == nk - 2) asm volatile("cp.async.wait_group 1;");
        else                   asm volatile("cp.async.wait_group 0;");
        __syncthreads();
        if (kc + 3 < nk) { load_stage(kc + 3, (kc + 3) & (GTC_NSTAGE - 1)); cp_commit(); }

        const char* sA = smem + (kc & (GTC_NSTAGE - 1)) * GSTAGE_B;
        const char* sB = sA + GOP_BYTES;
#pragma unroll
        for (int ks = 0; ks < 2; ks++) {
            const int kb = ks * 32 + t4 * 4;
            uint32_t af[4][4];
            uint32_t bf[8][2];
#pragma unroll
            for (int mt = 0; mt < 4; mt++) {
                const int r = wr * 64 + mt * 16 + g4;
                af[mt][0] = *(const uint32_t*)(sA + r * GPITCH_B + kb);
                af[mt][1] = *(const uint32_t*)(sA + (r + 8) * GPITCH_B + kb);
                af[mt][2] = *(const uint32_t*)(sA + r * GPITCH_B + kb + 16);
                af[mt][3] = *(const uint32_t*)(sA + (r + 8) * GPITCH_B + kb + 16);
            }
#pragma unroll
            for (int nt = 0; nt < 8; nt++) {
                const int n = wc * 64 + nt * 8 + g4;
                bf[nt][0] = *(const uint32_t*)(sB + n * GPITCH_B + kb);
                bf[nt][1] = *(const uint32_t*)(sB + n * GPITCH_B + kb + 16);
            }
#pragma unroll
            for (int mt = 0; mt < 4; mt++)
#pragma unroll
                for (int nt = 0; nt < 8; nt++)
                    mma_f16(acc[mt][nt], af[mt][0], af[mt][1], af[mt][2], af[mt][3],
                            bf[nt][0], bf[nt][1]);
        }
    }

#pragma unroll
    for (int mt = 0; mt < 4; mt++) {
        const int r0 = by * 128 + wr * 64 + mt * 16 + g4;
#pragma unroll
        for (int nt = 0; nt < 8; nt++) {
            const int col = bx * 128 + wc * 64 + nt * 8 + t4 * 2;
            float b0 = 0.f, b1 = 0.f;
            if (bias) { b0 = __ldg(bias + col); b1 = __ldg(bias + col + 1); }
            float v0 = acc[mt][nt][0] + b0;
            float v1 = acc[mt][nt][1] + b1;
            float v2 = acc[mt][nt][2] + b0;
            float v3 = acc[mt][nt][3] + b1;
            if (EPI == 1) {
                v0 = gelu_tanh(v0); v1 = gelu_tanh(v1);
                v2 = gelu_tanh(v2); v3 = gelu_tanh(v3);
            }
            if (OUTH) {
                __half* Ch = (__half*)Cout;
                if (r0 < M) *(__half2*)(Ch + (size_t)r0 * N + col) = __floats2half2_rn(v0, v1);
                if (r0 + 8 < M) *(__half2*)(Ch + (size_t)(r0 + 8) * N + col) = __floats2half2_rn(v2, v3);
            } else {
                float* Cf = (float*)Cout;
                if (r0 < M) *(float2*)(Cf + (size_t)r0 * N + col) = make_float2(v0, v1);
                if (r0 + 8 < M) *(float2*)(Cf + (size_t)(r0 + 8) * N + col) = make_float2(v2, v3);
            }
        }
    }
}

// ============ persistent fused LSTM: all 16 steps in one launch ============
// 64x128 block tile, 4 warps (2x2, warp tile 32x64), grid (32, 8) = 256 CTAs, 2-stage.
#define LSA_OP   (64 * GPITCH_B)
#define LSB_OP   (128 * GPITCH_B)
#define LSTAGE_B (LSA_OP + LSB_OP)
#define LSTM_SMEM_TOTAL (2 * LSTAGE_B)

__global__ __launch_bounds__(128, 2)
void lstm_persist_tc(__half* __restrict__ h0buf, __half* __restrict__ h1buf,
                     const __half* __restrict__ BT, const __half* __restrict__ gx,
                     float* __restrict__ cst, const __half* __restrict__ xbuf,
                     const float* __restrict__ rmod, float* __restrict__ outp) {
    extern __shared__ char smem[];
    const uint32_t sb = (uint32_t)__cvta_generic_to_shared(smem);
    const int tid = threadIdx.x;
    const int lane = tid & 31;
    const int wid = tid >> 5;
    const int wr = wid >> 1;
    const int wc = wid & 1;
    const int g4 = lane >> 2, t4 = lane & 3;
    const int bx = blockIdx.x, by = blockIdx.y;
    const int gra = by * 64;
    const int gnb = bx * 128;
    const int K = 1024, nk = 32;

    for (int t = 0; t < TT; t++) {
        const __half* A = (t & 1) ? h1buf : h0buf;
        __half* hnext = (t & 1) ? h0buf : h1buf;

        float acc[2][8][4];
#pragma unroll
        for (int mt = 0; mt < 2; mt++)
#pragma unroll
            for (int nt = 0; nt < 8; nt++)
#pragma unroll
                for (int q = 0; q < 4; q++) acc[mt][nt][q] = 0.f;

        if (t > 0) {
            auto load_stage = [&](int kc, int p) {
                const uint32_t sbase = sb + p * LSTAGE_B;
#pragma unroll
                for (int i = 0; i < 2; i++) {
                    const int c = tid + i * 128;
                    const int row = c >> 2, seg = c & 3;
                    cp_async16(sbase + row * GPITCH_B + seg * 16,
                               A + (size_t)(gra + row) * K + kc * 32 + seg * 8, 16);
                }
#pragma unroll
                for (int i = 0; i < 4; i++) {
                    const int c = tid + i * 128;
                    const int row = c >> 2, seg = c & 3;
                    cp_async16(sbase + LSA_OP + row * GPITCH_B + seg * 16,
                               BT + (size_t)(gnb + row) * K + kc * 32 + seg * 8, 16);
                }
            };

            load_stage(0, 0);
            cp_commit();

            for (int kc = 0; kc < nk; kc++) {
                const int p = kc & 1;
                if (kc + 1 < nk) {
                    load_stage(kc + 1, p ^ 1);
                    cp_commit();
                    asm volatile("cp.async.wait_group 1;");
                } else {
                    asm volatile("cp.async.wait_group 0;");
                }
                __syncthreads();
                const char* sA = smem + p * LSTAGE_B;
                const char* sB = sA + LSA_OP;
#pragma unroll
                for (int ks = 0; ks < 2; ks++) {
                    const int kb = ks * 32 + t4 * 4;
                    uint32_t af[2][4];
                    uint32_t bf[8][2];
#pragma unroll
                    for (int mt = 0; mt < 2; mt++) {
                        const int r = wr * 32 + mt * 16 + g4;
                        af[mt][0] = *(const uint32_t*)(sA + r * GPITCH_B + kb);
                        af[mt][1] = *(const uint32_t*)(sA + (r + 8) * GPITCH_B + kb);
                        af[mt][2] = *(const uint32_t*)(sA + r * GPITCH_B + kb + 16);
                        af[mt][3] = *(const uint32_t*)(sA + (r + 8) * GPITCH_B + kb + 16);
                    }
#pragma unroll
                    for (int nt = 0; nt < 8; nt++) {
                        const int n = wc * 64 + nt * 8 + g4;
                        bf[nt][0] = *(const uint32_t*)(sB + n * GPITCH_B + kb);
                        bf[nt][1] = *(const uint32_t*)(sB + n * GPITCH_B + kb + 16);
                    }
#pragma unroll
                    for (int mt = 0; mt < 2; mt++)
#pragma unroll
                        for (int nt = 0; nt < 8; nt++)
                            mma_f16(acc[mt][nt], af[mt][0], af[mt][1], af[mt][2], af[mt][3],
                                    bf[nt][0], bf[nt][1]);
                }
                __syncthreads();
            }
        }

        // fused cell epilogue (gate-interleaved columns: col = 4j+g), fused gated residual out
#pragma unroll
        for (int mt = 0; mt < 2; mt++) {
            const int r0 = by * 64 + wr * 32 + mt * 16 + g4;
            const int r1 = r0 + 8;
            const int tok0 = ((r0 >> 8) << 12) + (t << 8) + (r0 & 255);
            const int tok1 = ((r1 >> 8) << 12) + (t << 8) + (r1 & 255);
            const int bt0 = tok0 >> 8, bt1 = tok1 >> 8;
#pragma unroll
            for (int nt = 0; nt < 8; nt++) {
                const int col = bx * 128 + wc * 64 + nt * 8 + t4 * 2;
                __half2 gx0 = *(const __half2*)(gx + (size_t)tok0 * 4096 + col);
                __half2 gx1 = *(const __half2*)(gx + (size_t)tok1 * 4096 + col);
                float v0 = acc[mt][nt][0] + __half2float(__low2half(gx0));
                float v1 = acc[mt][nt][1] + __half2float(__high2half(gx0));
                float v2 = acc[mt][nt][2] + __half2float(__low2half(gx1));
                float v3 = acc[mt][nt][3] + __half2float(__high2half(gx1));
                float p0 = __shfl_xor_sync(0xffffffffu, v0, 1);
                float p1 = __shfl_xor_sync(0xffffffffu, v1, 1);
                float p2 = __shfl_xor_sync(0xffffffffu, v2, 1);
                float p3 = __shfl_xor_sync(0xffffffffu, v3, 1);
                if (!(lane & 1)) {
                    const int j = col >> 2;
                    {
                        float cprev = (t == 0) ? 0.f : cst[r0 * 1024 + j];
                        float cc = sigm(v1) * cprev + sigm(v0) * tanh_fast(p0);
                        float hh = sigm(p1) * tanh_fast(cc);
                        cst[r0 * 1024 + j] = cc;
                        hnext[r0 * 1024 + j] = __float2half(hh);
                        float rg = rmod[bt0 * MODW + 2048 + j];
                        outp[(size_t)tok0 * 1024 + j] =
                            __half2float(xbuf[(size_t)tok0 * 1024 + j]) + rg * hh;
                    }
                    {
                        float cprev = (t == 0) ? 0.f : cst[r1 * 1024 + j];
                        float cc = sigm(v3) * cprev + sigm(v2) * tanh_fast(p2);
                        float hh = sigm(p3) * tanh_fast(cc);
                        cst[r1 * 1024 + j] = cc;
                        hnext[r1 * 1024 + j] = __float2half(hh);
                        float rg = rmod[bt1 * MODW + 2048 + j];
                        outp[(size_t)tok1 * 1024 + j] =
                            __half2float(xbuf[(size_t)tok1 * 1024 + j]) + rg * hh;
                    }
                }
            }
        }

        if (t < TT - 1) {
            __syncthreads();
            if (tid == 0) {
                __threadfence();
                atomicAdd(&g_lstm_bar, 1u);
                const unsigned int target = 256u * (unsigned int)(t + 1);
                while (atomicAdd(&g_lstm_bar, 0u) < target) {}
                __threadfence();
            }
            __syncthreads();
        }
    }
}

// ---------------- batched weight transpose: all matrices in one launch ----------------
struct TransDesc { const float* W; __half* WT; int K; int N; int perm; int tileStart; };
struct TransArgs { TransDesc d[13]; };

__global__ __launch_bounds__(256)
void transpose_all_kernel(TransArgs a) {
    __shared__ float t[32][33];
    const int bid = blockIdx.x;
    int i = 0;
#pragma unroll
    for (int k = 0; k < 12; k++) if (bid >= a.d[k + 1].tileStart) i = k + 1;
    const TransDesc& td = a.d[i];
    const int local = bid - td.tileStart;
    const int ntx = td.N / 32;
    const int n0 = (local % ntx) * 32, k0 = (local / ntx) * 32;
    const int tx = threadIdx.x & 31, ty = threadIdx.x >> 5;
#pragma unroll
    for (int j = 0; j < 4; j++)
        t[ty + j * 8][tx] = td.W[(size_t)(k0 + ty + j * 8) * td.N + n0 + tx];
    __syncthreads();
#pragma unroll
    for (int j = 0; j < 4; j++) {
        int n = n0 + ty + j * 8;
        int nd = td.perm ? (4 * (n & 1023) + (n >> 10)) : n;
        td.WT[(size_t)nd * td.K + k0 + tx] = __float2half(t[tx][ty + j * 8]);
    }
}

// ---------------- LayerNorm + adaLN modulate (fp32 x in, fp16 out) ----------------
__global__ __launch_bounds__(256)
void ln_mod_kernel(const float* __restrict__ x, const float* __restrict__ mod,
                   int mstride, int shift_off, int scale_off, __half* __restrict__ out) {
    __shared__ float red[16];
    const int tok = blockIdx.x;
    const int tid = threadIdx.x;
    const float* xr = x + (size_t)tok * DD;
    float v[4];
    float s = 0.f, s2 = 0.f;
#pragma unroll
    for (int k = 0; k < 4; k++) {
        float f = xr[tid + k * 256];
        v[k] = f; s += f; s2 += f * f;
    }
#pragma unroll
    for (int o = 16; o; o >>= 1) {
        s += __shfl_xor_sync(0xffffffffu, s, o);
        s2 += __shfl_xor_sync(0xffffffffu, s2, o);
    }
    if ((tid & 31) == 0) { red[tid >> 5] = s; red[8 + (tid >> 5)] = s2; }
    __syncthreads();
    if (tid == 0) {
        float a = 0.f, b = 0.f;
        for (int i = 0; i < 8; i++) { a += red[i]; b += red[8 + i]; }
        red[0] = a; red[8] = b;
    }
    __syncthreads();
    const float mean = red[0] * (1.f / DD);
    const float var = red[8] * (1.f / DD) - mean * mean;
    const float inv = rsqrtf(var + 1e-6f);
    const int bt = tok >> 8;
    const float* m = mod + (size_t)bt * mstride;
    __half* orow = out + (size_t)tok * DD;
#pragma unroll
    for (int k = 0; k < 4; k++) {
        int d = tid + k * 256;
        float ln = (v[k] - mean) * inv;
        orow[d] = __float2half(ln * (1.f + m[scale_off + d]) + m[shift_off + d]);
    }
}

// -------- fused gated residual add + LayerNorm + modulate (fp16 delta; XIN32 selects xin) --
template<int XIN32>
__global__ __launch_bounds__(256)
void ga_ln_kernel(const void* __restrict__ xin, const __half* __restrict__ delta,
                  const float* __restrict__ modg, int gstride, int gate_off,
                  const float* __restrict__ modl, int lstride, int shift_off, int scale_off,
                  __half* __restrict__ xout, __half* __restrict__ lnout) {
    __shared__ float red[16];
    const int tok = blockIdx.x;
    const int tid = threadIdx.x;
    const int bt = tok >> 8;
    const __half* dr = delta + (size_t)tok * DD;
    const float* mg = modg + (size_t)bt * gstride + gate_off;
    float v[4];
    float s = 0.f, s2 = 0.f;
    __half* xo = xout + (size_t)tok * DD;
#pragma unroll
    for (int k = 0; k < 4; k++) {
        int d = tid + k * 256;
        float xv;
        if (XIN32) xv = ((const float*)xin)[(size_t)tok * DD + d];
        else       xv = __half2float(((const __half*)xin)[(size_t)tok * DD + d]);
        float f = xv + mg[d] * __half2float(dr[d]);
        xo[d] = __float2half(f);
        v[k] = f; s += f; s2 += f * f;
    }
#pragma unroll
    for (int o = 16; o; o >>= 1) {
        s += __shfl_xor_sync(0xffffffffu, s, o);
        s2 += __shfl_xor_sync(0xffffffffu, s2, o);
    }
    if ((tid & 31) == 0) { red[tid >> 5] = s; red[8 + (tid >> 5)] = s2; }
    __syncthreads();
    if (tid == 0) {
        float a = 0.f, b = 0.f;
        for (int i = 0; i < 8; i++) { a += red[i]; b += red[8 + i]; }
        red[0] = a; red[8] = b;
    }
    __syncthreads();
    const float mean = red[0] * (1.f / DD);
    const float var = red[8] * (1.f / DD) - mean * mean;
    const float inv = rsqrtf(var + 1e-6f);
    const float* ml = modl + (size_t)bt * lstride;
    __half* lo = lnout + (size_t)tok * DD;
#pragma unroll
    for (int k = 0; k < 4; k++) {
        int d = tid + k * 256;
        float ln = (v[k] - mean) * inv;
        lo[d] = __float2half(ln * (1.f + ml[scale_off + d]) + ml[shift_off + d]);
    }
}

// ---------------- setup: silu + combined ada bias + permuted lstm bias + barrier reset ----
__global__ void setup_kernel(const float* __restrict__ c, __half* __restrict__ csh,
                             const float* __restrict__ sbp, const float* __restrict__ tbp,
                             const float* __restrict__ rbp, float* __restrict__ adab,
                             const float* __restrict__ lba, const float* __restrict__ lbb,
                             float* __restrict__ lbias) {
    int i = blockIdx.x * 256 + threadIdx.x;
    if (i == 0) g_lstm_bar = 0u;
    if (i < NBT * DD) {
        float v = c[i];
        csh[i] = __float2half(v / (1.f + __expf(-v)));
    }
    if (i < MODW) {
        float b;
        if (i < 6144) b = sbp[i];
        else if (i < 12288) b = tbp[i - 6144];
        else b = rbp[i - 12288];
        adab[i] = b;
    }
    if (i < 4 * DD) {
        int j = i >> 2, g = i & 3;
        lbias[i] = lba[g * 1024 + j] + lbb[g * 1024 + j];
    }
}

// ======= spatial attention via mma.sync fp16 flash (L=256, dh=64, non-causal) =======
__global__ __launch_bounds__(256, 2)
void spatial_attn_tc(const __half* __restrict__ qkv, __half* __restrict__ out) {
    __shared__ __half sQ[128 * 72];
    __shared__ __half sK[64 * 72];
    __shared__ __half sVT[64 * 72];
    const int bid = blockIdx.x;
    const int qhalf = bid & 1;
    const int head = (bid >> 1) & 15;
    const int n = bid >> 5;
    const int tid = threadIdx.x;
    const int lane = tid & 31;
    const int wid = tid >> 5;
    const int g4 = lane >> 2, t4 = lane & 3;
    const size_t rowbase = (size_t)n * 256;

#pragma unroll
    for (int i = 0; i < 4; i++) {
        int idx = tid + i * 256;
        int row = idx >> 3, seg = idx & 7;
        *(uint4*)&sQ[row * 72 + seg * 8] =
            *(const uint4*)(qkv + (rowbase + qhalf * 128 + row) * 3072 + head * 64 + seg * 8);
    }
    __syncthreads();

    uint32_t af[4][4];
    {
        const int r = wid * 16 + g4;
#pragma unroll
        for (int ks = 0; ks < 4; ks++) {
            af[ks][0] = *(const uint32_t*)&sQ[r * 72 + ks * 16 + t4 * 2];
            af[ks][1] = *(const uint32_t*)&sQ[(r + 8) * 72 + ks * 16 + t4 * 2];
            af[ks][2] = *(const uint32_t*)&sQ[r * 72 + ks * 16 + 8 + t4 * 2];
            af[ks][3] = *(const uint32_t*)&sQ[(r + 8) * 72 + ks * 16 + 8 + t4 * 2];
        }
    }

    float O[8][4];
#pragma unroll
    for (int i = 0; i < 8; i++)
#pragma unroll
        for (int q = 0; q < 4; q++) O[i][q] = 0.f;
    float m0 = -1e30f, m1 = -1e30f, l0 = 0.f, l1 = 0.f;

    for (int kt = 0; kt < 4; kt++) {
#pragma unroll
        for (int i = 0; i < 2; i++) {
            int idx = tid + i * 256;
            int row = idx >> 3, seg = idx & 7;
            const __half* src = qkv + (rowbase + kt * 64 + row) * 3072 + 1024 + head * 64 + seg * 8;
            *(uint4*)&sK[row * 72 + seg * 8] = *(const uint4*)src;
            __half vv[8];
            *(uint4*)vv = *(const uint4*)(src + 1024);
#pragma unroll
            for (int jj = 0; jj < 8; jj++) sVT[(seg * 8 + jj) * 72 + row] = vv[jj];
        }
        __syncthreads();

        float sc[8][4];
#pragma unroll
        for (int nt = 0; nt < 8; nt++) {
#pragma unroll
            for (int q = 0; q < 4; q++) sc[nt][q] = 0.f;
#pragma unroll
            for (int ks = 0; ks < 4; ks++) {
                uint32_t b0 = *(const uint32_t*)&sK[(nt * 8 + g4) * 72 + ks * 16 + t4 * 2];
                uint32_t b1 = *(const uint32_t*)&sK[(nt * 8 + g4) * 72 + ks * 16 + 8 + t4 * 2];
                mma_f16(sc[nt], af[ks][0], af[ks][1], af[ks][2], af[ks][3], b0, b1);
            }
        }

        float mx0 = -1e30f, mx1 = -1e30f;
#pragma unroll
        for (int nt = 0; nt < 8; nt++) {
            sc[nt][0] *= 0.125f; sc[nt][1] *= 0.125f;
            sc[nt][2] *= 0.125f; sc[nt][3] *= 0.125f;
            mx0 = fmaxf(mx0, fmaxf(sc[nt][0], sc[nt][1]));
            mx1 = fmaxf(mx1, fmaxf(sc[nt][2], sc[nt][3]));
        }
        mx0 = fmaxf(mx0, __shfl_xor_sync(0xffffffffu, mx0, 1));
        mx0 = fmaxf(mx0, __shfl_xor_sync(0xffffffffu, mx0, 2));
        mx1 = fmaxf(mx1, __shfl_xor_sync(0xffffffffu, mx1, 1));
        mx1 = fmaxf(mx1, __shfl_xor_sync(0xffffffffu, mx1, 2));
        const float mn0 = fmaxf(m0, mx0), mn1 = fmaxf(m1, mx1);
        const float al0 = __expf(m0 - mn0), al1 = __expf(m1 - mn1);
        m0 = mn0; m1 = mn1;

        float sum0 = 0.f, sum1 = 0.f;
        uint32_t aP[8][2];
#pragma unroll
        for (int nt = 0; nt < 8; nt++) {
            float p0 = __expf(sc[nt][0] - mn0);
            float p1 = __expf(sc[nt][1] - mn0);
            float p2 = __expf(sc[nt][2] - mn1);
            float p3 = __expf(sc[nt][3] - mn1);
            sum0 += p0 + p1; sum1 += p2 + p3;
            aP[nt][0] = h2_as_u32(__floats2half2_rn(p0, p1));
            aP[nt][1] = h2_as_u32(__floats2half2_rn(p2, p3));
        }
        sum0 += __shfl_xor_sync(0xffffffffu, sum0, 1);
        sum0 += __shfl_xor_sync(0xffffffffu, sum0, 2);
        sum1 += __shfl_xor_sync(0xffffffffu, sum1, 1);
        sum1 += __shfl_xor_sync(0xffffffffu, sum1, 2);
        l0 = l0 * al0 + sum0;
        l1 = l1 * al1 + sum1;
#pragma unroll
        for (int nt2 = 0; nt2 < 8; nt2++) {
            O[nt2][0] *= al0; O[nt2][1] *= al0;
            O[nt2][2] *= al1; O[nt2][3] *= al1;
        }

#pragma unroll
        for (int ks2 = 0; ks2 < 4; ks2++) {
            const uint32_t a0 = aP[2 * ks2][0], a1 = aP[2 * ks2][1];
            const uint32_t a2 = aP[2 * ks2 + 1][0], a3 = aP[2 * ks2 + 1][1];
#pragma unroll
            for (int nt2 = 0; nt2 < 8; nt2++) {
                uint32_t b0 = *(const uint32_t*)&sVT[(nt2 * 8 + g4) * 72 + ks2 * 16 + t4 * 2];
                uint32_t b1 = *(const uint32_t*)&sVT[(nt2 * 8 + g4) * 72 + ks2 * 16 + 8 + t4 * 2];
                mma_f16(O[nt2], a0, a1, a2, a3, b0, b1);
            }
        }
        __syncthreads();
    }

    const float inv0 = 1.f / l0, inv1 = 1.f / l1;
    const int q0 = qhalf * 128 + wid * 16 + g4;
#pragma unroll
    for (int nt2 = 0; nt2 < 8; nt2++) {
        const int col = head * 64 + nt2 * 8 + t4 * 2;
        *(__half2*)(out + (rowbase + q0) * 1024 + col) =
            __floats2half2_rn(O[nt2][0] * inv0, O[nt2][1] * inv0);
        *(__half2*)(out + (rowbase + q0 + 8) * 1024 + col) =
            __floats2half2_rn(O[nt2][2] * inv1, O[nt2][3] * inv1);
    }
}

// ---------------- temporal attention (T=16, dh=64, causal; fp16 qkv in/out) ----------------
__global__ __launch_bounds__(128)
void temporal_attn_kernel(const __half* __restrict__ qkv, __half* __restrict__ out) {
    __shared__ float Q[16][65], K[16][65], V[16][65], S[16][17];
    const int bid = blockIdx.x;
    const int head = bid & 15;
    const int n = bid >> 4;
    const int b = n >> 8;
    const int hw = n & 255;
    const int tid = threadIdx.x;
    const size_t tokbase = (size_t)b * 4096 + hw;

    for (int i = tid; i < 16 * 64; i += 128) {
        int t = i >> 6, d = i & 63;
        size_t base = (tokbase + (size_t)t * 256) * 3072 + head * 64 + d;
        Q[t][d] = __half2float(qkv[base]);
        K[t][d] = __half2float(qkv[base + 1024]);
        V[t][d] = __half2float(qkv[base + 2048]);
    }
    __syncthreads();

    for (int idx = tid; idx < 256; idx += 128) {
        int qi = idx >> 4, kj = idx & 15;
        float s;
        if (kj <= qi) {
            float acc = 0.f;
#pragma unroll
            for (int d = 0; d < 64; d++) acc += Q[qi][d] * K[kj][d];
            s = acc * 0.125f;
        } else s = -1e30f;
        S[qi][kj] = s;
    }
    __syncthreads();

    {
        const int row = tid >> 3, c0 = tid & 7;
        float mx = fmaxf(S[row][c0], S[row][c0 + 8]);
#pragma unroll
        for (int o = 4; o; o >>= 1) mx = fmaxf(mx, __shfl_xor_sync(0xffffffffu, mx, o));
        float e0 = __expf(S[row][c0] - mx), e1 = __expf(S[row][c0 + 8] - mx);
        float sum = e0 + e1;
#pragma unroll
        for (int o = 4; o; o >>= 1) sum += __shfl_xor_sync(0xffffffffu, sum, o);
        float inv = 1.f / sum;
        S[row][c0] = e0 * inv;
        S[row][c0 + 8] = e1 * inv;
    }
    __syncthreads();

    for (int i = tid; i < 16 * 64; i += 128) {
        int qi = i >> 6, d = i & 63;
        float acc = 0.f;
#pragma unroll
        for (int k = 0; k < 16; k++) acc = fmaf(S[qi][k], V[k][d], acc);
        out[(tokbase + (size_t)qi * 256) * 1024 + head * 64 + d] = __float2half(acc);
    }
}

// ---------------- launch helpers ----------------
static void gemm(const __half* A, const __half* BT, const float* bias, void* C,
                 int M, int N, int K, int epi, int outh) {
    dim3 g(N / 128, (M + 127) / 128);
    if (epi == 1)      gemm_tc<1, 1><<<g, 128, GTC_SMEM_TOTAL>>>(A, BT, bias, C, M, N, K);
    else if (outh)     gemm_tc<0, 1><<<g, 128, GTC_SMEM_TOTAL>>>(A, BT, bias, C, M, N, K);
    else               gemm_tc<0, 0><<<g, 128, GTC_SMEM_TOTAL>>>(A, BT, bias, C, M, N, K);
}

extern "C" void kernel_launch(void* const* d_in, const int* in_sizes, int n_in,
                              void* d_out, int out_size) {
    const float* x        = (const float*)d_in[0];
    const float* c        = (const float*)d_in[1];
    const float* s_ada_w  = (const float*)d_in[2];
    const float* s_ada_b  = (const float*)d_in[3];
    const float* t_ada_w  = (const float*)d_in[4];
    const float* t_ada_b  = (const float*)d_in[5];
    const float* r_ada_w  = (const float*)d_in[6];
    const float* r_ada_b  = (const float*)d_in[7];
    const float* s_qkv_w  = (const float*)d_in[8];
    const float* s_out_w  = (const float*)d_in[9];
    const float* s_out_b  = (const float*)d_in[10];
    const float* t_qkv_w  = (const float*)d_in[11];
    const float* t_out_w  = (const float*)d_in[12];
    const float* t_out_b  = (const float*)d_in[13];
    const float* s_mlp_w1 = (const float*)d_in[14];
    const float* s_mlp_b1 = (const float*)d_in[15];
    const float* s_mlp_w2 = (const float*)d_in[16];
    const float* s_mlp_b2 = (const float*)d_in[17];
    const float* t_mlp_w1 = (const float*)d_in[18];
    const float* t_mlp_b1 = (const float*)d_in[19];
    const float* t_mlp_w2 = (const float*)d_in[20];
    const float* t_mlp_b2 = (const float*)d_in[21];
    const float* lstm_w_ih = (const float*)d_in[22];
    const float* lstm_w_hh = (const float*)d_in[23];
    const float* lstm_b_ih = (const float*)d_in[24];
    const float* lstm_b_hh = (const float*)d_in[25];
    float* out = (float*)d_out;

    cudaFuncSetAttribute(gemm_tc<0, 0>, cudaFuncAttributeMaxDynamicSharedMemorySize, GTC_SMEM_TOTAL);
    cudaFuncSetAttribute(gemm_tc<0, 1>, cudaFuncAttributeMaxDynamicSharedMemorySize, GTC_SMEM_TOTAL);
    cudaFuncSetAttribute(gemm_tc<1, 1>, cudaFuncAttributeMaxDynamicSharedMemorySize, GTC_SMEM_TOTAL);
    cudaFuncSetAttribute(lstm_persist_tc, cudaFuncAttributeMaxDynamicSharedMemorySize, LSTM_SMEM_TOTAL);

    __half *csh, *h1h, *qkvh, *deltah, *mlph, *gatesxh, *hstateh, *hstate2h, *wTh, *xbufh;
    float *modall, *adab, *cstate, *lstmbias;
    cudaGetSymbolAddress((void**)&csh, g_csh);
    cudaGetSymbolAddress((void**)&modall, g_modall);
    cudaGetSymbolAddress((void**)&adab, g_adab);
    cudaGetSymbolAddress((void**)&xbufh, g_xbufh);
    cudaGetSymbolAddress((void**)&h1h, g_h1h);
    cudaGetSymbolAddress((void**)&qkvh, g_qkvh);
    cudaGetSymbolAddress((void**)&deltah, g_deltah);
    cudaGetSymbolAddress((void**)&mlph, g_mlph);
    cudaGetSymbolAddress((void**)&gatesxh, g_gatesxh);
    cudaGetSymbolAddress((void**)&hstateh, g_hstateh);
    cudaGetSymbolAddress((void**)&hstate2h, g_hstate2h);
    cudaGetSymbolAddress((void**)&cstate, g_cstate);
    cudaGetSymbolAddress((void**)&lstmbias, g_lstmbias);
    cudaGetSymbolAddress((void**)&wTh, g_wTh);

    float* smod = modall;              // stride MODW
    float* tmod = modall + 6144;       // stride MODW
    float* rmod = modall + 12288;      // stride MODW

    const size_t MEG = 1048576;
    __half* wt_ada   = wTh + 0 * MEG;   // [15360,1024]: sada|tada|rada contiguous
    __half* wt_sqkv  = wTh + 15 * MEG;
    __half* wt_sout  = wTh + 18 * MEG;
    __half* wt_tqkv  = wTh + 19 * MEG;
    __half* wt_tout  = wTh + 22 * MEG;
    __half* wt_smlp1 = wTh + 23 * MEG;
    __half* wt_smlp2 = wTh + 27 * MEG;
    __half* wt_tmlp1 = wTh + 31 * MEG;
    __half* wt_tmlp2 = wTh + 35 * MEG;
    __half* wt_lih   = wTh + 39 * MEG;  // gate-interleaved [4096,1024]
    __half* wt_lhh   = wTh + 43 * MEG;  // gate-interleaved [4096,1024]

    // batched transpose: all 13 matrices, one launch
    {
        TransArgs ta;
        auto set = [&](int i, const float* W, __half* WT, int K, int N, int perm, int start) {
            ta.d[i].W = W; ta.d[i].WT = WT; ta.d[i].K = K; ta.d[i].N = N;
            ta.d[i].perm = perm; ta.d[i].tileStart = start;
        };
        int s = 0;
        set(0,  s_ada_w,  wt_ada,            1024, 6144, 0, s); s += (6144 / 32) * 32;
        set(1,  t_ada_w,  wt_ada + 6 * MEG,  1024, 6144, 0, s); s += (6144 / 32) * 32;
        set(2,  r_ada_w,  wt_ada + 12 * MEG, 1024, 3072, 0, s); s += (3072 / 32) * 32;
        set(3,  s_qkv_w,  wt_sqkv,  1024, 3072, 0, s); s += (3072 / 32) * 32;
        set(4,  s_out_w,  wt_sout,  1024, 1024, 0, s); s += (1024 / 32) * 32;
        set(5,  t_qkv_w,  wt_tqkv,  1024, 3072, 0, s); s += (3072 / 32) * 32;
        set(6,  t_out_w,  wt_tout,  1024, 1024, 0, s); s += (1024 / 32) * 32;
        set(7,  s_mlp_w1, wt_smlp1, 1024, 4096, 0, s); s += (4096 / 32) * 32;
        set(8,  s_mlp_w2, wt_smlp2, 4096, 1024, 0, s); s += (1024 / 32) * 128;
        set(9,  t_mlp_w1, wt_tmlp1, 1024, 4096, 0, s); s += (4096 / 32) * 32;
        set(10, t_mlp_w2, wt_tmlp2, 4096, 1024, 0, s); s += (1024 / 32) * 128;
        set(11, lstm_w_ih, wt_lih,  1024, 4096, 1, s); s += (4096 / 32) * 32;
        set(12, lstm_w_hh, wt_lhh,  1024, 4096, 1, s); s += (4096 / 32) * 32;
        transpose_all_kernel<<<s, 256>>>(ta);
    }

    // setup (silu + ada bias concat + lstm bias permute + barrier reset)
    setup_kernel<<<(NBT * DD + 255) / 256, 256>>>(c, csh, s_ada_b, t_ada_b, r_ada_b, adab,
                                                  lstm_b_ih, lstm_b_hh, lstmbias);
    gemm(csh, wt_ada, adab, modall, NBT, MODW, DD, 0, 0);

    // ---- spatial attention ----
    ln_mod_kernel<<<NTOK, 256>>>(x, smod, MODW, 0, DD, h1h);
    gemm(h1h, wt_sqkv, nullptr, qkvh, NTOK, 3 * DD, DD, 0, 1);
    spatial_attn_tc<<<1024, 256>>>(qkvh, h1h);
    gemm(h1h, wt_sout, s_out_b, deltah, NTOK, DD, DD, 0, 1);
    ga_ln_kernel<1><<<NTOK, 256>>>(x, deltah, smod, MODW, 2 * DD,
                                   smod, MODW, 3 * DD, 4 * DD, xbufh, h1h);

    // ---- spatial MLP ----
    gemm(h1h, wt_smlp1, s_mlp_b1, mlph, NTOK, 4 * DD, DD, 1, 1);
    gemm(mlph, wt_smlp2, s_mlp_b2, deltah, NTOK, DD, 4 * DD, 0, 1);
    ga_ln_kernel<0><<<NTOK, 256>>>(xbufh, deltah, smod, MODW, 5 * DD,
                                   tmod, MODW, 0, DD, xbufh, h1h);

    // ---- temporal attention (causal) ----
    gemm(h1h, wt_tqkv, nullptr, qkvh, NTOK, 3 * DD, DD, 0, 1);
    temporal_attn_kernel<<<8192, 128>>>(qkvh, h1h);
    gemm(h1h, wt_tout, t_out_b, deltah, NTOK, DD, DD, 0, 1);
    ga_ln_kernel<0><<<NTOK, 256>>>(xbufh, deltah, tmod, MODW, 2 * DD,
                                   tmod, MODW, 3 * DD, 4 * DD, xbufh, h1h);

    // ---- temporal MLP ----
    gemm(h1h, wt_tmlp1, t_mlp_b1, mlph, NTOK, 4 * DD, DD, 1, 1);
    gemm(mlph, wt_tmlp2, t_mlp_b2, deltah, NTOK, DD, 4 * DD, 0, 1);
    ga_ln_kernel<0><<<NTOK, 256>>>(xbufh, deltah, tmod, MODW, 5 * DD,
                                   rmod, MODW, 0, DD, xbufh, h1h);

    // ---- LSTM branch: persistent kernel, all 16 steps ----
    gemm(h1h, wt_lih, lstmbias, gatesxh, NTOK, 4 * DD, DD, 0, 1);
    lstm_persist_tc<<<dim3(32, 8), 128, LSTM_SMEM_TOTAL>>>(
        hstateh, hstate2h, wt_lhh, gatesxh, cstate, xbufh, rmod, out);
}